// round 2
// baseline (speedup 1.0000x reference)
#include <cuda_runtime.h>
#include <cstdint>

#define NSN 50000
#define NDN 50000
#define EE  600000
#define CC  64
#define AA  16
#define HH  8
#define MM  192
#define LNEPS 1e-5f
#define NTILE (EE/64)

// ---------------- scratch (__device__ globals; no allocation allowed) ----------------
__device__ float g_ms[(size_t)NSN*CC];
__device__ float g_md[(size_t)NDN*CC];
__device__ float g_val[(size_t)EE*CC];
__device__ float g_att[(size_t)EE*HH];
__device__ float g_max[(size_t)NDN*HH];
__device__ float g_z[(size_t)NDN*HH];
__device__ float g_acc[(size_t)NDN*CC];

__device__ __forceinline__ void atomicMaxFloat(float* addr, float v) {
    if (v >= 0.0f) atomicMax((int*)addr, __float_as_int(v));
    else           atomicMin((unsigned int*)addr, __float_as_uint(v));
}

// ---------------- init ----------------
__global__ void k_init() {
    int i = blockIdx.x * blockDim.x + threadIdx.x;
    if (i < NDN*HH) { g_max[i] = __int_as_float(0xFF800000); g_z[i] = 0.0f; }
    if (i < NDN*CC) g_acc[i] = 0.0f;
}

// ---------------- node projections: ms = LN(src)@Wsrc ; md = LN(dst)@Wdst + b ----------------
__global__ void k_node(const float* __restrict__ src_f, const float* __restrict__ dst_f,
                       const float* __restrict__ lnsw, const float* __restrict__ lnsb,
                       const float* __restrict__ Wsrc,
                       const float* __restrict__ lndw, const float* __restrict__ lndb,
                       const float* __restrict__ Wdst, const float* __restrict__ bdst) {
    __shared__ float sW[2*64*64];
    for (int i = threadIdx.x; i < 8192; i += blockDim.x)
        sW[i] = (i < 4096) ? Wsrc[i] : Wdst[i-4096];
    __syncthreads();
    const int l = threadIdx.x & 31;
    const int warp = (blockIdx.x * blockDim.x + threadIdx.x) >> 5;
    const int nwarps = (gridDim.x * blockDim.x) >> 5;
    for (int n = warp; n < NSN + NDN; n += nwarps) {
        const bool isd = (n >= NSN);
        const int idx = isd ? n - NSN : n;
        const float* xf = (isd ? dst_f : src_f) + (size_t)idx * 64;
        float x0 = xf[l], x1 = xf[l+32];
        float s = x0 + x1;
        #pragma unroll
        for (int o = 16; o; o >>= 1) s += __shfl_xor_sync(~0u, s, o);
        const float mean = s * (1.0f/64.0f);
        const float c0 = x0 - mean, c1 = x1 - mean;
        float v = c0*c0 + c1*c1;
        #pragma unroll
        for (int o = 16; o; o >>= 1) v += __shfl_xor_sync(~0u, v, o);
        const float rs = rsqrtf(v * (1.0f/64.0f) + LNEPS);
        const float* lw = isd ? lndw : lnsw;
        const float* lb = isd ? lndb : lnsb;
        const float y0 = c0 * rs * lw[l]    + lb[l];
        const float y1 = c1 * rs * lw[l+32] + lb[l+32];
        const float* W = sW + (isd ? 4096 : 0);
        float a0 = 0.0f, a1 = 0.0f;
        #pragma unroll
        for (int k = 0; k < 32; k++) {
            float b = __shfl_sync(~0u, y0, k);
            a0 += b * W[k*64 + l];
            a1 += b * W[k*64 + l + 32];
        }
        #pragma unroll
        for (int k = 0; k < 32; k++) {
            float b = __shfl_sync(~0u, y1, k);
            a0 += b * W[(k+32)*64 + l];
            a1 += b * W[(k+32)*64 + l + 32];
        }
        if (isd) { a0 += bdst[l]; a1 += bdst[l+32]; }
        float* out = isd ? g_md : g_ms;
        out[(size_t)idx*64 + l]      = a0;
        out[(size_t)idx*64 + l + 32] = a1;
    }
}

// ---------------- heavy fused edge kernel ----------------
// smem float offsets
#define OFF_WR1   0
#define OFF_WR2   4096
#define OFF_WEA   12288
#define OFF_WDTP  13312
#define OFF_BR1   21504
#define OFF_BR2   21568
#define OFF_AL    21696
#define OFF_ES    21760
#define OFF_R     25920
#define OFF_MSG   30080
#define OFF_EA    34240
#define SMEM_EDGE_FLOATS 35328   // 141312 bytes

__global__ void __launch_bounds__(256, 1)
k_edge(const float* __restrict__ es_g, const float* __restrict__ ea_g,
       const float* __restrict__ el_g,
       const int* __restrict__ esrc, const int* __restrict__ edst,
       const float* __restrict__ Wr1, const float* __restrict__ br1,
       const float* __restrict__ Wr2, const float* __restrict__ br2,
       const float* __restrict__ Wea, const float* __restrict__ Wdtp,
       const float* __restrict__ alpha) {
    extern __shared__ float sm[];
    float* sWr1  = sm + OFF_WR1;
    float* sWr2  = sm + OFF_WR2;
    float* sWea  = sm + OFF_WEA;
    float* sWdtp = sm + OFF_WDTP;
    float* sbr1  = sm + OFF_BR1;
    float* sbr2  = sm + OFF_BR2;
    float* sal   = sm + OFF_AL;
    float* sES   = sm + OFF_ES;
    float* sR    = sm + OFF_R;
    float* sMSG  = sm + OFF_MSG;
    float* sEA   = sm + OFF_EA;

    const int tid = threadIdx.x;
    for (int i = tid; i < 4096; i += 256) sWr1[i]  = Wr1[i];
    for (int i = tid; i < 8192; i += 256) sWr2[i]  = Wr2[i];
    for (int i = tid; i < 1024; i += 256) sWea[i]  = Wea[i];
    for (int i = tid; i < 8192; i += 256) sWdtp[i] = Wdtp[i];
    if (tid < 64)  sbr1[tid] = br1[tid];
    if (tid < 128) sbr2[tid] = br2[tid];
    if (tid < 64)  sal[tid]  = alpha[tid];

    const int te = tid & 15;      // edge group
    const int tc = tid >> 4;      // col group [0,16)
    const int e0 = te * 4;

    for (int tile = blockIdx.x; tile < NTILE; tile += gridDim.x) {
        const int base = tile * 64;
        __syncthreads();  // previous tile fully consumed (also covers weight load 1st iter)

        // ---- stage es + msg (gather) + edge_attr ----
        {
            const int e = tid >> 2, p = tid & 3;
            const int ge = base + e;
            const float4* esrow = (const float4*)(es_g + (size_t)ge*64 + p*16);
            const int sidx = esrc[ge], didx = edst[ge];
            const float4* msr = (const float4*)(g_ms + (size_t)sidx*64 + p*16);
            const float4* mdr = (const float4*)(g_md + (size_t)didx*64 + p*16);
            #pragma unroll
            for (int q = 0; q < 4; q++) {
                float4 v = esrow[q];
                int b = e*65 + p*16 + q*4;
                sES[b] = v.x; sES[b+1] = v.y; sES[b+2] = v.z; sES[b+3] = v.w;
                float4 a = msr[q], d = mdr[q];
                sMSG[b]   = a.x + d.x; sMSG[b+1] = a.y + d.y;
                sMSG[b+2] = a.z + d.z; sMSG[b+3] = a.w + d.w;
            }
            if (tid < 64) {
                const int ge2 = base + tid;
                const float4* ear = (const float4*)(ea_g + (size_t)ge2*16);
                #pragma unroll
                for (int q = 0; q < 4; q++) {
                    float4 v = ear[q];
                    int b = tid*17 + q*4;
                    sEA[b] = v.x; sEA[b+1] = v.y; sEA[b+2] = v.z; sEA[b+3] = v.w;
                }
            }
        }
        __syncthreads();

        // ---- GEMM1: r = silu(es @ Wr1 + br1), [64,64] ----
        {
            float acc[4][4] = {};
            #pragma unroll 4
            for (int k = 0; k < 64; k++) {
                float4 w = *(const float4*)(sWr1 + k*64 + tc*4);
                #pragma unroll
                for (int i = 0; i < 4; i++) {
                    float x = sES[(e0+i)*65 + k];
                    acc[i][0] += x*w.x; acc[i][1] += x*w.y;
                    acc[i][2] += x*w.z; acc[i][3] += x*w.w;
                }
            }
            #pragma unroll
            for (int i = 0; i < 4; i++)
                #pragma unroll
                for (int j = 0; j < 4; j++) {
                    float v = acc[i][j] + sbr1[tc*4 + j];
                    v = v / (1.0f + __expf(-v));
                    sR[(e0+i)*65 + tc*4 + j] = v;
                }
        }
        __syncthreads();

        // ---- GEMM2: w_edge = r @ Wr2 + br2, [64,128] (kept in regs) ----
        float we[4][8];
        {
            float acc[4][8] = {};
            #pragma unroll 2
            for (int k = 0; k < 64; k++) {
                float4 w0 = *(const float4*)(sWr2 + k*128 + tc*8);
                float4 w1 = *(const float4*)(sWr2 + k*128 + tc*8 + 4);
                #pragma unroll
                for (int i = 0; i < 4; i++) {
                    float x = sR[(e0+i)*65 + k];
                    acc[i][0] += x*w0.x; acc[i][1] += x*w0.y;
                    acc[i][2] += x*w0.z; acc[i][3] += x*w0.w;
                    acc[i][4] += x*w1.x; acc[i][5] += x*w1.y;
                    acc[i][6] += x*w1.z; acc[i][7] += x*w1.w;
                }
            }
            #pragma unroll
            for (int i = 0; i < 4; i++)
                #pragma unroll
                for (int j = 0; j < 8; j++)
                    we[i][j] = acc[i][j] + sbr2[tc*8 + j];
        }

        // ---- ea = edge_attr @ Wea ; t = msg * ea (in-place in sMSG) ----
        {
            float acc[4][4] = {};
            #pragma unroll
            for (int k = 0; k < 16; k++) {
                float4 w = *(const float4*)(sWea + k*64 + tc*4);
                #pragma unroll
                for (int i = 0; i < 4; i++) {
                    float x = sEA[(e0+i)*17 + k];
                    acc[i][0] += x*w.x; acc[i][1] += x*w.y;
                    acc[i][2] += x*w.z; acc[i][3] += x*w.w;
                }
            }
            #pragma unroll
            for (int i = 0; i < 4; i++)
                #pragma unroll
                for (int j = 0; j < 4; j++)
                    sMSG[(e0+i)*65 + tc*4 + j] *= acc[i][j];
        }
        __syncthreads();

        // ---- GEMM3: dtp = (t @ Wdtp) * w_edge, [64,128] ----
        float dtp[4][8];
        {
            float acc[4][8] = {};
            #pragma unroll 2
            for (int k = 0; k < 64; k++) {
                float4 w0 = *(const float4*)(sWdtp + k*128 + tc*8);
                float4 w1 = *(const float4*)(sWdtp + k*128 + tc*8 + 4);
                #pragma unroll
                for (int i = 0; i < 4; i++) {
                    float x = sMSG[(e0+i)*65 + k];
                    acc[i][0] += x*w0.x; acc[i][1] += x*w0.y;
                    acc[i][2] += x*w0.z; acc[i][3] += x*w0.w;
                    acc[i][4] += x*w1.x; acc[i][5] += x*w1.y;
                    acc[i][6] += x*w1.z; acc[i][7] += x*w1.w;
                }
            }
            #pragma unroll
            for (int i = 0; i < 4; i++)
                #pragma unroll
                for (int j = 0; j < 8; j++)
                    dtp[i][j] = acc[i][j] * we[i][j];
        }

        // ---- epilogue: logits (cols<64) / val (cols>=64) ----
        if (tc < 8) {
            #pragma unroll
            for (int i = 0; i < 4; i++) {
                const int ge = base + e0 + i;
                float lg = 0.0f;
                #pragma unroll
                for (int j = 0; j < 8; j++) {
                    float x = dtp[i][j];
                    float lr = (x > 0.0f) ? x : 0.2f * x;
                    lg += lr * sal[tc*8 + j];
                }
                lg += el_g[ge];
                const int d = edst[ge];
                g_att[(size_t)ge*8 + tc] = lg;
                atomicMaxFloat(&g_max[(size_t)d*8 + tc], lg);
            }
        } else {
            const int c = (tc - 8) * 8;
            #pragma unroll
            for (int i = 0; i < 4; i++) {
                const int ge = base + e0 + i;
                float4 v0 = make_float4(dtp[i][0], dtp[i][1], dtp[i][2], dtp[i][3]);
                float4 v1 = make_float4(dtp[i][4], dtp[i][5], dtp[i][6], dtp[i][7]);
                *(float4*)(g_val + (size_t)ge*64 + c)     = v0;
                *(float4*)(g_val + (size_t)ge*64 + c + 4) = v1;
            }
        }
    }
}

// ---------------- softmax pass 2: a = exp(l - m[dst]); z += a ----------------
__global__ void k_soft(const int* __restrict__ edst) {
    int i = blockIdx.x * blockDim.x + threadIdx.x;
    if (i >= EE*HH) return;
    int e = i >> 3, h = i & 7;
    int d = edst[e];
    float a = __expf(g_att[i] - g_max[(size_t)d*8 + h]);
    g_att[i] = a;
    atomicAdd(&g_z[(size_t)d*8 + h], a);
}

// ---------------- scatter: acc[dst] += val * a/z ----------------
__global__ void k_scat(const int* __restrict__ edst) {
    int i = blockIdx.x * blockDim.x + threadIdx.x;
    if (i >= EE*CC) return;
    int e = i >> 6, c = i & 63;
    int h = c >> 3;
    int d = edst[e];
    float attn = g_att[(size_t)e*8 + h] / g_z[(size_t)d*8 + h];
    atomicAdd(&g_acc[(size_t)d*64 + c], g_val[i] * attn);
}

// ---------------- final: proj + skip + LN + FFN + skip ----------------
#define SMEM_FIN_FLOATS 28672  // 114688 bytes
__global__ void __launch_bounds__(256, 1)
k_final(const float* __restrict__ dst_f,
        const float* __restrict__ Wp, const float* __restrict__ bp,
        const float* __restrict__ lnw, const float* __restrict__ lnb,
        const float* __restrict__ Wf1, const float* __restrict__ bf1,
        const float* __restrict__ Wf2, const float* __restrict__ bf2,
        float* __restrict__ out) {
    extern __shared__ float sm[];
    float* sWp  = sm;
    float* sWf1 = sm + 4096;
    float* sWf2 = sm + 16384;
    for (int i = threadIdx.x; i < 4096;  i += blockDim.x) sWp[i]  = Wp[i];
    for (int i = threadIdx.x; i < 12288; i += blockDim.x) sWf1[i] = Wf1[i];
    for (int i = threadIdx.x; i < 12288; i += blockDim.x) sWf2[i] = Wf2[i];
    __syncthreads();
    const int l = threadIdx.x & 31;
    const int warp = (blockIdx.x * blockDim.x + threadIdx.x) >> 5;
    const int nw = (gridDim.x * blockDim.x) >> 5;
    for (int n = warp; n < NDN; n += nw) {
        float i0 = g_acc[(size_t)n*64 + l], i1 = g_acc[(size_t)n*64 + l + 32];
        float o0 = bp[l], o1 = bp[l+32];
        #pragma unroll
        for (int k = 0; k < 32; k++) {
            float b = __shfl_sync(~0u, i0, k);
            o0 += b * sWp[k*64 + l];
            o1 += b * sWp[k*64 + l + 32];
        }
        #pragma unroll
        for (int k = 0; k < 32; k++) {
            float b = __shfl_sync(~0u, i1, k);
            o0 += b * sWp[(k+32)*64 + l];
            o1 += b * sWp[(k+32)*64 + l + 32];
        }
        const float e0 = o0 + dst_f[(size_t)n*64 + l];
        const float e1 = o1 + dst_f[(size_t)n*64 + l + 32];
        float s = e0 + e1;
        #pragma unroll
        for (int o = 16; o; o >>= 1) s += __shfl_xor_sync(~0u, s, o);
        const float mean = s * (1.0f/64.0f);
        const float c0 = e0 - mean, c1 = e1 - mean;
        float v = c0*c0 + c1*c1;
        #pragma unroll
        for (int o = 16; o; o >>= 1) v += __shfl_xor_sync(~0u, v, o);
        const float rs = rsqrtf(v * (1.0f/64.0f) + LNEPS);
        const float y0 = c0 * rs * lnw[l]    + lnb[l];
        const float y1 = c1 * rs * lnw[l+32] + lnb[l+32];
        float h[6];
        #pragma unroll
        for (int i = 0; i < 6; i++) h[i] = bf1[l + 32*i];
        #pragma unroll
        for (int k = 0; k < 32; k++) {
            float b = __shfl_sync(~0u, y0, k);
            #pragma unroll
            for (int i = 0; i < 6; i++) h[i] += b * sWf1[k*192 + l + 32*i];
        }
        #pragma unroll
        for (int k = 0; k < 32; k++) {
            float b = __shfl_sync(~0u, y1, k);
            #pragma unroll
            for (int i = 0; i < 6; i++) h[i] += b * sWf1[(k+32)*192 + l + 32*i];
        }
        #pragma unroll
        for (int i = 0; i < 6; i++) h[i] = h[i] / (1.0f + __expf(-h[i]));
        float f0 = bf2[l], f1 = bf2[l+32];
        #pragma unroll
        for (int kk = 0; kk < 6; kk++)
            #pragma unroll
            for (int k2 = 0; k2 < 32; k2++) {
                float b = __shfl_sync(~0u, h[kk], k2);
                f0 += b * sWf2[(kk*32 + k2)*64 + l];
                f1 += b * sWf2[(kk*32 + k2)*64 + l + 32];
            }
        out[(size_t)n*64 + l]      = f0 + e0;
        out[(size_t)n*64 + l + 32] = f1 + e1;
    }
}

// ---------------- launch ----------------
extern "C" void kernel_launch(void* const* d_in, const int* in_sizes, int n_in,
                              void* d_out, int out_size) {
    const float* src_f        = (const float*)d_in[0];
    const float* dst_f        = (const float*)d_in[1];
    const float* edge_attr    = (const float*)d_in[2];
    const float* edge_scalars = (const float*)d_in[3];
    const float* edge_logits  = (const float*)d_in[4];
    const int*   edge_src     = (const int*)d_in[5];
    const int*   edge_dst     = (const int*)d_in[6];
    const float* ln_src_w = (const float*)d_in[7];
    const float* ln_src_b = (const float*)d_in[8];
    const float* W_src    = (const float*)d_in[9];
    const float* ln_dst_w = (const float*)d_in[10];
    const float* ln_dst_b = (const float*)d_in[11];
    const float* W_dst    = (const float*)d_in[12];
    const float* b_dst    = (const float*)d_in[13];
    const float* W_ea     = (const float*)d_in[14];
    const float* W_dtp    = (const float*)d_in[15];
    const float* W_r1     = (const float*)d_in[16];
    const float* b_r1     = (const float*)d_in[17];
    const float* W_r2     = (const float*)d_in[18];
    const float* b_r2     = (const float*)d_in[19];
    const float* alpha    = (const float*)d_in[20];
    const float* W_proj   = (const float*)d_in[21];
    const float* b_proj   = (const float*)d_in[22];
    const float* ln_post_w = (const float*)d_in[23];
    const float* ln_post_b = (const float*)d_in[24];
    const float* W_f1     = (const float*)d_in[25];
    const float* b_f1     = (const float*)d_in[26];
    const float* W_f2     = (const float*)d_in[27];
    const float* b_f2     = (const float*)d_in[28];
    float* out = (float*)d_out;

    cudaFuncSetAttribute(k_edge, cudaFuncAttributeMaxDynamicSharedMemorySize,
                         SMEM_EDGE_FLOATS * 4);
    cudaFuncSetAttribute(k_final, cudaFuncAttributeMaxDynamicSharedMemorySize,
                         SMEM_FIN_FLOATS * 4);

    k_init<<<(NDN*CC + 255)/256, 256>>>();
    k_node<<<1600, 256>>>(src_f, dst_f, ln_src_w, ln_src_b, W_src,
                          ln_dst_w, ln_dst_b, W_dst, b_dst);
    k_edge<<<304, 256, SMEM_EDGE_FLOATS*4>>>(edge_scalars, edge_attr, edge_logits,
                                             edge_src, edge_dst,
                                             W_r1, b_r1, W_r2, b_r2, W_ea, W_dtp, alpha);
    k_soft<<<(EE*HH + 255)/256, 256>>>(edge_dst);
    k_scat<<<(EE*CC + 255)/256, 256>>>(edge_dst);
    k_final<<<800, 256, SMEM_FIN_FLOATS*4>>>(dst_f, W_proj, b_proj,
                                             ln_post_w, ln_post_b,
                                             W_f1, b_f1, W_f2, b_f2, out);
}

// round 3
// speedup vs baseline: 1.0762x; 1.0762x over previous
#include <cuda_runtime.h>
#include <cstdint>

#define NSN 50000
#define NDN 50000
#define EE  600000
#define CC  64
#define AA  16
#define HH  8
#define MM  192
#define LNEPS 1e-5f
#define NTILE (EE/64)

typedef unsigned long long u64;

// packed f32x2 helpers (SASS FFMA2 — only reachable via PTX fma.rn.f32x2)
#define FFMA2(d, a, b, c) asm("fma.rn.f32x2 %0, %1, %2, %3;" : "=l"(d) : "l"(a), "l"(b), "l"(c))
#define MUL2(d, a, b)     asm("mul.rn.f32x2 %0, %1, %2;"     : "=l"(d) : "l"(a), "l"(b))
#define ADD2(d, a, b)     asm("add.rn.f32x2 %0, %1, %2;"     : "=l"(d) : "l"(a), "l"(b))
#define PK2(d, x)         asm("mov.b64 %0, {%1, %1};"        : "=l"(d) : "f"(x))
#define UPK2(lo, hi, v)   asm("mov.b64 {%0, %1}, %2;"        : "=f"(lo), "=f"(hi) : "l"(v))

// ---------------- scratch ----------------
__device__ float g_ms[(size_t)NSN*CC];
__device__ float g_md[(size_t)NDN*CC];
__device__ float g_val[(size_t)EE*CC];
__device__ float g_att[(size_t)EE*HH];
__device__ float g_max[(size_t)NDN*HH];
__device__ float g_z[(size_t)NDN*HH];
__device__ float g_acc[(size_t)NDN*CC];

__device__ __forceinline__ void atomicMaxFloat(float* addr, float v) {
    if (v >= 0.0f) atomicMax((int*)addr, __float_as_int(v));
    else           atomicMin((unsigned int*)addr, __float_as_uint(v));
}

// ---------------- init ----------------
__global__ void k_init() {
    int i = blockIdx.x * blockDim.x + threadIdx.x;
    if (i < NDN*HH) { g_max[i] = __int_as_float(0xFF800000); g_z[i] = 0.0f; }
    if (i < NDN*CC) g_acc[i] = 0.0f;
}

// ---------------- node projections ----------------
__global__ void k_node(const float* __restrict__ src_f, const float* __restrict__ dst_f,
                       const float* __restrict__ lnsw, const float* __restrict__ lnsb,
                       const float* __restrict__ Wsrc,
                       const float* __restrict__ lndw, const float* __restrict__ lndb,
                       const float* __restrict__ Wdst, const float* __restrict__ bdst) {
    __shared__ float sW[2*64*64];
    for (int i = threadIdx.x; i < 8192; i += blockDim.x)
        sW[i] = (i < 4096) ? Wsrc[i] : Wdst[i-4096];
    __syncthreads();
    const int l = threadIdx.x & 31;
    const int warp = (blockIdx.x * blockDim.x + threadIdx.x) >> 5;
    const int nwarps = (gridDim.x * blockDim.x) >> 5;
    for (int n = warp; n < NSN + NDN; n += nwarps) {
        const bool isd = (n >= NSN);
        const int idx = isd ? n - NSN : n;
        const float* xf = (isd ? dst_f : src_f) + (size_t)idx * 64;
        float x0 = xf[l], x1 = xf[l+32];
        float s = x0 + x1;
        #pragma unroll
        for (int o = 16; o; o >>= 1) s += __shfl_xor_sync(~0u, s, o);
        const float mean = s * (1.0f/64.0f);
        const float c0 = x0 - mean, c1 = x1 - mean;
        float v = c0*c0 + c1*c1;
        #pragma unroll
        for (int o = 16; o; o >>= 1) v += __shfl_xor_sync(~0u, v, o);
        const float rs = rsqrtf(v * (1.0f/64.0f) + LNEPS);
        const float* lw = isd ? lndw : lnsw;
        const float* lb = isd ? lndb : lnsb;
        const float y0 = c0 * rs * lw[l]    + lb[l];
        const float y1 = c1 * rs * lw[l+32] + lb[l+32];
        const float* W = sW + (isd ? 4096 : 0);
        float a0 = 0.0f, a1 = 0.0f;
        #pragma unroll
        for (int k = 0; k < 32; k++) {
            float b = __shfl_sync(~0u, y0, k);
            a0 += b * W[k*64 + l];
            a1 += b * W[k*64 + l + 32];
        }
        #pragma unroll
        for (int k = 0; k < 32; k++) {
            float b = __shfl_sync(~0u, y1, k);
            a0 += b * W[(k+32)*64 + l];
            a1 += b * W[(k+32)*64 + l + 32];
        }
        if (isd) { a0 += bdst[l]; a1 += bdst[l+32]; }
        float* out = isd ? g_md : g_ms;
        out[(size_t)idx*64 + l]      = a0;
        out[(size_t)idx*64 + l + 32] = a1;
    }
}

// ---------------- heavy fused edge kernel (f32x2 packed) ----------------
// transposed activation arrays: [k][edge], row stride 68 floats
#define SDE 68
#define OFF_WR1   0
#define OFF_WR2   4096
#define OFF_WEA   12288
#define OFF_WDTP  13312
#define OFF_BR1   21504
#define OFF_BR2   21568
#define OFF_AL    21696
#define OFF_ESt   21760                 // 64*68 = 4352
#define OFF_Rt    (OFF_ESt + 4352)      // 26112
#define OFF_MSGt  (OFF_Rt  + 4352)      // 30464
#define OFF_EAt   (OFF_MSGt+ 4352)      // 34816, 16*68 = 1088
#define SMEM_EDGE_FLOATS (OFF_EAt + 1088)   // 35904 floats = 143616 B

__global__ void __launch_bounds__(256, 1)
k_edge(const float* __restrict__ es_g, const float* __restrict__ ea_g,
       const float* __restrict__ el_g,
       const int* __restrict__ esrc, const int* __restrict__ edst,
       const float* __restrict__ Wr1, const float* __restrict__ br1,
       const float* __restrict__ Wr2, const float* __restrict__ br2,
       const float* __restrict__ Wea, const float* __restrict__ Wdtp,
       const float* __restrict__ alpha) {
    extern __shared__ float sm[];
    float* sWr1  = sm + OFF_WR1;
    float* sWr2  = sm + OFF_WR2;
    float* sWea  = sm + OFF_WEA;
    float* sWdtp = sm + OFF_WDTP;
    float* sbr1  = sm + OFF_BR1;
    float* sbr2  = sm + OFF_BR2;
    float* sal   = sm + OFF_AL;
    float* sESt  = sm + OFF_ESt;
    float* sRt   = sm + OFF_Rt;
    float* sMSGt = sm + OFF_MSGt;
    float* sEAt  = sm + OFF_EAt;

    const int tid = threadIdx.x;
    for (int i = tid; i < 4096; i += 256) sWr1[i]  = Wr1[i];
    for (int i = tid; i < 8192; i += 256) sWr2[i]  = Wr2[i];
    for (int i = tid; i < 1024; i += 256) sWea[i]  = Wea[i];
    for (int i = tid; i < 8192; i += 256) sWdtp[i] = Wdtp[i];
    if (tid < 64)  sbr1[tid] = br1[tid];
    if (tid < 128) sbr2[tid] = br2[tid];
    if (tid < 64)  sal[tid]  = alpha[tid];

    const int te = tid & 15;      // edge group -> 4 edges
    const int tc = tid >> 4;      // col group [0,16)
    const int e0 = te * 4;

    for (int tile = blockIdx.x; tile < NTILE; tile += gridDim.x) {
        const int base = tile * 64;
        __syncthreads();  // previous tile consumed (also covers weight load on iter 1)

        // ---- stage: ES^T, MSG^T (gather), EA^T ----
        {
            const int e = tid >> 2, p = tid & 3;
            const int ge = base + e;
            const float4* esrow = (const float4*)(es_g + (size_t)ge*64 + p*16);
            const int sidx = esrc[ge], didx = edst[ge];
            const float4* msr = (const float4*)(g_ms + (size_t)sidx*64 + p*16);
            const float4* mdr = (const float4*)(g_md + (size_t)didx*64 + p*16);
            #pragma unroll
            for (int q = 0; q < 4; q++) {
                float4 v = esrow[q];
                int k0 = p*16 + q*4;
                sESt[(k0+0)*SDE + e] = v.x;
                sESt[(k0+1)*SDE + e] = v.y;
                sESt[(k0+2)*SDE + e] = v.z;
                sESt[(k0+3)*SDE + e] = v.w;
                float4 a = msr[q], d = mdr[q];
                sMSGt[(k0+0)*SDE + e] = a.x + d.x;
                sMSGt[(k0+1)*SDE + e] = a.y + d.y;
                sMSGt[(k0+2)*SDE + e] = a.z + d.z;
                sMSGt[(k0+3)*SDE + e] = a.w + d.w;
            }
            if (tid < 64) {
                const int ge2 = base + tid;
                const float4* ear = (const float4*)(ea_g + (size_t)ge2*16);
                #pragma unroll
                for (int q = 0; q < 4; q++) {
                    float4 v = ear[q];
                    sEAt[(q*4+0)*SDE + tid] = v.x;
                    sEAt[(q*4+1)*SDE + tid] = v.y;
                    sEAt[(q*4+2)*SDE + tid] = v.z;
                    sEAt[(q*4+3)*SDE + tid] = v.w;
                }
            }
        }
        __syncthreads();

        // ---- GEMM1: r = silu(es @ Wr1 + br1)  [64e, 64c] -> sRt (transposed) ----
        {
            u64 acc[4][2] = {};
            #pragma unroll 4
            for (int k = 0; k < 64; k++) {
                float4 xv = *(const float4*)(sESt + k*SDE + e0);
                u64 w0 = *(const u64*)(sWr1 + k*64 + tc*4);
                u64 w1 = *(const u64*)(sWr1 + k*64 + tc*4 + 2);
                u64 xp;
                PK2(xp, xv.x); FFMA2(acc[0][0], xp, w0, acc[0][0]); FFMA2(acc[0][1], xp, w1, acc[0][1]);
                PK2(xp, xv.y); FFMA2(acc[1][0], xp, w0, acc[1][0]); FFMA2(acc[1][1], xp, w1, acc[1][1]);
                PK2(xp, xv.z); FFMA2(acc[2][0], xp, w0, acc[2][0]); FFMA2(acc[2][1], xp, w1, acc[2][1]);
                PK2(xp, xv.w); FFMA2(acc[3][0], xp, w0, acc[3][0]); FFMA2(acc[3][1], xp, w1, acc[3][1]);
            }
            #pragma unroll
            for (int i = 0; i < 4; i++)
                #pragma unroll
                for (int jp = 0; jp < 2; jp++) {
                    float lo, hi;
                    UPK2(lo, hi, acc[i][jp]);
                    lo += sbr1[tc*4 + 2*jp];
                    hi += sbr1[tc*4 + 2*jp + 1];
                    lo = lo / (1.0f + __expf(-lo));
                    hi = hi / (1.0f + __expf(-hi));
                    sRt[(tc*4 + 2*jp)*SDE   + e0 + i] = lo;
                    sRt[(tc*4 + 2*jp+1)*SDE + e0 + i] = hi;
                }
        }

        // ---- Gea: ea2 = edge_attr @ Wea  [64e, 64c], then T = msg*ea2 (after sync) ----
        u64 ea2[4][2] = {};
        {
            #pragma unroll
            for (int k = 0; k < 16; k++) {
                float4 xv = *(const float4*)(sEAt + k*SDE + e0);
                u64 w0 = *(const u64*)(sWea + k*64 + tc*4);
                u64 w1 = *(const u64*)(sWea + k*64 + tc*4 + 2);
                u64 xp;
                PK2(xp, xv.x); FFMA2(ea2[0][0], xp, w0, ea2[0][0]); FFMA2(ea2[0][1], xp, w1, ea2[0][1]);
                PK2(xp, xv.y); FFMA2(ea2[1][0], xp, w0, ea2[1][0]); FFMA2(ea2[1][1], xp, w1, ea2[1][1]);
                PK2(xp, xv.z); FFMA2(ea2[2][0], xp, w0, ea2[2][0]); FFMA2(ea2[2][1], xp, w1, ea2[2][1]);
                PK2(xp, xv.w); FFMA2(ea2[3][0], xp, w0, ea2[3][0]); FFMA2(ea2[3][1], xp, w1, ea2[3][1]);
            }
        }
        __syncthreads();   // sRt written; sMSGt still pristine

        // ---- T = msg * ea2, written back into sMSGt (transposed, exclusive cells) ----
        {
            #pragma unroll
            for (int jp = 0; jp < 2; jp++) {
                #pragma unroll
                for (int h = 0; h < 2; h++) {
                    const int c = tc*4 + 2*jp + h;
                    float4 m4 = *(float4*)(sMSGt + c*SDE + e0);
                    float v0, v1, v2, v3, dummy;
                    if (h == 0) {
                        UPK2(v0, dummy, ea2[0][jp]); UPK2(v1, dummy, ea2[1][jp]);
                        UPK2(v2, dummy, ea2[2][jp]); UPK2(v3, dummy, ea2[3][jp]);
                    } else {
                        UPK2(dummy, v0, ea2[0][jp]); UPK2(dummy, v1, ea2[1][jp]);
                        UPK2(dummy, v2, ea2[2][jp]); UPK2(dummy, v3, ea2[3][jp]);
                    }
                    m4.x *= v0; m4.y *= v1; m4.z *= v2; m4.w *= v3;
                    *(float4*)(sMSGt + c*SDE + e0) = m4;
                }
            }
        }

        // ---- GEMM2: w_edge = r @ Wr2 + br2  [64e, 128c] (in regs, packed) ----
        u64 we[4][4];
        {
            u64 acc[4][4] = {};
            #pragma unroll 2
            for (int k = 0; k < 64; k++) {
                float4 xv = *(const float4*)(sRt + k*SDE + e0);
                u64 w0 = *(const u64*)(sWr2 + k*128 + tc*8);
                u64 w1 = *(const u64*)(sWr2 + k*128 + tc*8 + 2);
                u64 w2 = *(const u64*)(sWr2 + k*128 + tc*8 + 4);
                u64 w3 = *(const u64*)(sWr2 + k*128 + tc*8 + 6);
                u64 xp;
                PK2(xp, xv.x);
                FFMA2(acc[0][0], xp, w0, acc[0][0]); FFMA2(acc[0][1], xp, w1, acc[0][1]);
                FFMA2(acc[0][2], xp, w2, acc[0][2]); FFMA2(acc[0][3], xp, w3, acc[0][3]);
                PK2(xp, xv.y);
                FFMA2(acc[1][0], xp, w0, acc[1][0]); FFMA2(acc[1][1], xp, w1, acc[1][1]);
                FFMA2(acc[1][2], xp, w2, acc[1][2]); FFMA2(acc[1][3], xp, w3, acc[1][3]);
                PK2(xp, xv.z);
                FFMA2(acc[2][0], xp, w0, acc[2][0]); FFMA2(acc[2][1], xp, w1, acc[2][1]);
                FFMA2(acc[2][2], xp, w2, acc[2][2]); FFMA2(acc[2][3], xp, w3, acc[2][3]);
                PK2(xp, xv.w);
                FFMA2(acc[3][0], xp, w0, acc[3][0]); FFMA2(acc[3][1], xp, w1, acc[3][1]);
                FFMA2(acc[3][2], xp, w2, acc[3][2]); FFMA2(acc[3][3], xp, w3, acc[3][3]);
            }
            #pragma unroll
            for (int i = 0; i < 4; i++)
                #pragma unroll
                for (int jp = 0; jp < 4; jp++) {
                    u64 b = *(const u64*)(sbr2 + tc*8 + 2*jp);
                    ADD2(we[i][jp], acc[i][jp], b);
                }
        }
        __syncthreads();   // T writes done

        // ---- GEMM3: dtp = (T @ Wdtp) * w_edge  [64e, 128c] ----
        u64 dtp[4][4];
        {
            u64 acc[4][4] = {};
            #pragma unroll 2
            for (int k = 0; k < 64; k++) {
                float4 xv = *(const float4*)(sMSGt + k*SDE + e0);
                u64 w0 = *(const u64*)(sWdtp + k*128 + tc*8);
                u64 w1 = *(const u64*)(sWdtp + k*128 + tc*8 + 2);
                u64 w2 = *(const u64*)(sWdtp + k*128 + tc*8 + 4);
                u64 w3 = *(const u64*)(sWdtp + k*128 + tc*8 + 6);
                u64 xp;
                PK2(xp, xv.x);
                FFMA2(acc[0][0], xp, w0, acc[0][0]); FFMA2(acc[0][1], xp, w1, acc[0][1]);
                FFMA2(acc[0][2], xp, w2, acc[0][2]); FFMA2(acc[0][3], xp, w3, acc[0][3]);
                PK2(xp, xv.y);
                FFMA2(acc[1][0], xp, w0, acc[1][0]); FFMA2(acc[1][1], xp, w1, acc[1][1]);
                FFMA2(acc[1][2], xp, w2, acc[1][2]); FFMA2(acc[1][3], xp, w3, acc[1][3]);
                PK2(xp, xv.z);
                FFMA2(acc[2][0], xp, w0, acc[2][0]); FFMA2(acc[2][1], xp, w1, acc[2][1]);
                FFMA2(acc[2][2], xp, w2, acc[2][2]); FFMA2(acc[2][3], xp, w3, acc[2][3]);
                PK2(xp, xv.w);
                FFMA2(acc[3][0], xp, w0, acc[3][0]); FFMA2(acc[3][1], xp, w1, acc[3][1]);
                FFMA2(acc[3][2], xp, w2, acc[3][2]); FFMA2(acc[3][3], xp, w3, acc[3][3]);
            }
            #pragma unroll
            for (int i = 0; i < 4; i++)
                #pragma unroll
                for (int jp = 0; jp < 4; jp++)
                    MUL2(dtp[i][jp], acc[i][jp], we[i][jp]);
        }

        // ---- epilogue ----
        if (tc < 8) {
            #pragma unroll
            for (int i = 0; i < 4; i++) {
                const int ge = base + e0 + i;
                float lg = 0.0f;
                #pragma unroll
                for (int jp = 0; jp < 4; jp++) {
                    float x0, x1;
                    UPK2(x0, x1, dtp[i][jp]);
                    float lr0 = (x0 > 0.0f) ? x0 : 0.2f * x0;
                    float lr1 = (x1 > 0.0f) ? x1 : 0.2f * x1;
                    lg += lr0 * sal[tc*8 + 2*jp] + lr1 * sal[tc*8 + 2*jp + 1];
                }
                lg += el_g[ge];
                const int d = edst[ge];
                g_att[(size_t)ge*8 + tc] = lg;
                atomicMaxFloat(&g_max[(size_t)d*8 + tc], lg);
            }
        } else {
            const int c = (tc - 8) * 8;
            #pragma unroll
            for (int i = 0; i < 4; i++) {
                const int ge = base + e0 + i;
                float4 v0, v1;
                UPK2(v0.x, v0.y, dtp[i][0]); UPK2(v0.z, v0.w, dtp[i][1]);
                UPK2(v1.x, v1.y, dtp[i][2]); UPK2(v1.z, v1.w, dtp[i][3]);
                *(float4*)(g_val + (size_t)ge*64 + c)     = v0;
                *(float4*)(g_val + (size_t)ge*64 + c + 4) = v1;
            }
        }
    }
}

// ---------------- softmax pass 2 ----------------
__global__ void k_soft(const int* __restrict__ edst) {
    int i = blockIdx.x * blockDim.x + threadIdx.x;
    if (i >= EE*HH) return;
    int e = i >> 3, h = i & 7;
    int d = edst[e];
    float a = __expf(g_att[i] - g_max[(size_t)d*8 + h]);
    g_att[i] = a;
    atomicAdd(&g_z[(size_t)d*8 + h], a);
}

// ---------------- scatter ----------------
__global__ void k_scat(const int* __restrict__ edst) {
    int i = blockIdx.x * blockDim.x + threadIdx.x;
    if (i >= EE*CC) return;
    int e = i >> 6, c = i & 63;
    int h = c >> 3;
    int d = edst[e];
    float attn = g_att[(size_t)e*8 + h] / g_z[(size_t)d*8 + h];
    atomicAdd(&g_acc[(size_t)d*64 + c], g_val[i] * attn);
}

// ---------------- final ----------------
#define SMEM_FIN_FLOATS 28672
__global__ void __launch_bounds__(256, 1)
k_final(const float* __restrict__ dst_f,
        const float* __restrict__ Wp, const float* __restrict__ bp,
        const float* __restrict__ lnw, const float* __restrict__ lnb,
        const float* __restrict__ Wf1, const float* __restrict__ bf1,
        const float* __restrict__ Wf2, const float* __restrict__ bf2,
        float* __restrict__ out) {
    extern __shared__ float sm[];
    float* sWp  = sm;
    float* sWf1 = sm + 4096;
    float* sWf2 = sm + 16384;
    for (int i = threadIdx.x; i < 4096;  i += blockDim.x) sWp[i]  = Wp[i];
    for (int i = threadIdx.x; i < 12288; i += blockDim.x) sWf1[i] = Wf1[i];
    for (int i = threadIdx.x; i < 12288; i += blockDim.x) sWf2[i] = Wf2[i];
    __syncthreads();
    const int l = threadIdx.x & 31;
    const int warp = (blockIdx.x * blockDim.x + threadIdx.x) >> 5;
    const int nw = (gridDim.x * blockDim.x) >> 5;
    for (int n = warp; n < NDN; n += nw) {
        float i0 = g_acc[(size_t)n*64 + l], i1 = g_acc[(size_t)n*64 + l + 32];
        float o0 = bp[l], o1 = bp[l+32];
        #pragma unroll
        for (int k = 0; k < 32; k++) {
            float b = __shfl_sync(~0u, i0, k);
            o0 += b * sWp[k*64 + l];
            o1 += b * sWp[k*64 + l + 32];
        }
        #pragma unroll
        for (int k = 0; k < 32; k++) {
            float b = __shfl_sync(~0u, i1, k);
            o0 += b * sWp[(k+32)*64 + l];
            o1 += b * sWp[(k+32)*64 + l + 32];
        }
        const float e0 = o0 + dst_f[(size_t)n*64 + l];
        const float e1 = o1 + dst_f[(size_t)n*64 + l + 32];
        float s = e0 + e1;
        #pragma unroll
        for (int o = 16; o; o >>= 1) s += __shfl_xor_sync(~0u, s, o);
        const float mean = s * (1.0f/64.0f);
        const float c0 = e0 - mean, c1 = e1 - mean;
        float v = c0*c0 + c1*c1;
        #pragma unroll
        for (int o = 16; o; o >>= 1) v += __shfl_xor_sync(~0u, v, o);
        const float rs = rsqrtf(v * (1.0f/64.0f) + LNEPS);
        const float y0 = c0 * rs * lnw[l]    + lnb[l];
        const float y1 = c1 * rs * lnw[l+32] + lnb[l+32];
        float h[6];
        #pragma unroll
        for (int i = 0; i < 6; i++) h[i] = bf1[l + 32*i];
        #pragma unroll
        for (int k = 0; k < 32; k++) {
            float b = __shfl_sync(~0u, y0, k);
            #pragma unroll
            for (int i = 0; i < 6; i++) h[i] += b * sWf1[k*192 + l + 32*i];
        }
        #pragma unroll
        for (int k = 0; k < 32; k++) {
            float b = __shfl_sync(~0u, y1, k);
            #pragma unroll
            for (int i = 0; i < 6; i++) h[i] += b * sWf1[(k+32)*192 + l + 32*i];
        }
        #pragma unroll
        for (int i = 0; i < 6; i++) h[i] = h[i] / (1.0f + __expf(-h[i]));
        float f0 = bf2[l], f1 = bf2[l+32];
        #pragma unroll
        for (int kk = 0; kk < 6; kk++)
            #pragma unroll
            for (int k2 = 0; k2 < 32; k2++) {
                float b = __shfl_sync(~0u, h[kk], k2);
                f0 += b * sWf2[(kk*32 + k2)*64 + l];
                f1 += b * sWf2[(kk*32 + k2)*64 + l + 32];
            }
        out[(size_t)n*64 + l]      = f0 + e0;
        out[(size_t)n*64 + l + 32] = f1 + e1;
    }
}

// ---------------- launch ----------------
extern "C" void kernel_launch(void* const* d_in, const int* in_sizes, int n_in,
                              void* d_out, int out_size) {
    const float* src_f        = (const float*)d_in[0];
    const float* dst_f        = (const float*)d_in[1];
    const float* edge_attr    = (const float*)d_in[2];
    const float* edge_scalars = (const float*)d_in[3];
    const float* edge_logits  = (const float*)d_in[4];
    const int*   edge_src     = (const int*)d_in[5];
    const int*   edge_dst     = (const int*)d_in[6];
    const float* ln_src_w = (const float*)d_in[7];
    const float* ln_src_b = (const float*)d_in[8];
    const float* W_src    = (const float*)d_in[9];
    const float* ln_dst_w = (const float*)d_in[10];
    const float* ln_dst_b = (const float*)d_in[11];
    const float* W_dst    = (const float*)d_in[12];
    const float* b_dst    = (const float*)d_in[13];
    const float* W_ea     = (const float*)d_in[14];
    const float* W_dtp    = (const float*)d_in[15];
    const float* W_r1     = (const float*)d_in[16];
    const float* b_r1     = (const float*)d_in[17];
    const float* W_r2     = (const float*)d_in[18];
    const float* b_r2     = (const float*)d_in[19];
    const float* alpha    = (const float*)d_in[20];
    const float* W_proj   = (const float*)d_in[21];
    const float* b_proj   = (const float*)d_in[22];
    const float* ln_post_w = (const float*)d_in[23];
    const float* ln_post_b = (const float*)d_in[24];
    const float* W_f1     = (const float*)d_in[25];
    const float* b_f1     = (const float*)d_in[26];
    const float* W_f2     = (const float*)d_in[27];
    const float* b_f2     = (const float*)d_in[28];
    float* out = (float*)d_out;

    cudaFuncSetAttribute(k_edge, cudaFuncAttributeMaxDynamicSharedMemorySize,
                         SMEM_EDGE_FLOATS * 4);
    cudaFuncSetAttribute(k_final, cudaFuncAttributeMaxDynamicSharedMemorySize,
                         SMEM_FIN_FLOATS * 4);

    k_init<<<(NDN*CC + 255)/256, 256>>>();
    k_node<<<1600, 256>>>(src_f, dst_f, ln_src_w, ln_src_b, W_src,
                          ln_dst_w, ln_dst_b, W_dst, b_dst);
    k_edge<<<304, 256, SMEM_EDGE_FLOATS*4>>>(edge_scalars, edge_attr, edge_logits,
                                             edge_src, edge_dst,
                                             W_r1, b_r1, W_r2, b_r2, W_ea, W_dtp, alpha);
    k_soft<<<(EE*HH + 255)/256, 256>>>(edge_dst);
    k_scat<<<(EE*CC + 255)/256, 256>>>(edge_dst);
    k_final<<<800, 256, SMEM_FIN_FLOATS*4>>>(dst_f, W_proj, b_proj,
                                             ln_post_w, ln_post_b,
                                             W_f1, b_f1, W_f2, b_f2, out);
}

// round 4
// speedup vs baseline: 1.1550x; 1.0732x over previous
#include <cuda_runtime.h>
#include <cstdint>

#define NSN 50000
#define NDN 50000
#define EE  600000
#define CC  64
#define AA  16
#define HH  8
#define MM  192
#define LNEPS 1e-5f

typedef unsigned long long u64;

// packed f32x2 helpers (SASS FFMA2 — only reachable via PTX fma.rn.f32x2)
#define FFMA2(d, a, b, c) asm("fma.rn.f32x2 %0, %1, %2, %3;" : "=l"(d) : "l"(a), "l"(b), "l"(c))
#define MUL2(d, a, b)     asm("mul.rn.f32x2 %0, %1, %2;"     : "=l"(d) : "l"(a), "l"(b))
#define ADD2(d, a, b)     asm("add.rn.f32x2 %0, %1, %2;"     : "=l"(d) : "l"(a), "l"(b))
#define PK2(d, x)         asm("mov.b64 %0, {%1, %1};"        : "=l"(d) : "f"(x))
#define UPK2(lo, hi, v)   asm("mov.b64 {%0, %1}, %2;"        : "=f"(lo), "=f"(hi) : "l"(v))

// ---------------- scratch ----------------
__device__ float g_ms[(size_t)NSN*CC];
__device__ float g_md[(size_t)NDN*CC];
__device__ float g_val[(size_t)EE*CC];
__device__ float g_att[(size_t)EE*HH];
__device__ float g_max[(size_t)NDN*HH];
__device__ float g_z[(size_t)NDN*HH];
__device__ float g_acc[(size_t)NDN*CC];

__device__ __forceinline__ void atomicMaxFloat(float* addr, float v) {
    if (v >= 0.0f) atomicMax((int*)addr, __float_as_int(v));
    else           atomicMin((unsigned int*)addr, __float_as_uint(v));
}

// ---------------- init ----------------
__global__ void k_init() {
    int i = blockIdx.x * blockDim.x + threadIdx.x;
    if (i < NDN*HH) { g_max[i] = __int_as_float(0xFF800000); g_z[i] = 0.0f; }
    if (i < NDN*CC) g_acc[i] = 0.0f;
}

// ---------------- node projections ----------------
__global__ void k_node(const float* __restrict__ src_f, const float* __restrict__ dst_f,
                       const float* __restrict__ lnsw, const float* __restrict__ lnsb,
                       const float* __restrict__ Wsrc,
                       const float* __restrict__ lndw, const float* __restrict__ lndb,
                       const float* __restrict__ Wdst, const float* __restrict__ bdst) {
    __shared__ float sW[2*64*64];
    for (int i = threadIdx.x; i < 8192; i += blockDim.x)
        sW[i] = (i < 4096) ? Wsrc[i] : Wdst[i-4096];
    __syncthreads();
    const int l = threadIdx.x & 31;
    const int warp = (blockIdx.x * blockDim.x + threadIdx.x) >> 5;
    const int nwarps = (gridDim.x * blockDim.x) >> 5;
    for (int n = warp; n < NSN + NDN; n += nwarps) {
        const bool isd = (n >= NSN);
        const int idx = isd ? n - NSN : n;
        const float* xf = (isd ? dst_f : src_f) + (size_t)idx * 64;
        float x0 = xf[l], x1 = xf[l+32];
        float s = x0 + x1;
        #pragma unroll
        for (int o = 16; o; o >>= 1) s += __shfl_xor_sync(~0u, s, o);
        const float mean = s * (1.0f/64.0f);
        const float c0 = x0 - mean, c1 = x1 - mean;
        float v = c0*c0 + c1*c1;
        #pragma unroll
        for (int o = 16; o; o >>= 1) v += __shfl_xor_sync(~0u, v, o);
        const float rs = rsqrtf(v * (1.0f/64.0f) + LNEPS);
        const float* lw = isd ? lndw : lnsw;
        const float* lb = isd ? lndb : lnsb;
        const float y0 = c0 * rs * lw[l]    + lb[l];
        const float y1 = c1 * rs * lw[l+32] + lb[l+32];
        const float* W = sW + (isd ? 4096 : 0);
        float a0 = 0.0f, a1 = 0.0f;
        #pragma unroll
        for (int k = 0; k < 32; k++) {
            float b = __shfl_sync(~0u, y0, k);
            a0 += b * W[k*64 + l];
            a1 += b * W[k*64 + l + 32];
        }
        #pragma unroll
        for (int k = 0; k < 32; k++) {
            float b = __shfl_sync(~0u, y1, k);
            a0 += b * W[(k+32)*64 + l];
            a1 += b * W[(k+32)*64 + l + 32];
        }
        if (isd) { a0 += bdst[l]; a1 += bdst[l+32]; }
        float* out = isd ? g_md : g_ms;
        out[(size_t)idx*64 + l]      = a0;
        out[(size_t)idx*64 + l + 32] = a1;
    }
}

// ---------------- heavy fused edge kernel: 512 threads, 128-edge tiles ----------------
#define TEDGE 128
#define NTILE2 ((EE + TEDGE - 1) / TEDGE)   // 4688
#define SDE 132                              // [k][edge] stride
#define OFF_WR1   0
#define OFF_WR2   4096
#define OFF_WEA   12288
#define OFF_WDTP  13312
#define OFF_BR1   21504
#define OFF_BR2   21568
#define OFF_AL    21696
#define OFF_ESt   21760                      // 64*132 = 8448
#define OFF_Rt    (OFF_ESt + 8448)           // 30208
#define OFF_MSGt  (OFF_Rt  + 8448)           // 38656
#define OFF_EAt   (OFF_MSGt+ 8448)           // 47104, 16*132 = 2112
#define SMEM_EDGE_FLOATS (OFF_EAt + 2112)    // 49216 floats = 196864 B

__global__ void __launch_bounds__(512, 1)
k_edge(const float* __restrict__ es_g, const float* __restrict__ ea_g,
       const float* __restrict__ el_g,
       const int* __restrict__ esrc, const int* __restrict__ edst,
       const float* __restrict__ Wr1, const float* __restrict__ br1,
       const float* __restrict__ Wr2, const float* __restrict__ br2,
       const float* __restrict__ Wea, const float* __restrict__ Wdtp,
       const float* __restrict__ alpha) {
    extern __shared__ float sm[];
    float* sWr1  = sm + OFF_WR1;
    float* sWr2  = sm + OFF_WR2;
    float* sWea  = sm + OFF_WEA;
    float* sWdtp = sm + OFF_WDTP;
    float* sbr1  = sm + OFF_BR1;
    float* sbr2  = sm + OFF_BR2;
    float* sal   = sm + OFF_AL;
    float* sESt  = sm + OFF_ESt;
    float* sRt   = sm + OFF_Rt;
    float* sMSGt = sm + OFF_MSGt;
    float* sEAt  = sm + OFF_EAt;

    const int tid = threadIdx.x;
    for (int i = tid; i < 4096; i += 512) sWr1[i]  = Wr1[i];
    for (int i = tid; i < 8192; i += 512) sWr2[i]  = Wr2[i];
    for (int i = tid; i < 1024; i += 512) sWea[i]  = Wea[i];
    for (int i = tid; i < 8192; i += 512) sWdtp[i] = Wdtp[i];
    if (tid < 64)  sbr1[tid] = br1[tid];
    if (tid < 128) sbr2[tid] = br2[tid];
    if (tid < 64)  sal[tid]  = alpha[tid];

    const int te = tid & 31;      // edge group -> 4 edges (lane)
    const int tc = tid >> 5;      // col group [0,16) (warp)
    const int e0 = te * 4;

    for (int tile = blockIdx.x; tile < NTILE2; tile += gridDim.x) {
        const int base = tile * TEDGE;
        __syncthreads();  // previous tile consumed (covers weight load on iter 1)

        // ---- stage: ES^T, MSG^T (gather), EA^T ----
        {
            const int e = tid >> 2, p = tid & 3;
            int ge = base + e; if (ge >= EE) ge = EE - 1;
            const float4* esrow = (const float4*)(es_g + (size_t)ge*64 + p*16);
            const int sidx = esrc[ge], didx = edst[ge];
            const float4* msr = (const float4*)(g_ms + (size_t)sidx*64 + p*16);
            const float4* mdr = (const float4*)(g_md + (size_t)didx*64 + p*16);
            #pragma unroll
            for (int q = 0; q < 4; q++) {
                float4 v = esrow[q];
                int k0 = p*16 + q*4;
                sESt[(k0+0)*SDE + e] = v.x;
                sESt[(k0+1)*SDE + e] = v.y;
                sESt[(k0+2)*SDE + e] = v.z;
                sESt[(k0+3)*SDE + e] = v.w;
                float4 a = msr[q], d = mdr[q];
                sMSGt[(k0+0)*SDE + e] = a.x + d.x;
                sMSGt[(k0+1)*SDE + e] = a.y + d.y;
                sMSGt[(k0+2)*SDE + e] = a.z + d.z;
                sMSGt[(k0+3)*SDE + e] = a.w + d.w;
            }
            if (tid < TEDGE) {
                int ge2 = base + tid; if (ge2 >= EE) ge2 = EE - 1;
                const float4* ear = (const float4*)(ea_g + (size_t)ge2*16);
                #pragma unroll
                for (int q = 0; q < 4; q++) {
                    float4 v = ear[q];
                    sEAt[(q*4+0)*SDE + tid] = v.x;
                    sEAt[(q*4+1)*SDE + tid] = v.y;
                    sEAt[(q*4+2)*SDE + tid] = v.z;
                    sEAt[(q*4+3)*SDE + tid] = v.w;
                }
            }
        }
        __syncthreads();

        // ---- GEMM1: r = silu(es @ Wr1 + br1) [128e, 64c] -> sRt ; Gea -> regs ----
        u64 ea2[4][2] = {};
        {
            u64 acc[4][2] = {};
            #pragma unroll 4
            for (int k = 0; k < 64; k++) {
                float4 xv = *(const float4*)(sESt + k*SDE + e0);
                ulonglong2 wp = *(const ulonglong2*)(sWr1 + k*64 + tc*4);
                u64 xp;
                PK2(xp, xv.x); FFMA2(acc[0][0], xp, wp.x, acc[0][0]); FFMA2(acc[0][1], xp, wp.y, acc[0][1]);
                PK2(xp, xv.y); FFMA2(acc[1][0], xp, wp.x, acc[1][0]); FFMA2(acc[1][1], xp, wp.y, acc[1][1]);
                PK2(xp, xv.z); FFMA2(acc[2][0], xp, wp.x, acc[2][0]); FFMA2(acc[2][1], xp, wp.y, acc[2][1]);
                PK2(xp, xv.w); FFMA2(acc[3][0], xp, wp.x, acc[3][0]); FFMA2(acc[3][1], xp, wp.y, acc[3][1]);
            }
            // silu + write transposed, float4 per column across the 4 edges
            #pragma unroll
            for (int jp = 0; jp < 2; jp++) {
                float lo[4], hi[4];
                #pragma unroll
                for (int i = 0; i < 4; i++) UPK2(lo[i], hi[i], acc[i][jp]);
                float b0 = sbr1[tc*4 + 2*jp], b1 = sbr1[tc*4 + 2*jp + 1];
                float4 v0, v1;
                v0.x = lo[0]+b0; v0.y = lo[1]+b0; v0.z = lo[2]+b0; v0.w = lo[3]+b0;
                v1.x = hi[0]+b1; v1.y = hi[1]+b1; v1.z = hi[2]+b1; v1.w = hi[3]+b1;
                v0.x /= (1.0f + __expf(-v0.x)); v0.y /= (1.0f + __expf(-v0.y));
                v0.z /= (1.0f + __expf(-v0.z)); v0.w /= (1.0f + __expf(-v0.w));
                v1.x /= (1.0f + __expf(-v1.x)); v1.y /= (1.0f + __expf(-v1.y));
                v1.z /= (1.0f + __expf(-v1.z)); v1.w /= (1.0f + __expf(-v1.w));
                *(float4*)(sRt + (tc*4 + 2*jp)*SDE   + e0) = v0;
                *(float4*)(sRt + (tc*4 + 2*jp+1)*SDE + e0) = v1;
            }
            // Gea: ea2 = edge_attr @ Wea [128e, 64c]
            #pragma unroll
            for (int k = 0; k < 16; k++) {
                float4 xv = *(const float4*)(sEAt + k*SDE + e0);
                ulonglong2 wp = *(const ulonglong2*)(sWea + k*64 + tc*4);
                u64 xp;
                PK2(xp, xv.x); FFMA2(ea2[0][0], xp, wp.x, ea2[0][0]); FFMA2(ea2[0][1], xp, wp.y, ea2[0][1]);
                PK2(xp, xv.y); FFMA2(ea2[1][0], xp, wp.x, ea2[1][0]); FFMA2(ea2[1][1], xp, wp.y, ea2[1][1]);
                PK2(xp, xv.z); FFMA2(ea2[2][0], xp, wp.x, ea2[2][0]); FFMA2(ea2[2][1], xp, wp.y, ea2[2][1]);
                PK2(xp, xv.w); FFMA2(ea2[3][0], xp, wp.x, ea2[3][0]); FFMA2(ea2[3][1], xp, wp.y, ea2[3][1]);
            }
            // T = msg * ea2 written into sMSGt (exclusive cells, staged before sync)
            #pragma unroll
            for (int jp = 0; jp < 2; jp++) {
                #pragma unroll
                for (int h = 0; h < 2; h++) {
                    const int c = tc*4 + 2*jp + h;
                    float4 m4 = *(float4*)(sMSGt + c*SDE + e0);
                    float v0, v1, v2, v3, dummy;
                    if (h == 0) {
                        UPK2(v0, dummy, ea2[0][jp]); UPK2(v1, dummy, ea2[1][jp]);
                        UPK2(v2, dummy, ea2[2][jp]); UPK2(v3, dummy, ea2[3][jp]);
                    } else {
                        UPK2(dummy, v0, ea2[0][jp]); UPK2(dummy, v1, ea2[1][jp]);
                        UPK2(dummy, v2, ea2[2][jp]); UPK2(dummy, v3, ea2[3][jp]);
                    }
                    m4.x *= v0; m4.y *= v1; m4.z *= v2; m4.w *= v3;
                    *(float4*)(sMSGt + c*SDE + e0) = m4;
                }
            }
        }
        __syncthreads();   // sRt + T(sMSGt) complete

        // ---- GEMM2: w_edge = r @ Wr2 + br2 [128e, 128c] (regs) ----
        u64 we[4][4];
        {
            u64 acc[4][4] = {};
            #pragma unroll 2
            for (int k = 0; k < 64; k++) {
                float4 xv = *(const float4*)(sRt + k*SDE + e0);
                ulonglong2 wa = *(const ulonglong2*)(sWr2 + k*128 + tc*8);
                ulonglong2 wb = *(const ulonglong2*)(sWr2 + k*128 + tc*8 + 4);
                u64 xp;
                PK2(xp, xv.x);
                FFMA2(acc[0][0], xp, wa.x, acc[0][0]); FFMA2(acc[0][1], xp, wa.y, acc[0][1]);
                FFMA2(acc[0][2], xp, wb.x, acc[0][2]); FFMA2(acc[0][3], xp, wb.y, acc[0][3]);
                PK2(xp, xv.y);
                FFMA2(acc[1][0], xp, wa.x, acc[1][0]); FFMA2(acc[1][1], xp, wa.y, acc[1][1]);
                FFMA2(acc[1][2], xp, wb.x, acc[1][2]); FFMA2(acc[1][3], xp, wb.y, acc[1][3]);
                PK2(xp, xv.z);
                FFMA2(acc[2][0], xp, wa.x, acc[2][0]); FFMA2(acc[2][1], xp, wa.y, acc[2][1]);
                FFMA2(acc[2][2], xp, wb.x, acc[2][2]); FFMA2(acc[2][3], xp, wb.y, acc[2][3]);
                PK2(xp, xv.w);
                FFMA2(acc[3][0], xp, wa.x, acc[3][0]); FFMA2(acc[3][1], xp, wa.y, acc[3][1]);
                FFMA2(acc[3][2], xp, wb.x, acc[3][2]); FFMA2(acc[3][3], xp, wb.y, acc[3][3]);
            }
            #pragma unroll
            for (int i = 0; i < 4; i++)
                #pragma unroll
                for (int jp = 0; jp < 4; jp++) {
                    u64 b = *(const u64*)(sbr2 + tc*8 + 2*jp);
                    ADD2(we[i][jp], acc[i][jp], b);
                }
        }

        // ---- GEMM3: dtp = (T @ Wdtp) * w_edge [128e, 128c] ----
        u64 dtp[4][4];
        {
            u64 acc[4][4] = {};
            #pragma unroll 2
            for (int k = 0; k < 64; k++) {
                float4 xv = *(const float4*)(sMSGt + k*SDE + e0);
                ulonglong2 wa = *(const ulonglong2*)(sWdtp + k*128 + tc*8);
                ulonglong2 wb = *(const ulonglong2*)(sWdtp + k*128 + tc*8 + 4);
                u64 xp;
                PK2(xp, xv.x);
                FFMA2(acc[0][0], xp, wa.x, acc[0][0]); FFMA2(acc[0][1], xp, wa.y, acc[0][1]);
                FFMA2(acc[0][2], xp, wb.x, acc[0][2]); FFMA2(acc[0][3], xp, wb.y, acc[0][3]);
                PK2(xp, xv.y);
                FFMA2(acc[1][0], xp, wa.x, acc[1][0]); FFMA2(acc[1][1], xp, wa.y, acc[1][1]);
                FFMA2(acc[1][2], xp, wb.x, acc[1][2]); FFMA2(acc[1][3], xp, wb.y, acc[1][3]);
                PK2(xp, xv.z);
                FFMA2(acc[2][0], xp, wa.x, acc[2][0]); FFMA2(acc[2][1], xp, wa.y, acc[2][1]);
                FFMA2(acc[2][2], xp, wb.x, acc[2][2]); FFMA2(acc[2][3], xp, wb.y, acc[2][3]);
                PK2(xp, xv.w);
                FFMA2(acc[3][0], xp, wa.x, acc[3][0]); FFMA2(acc[3][1], xp, wa.y, acc[3][1]);
                FFMA2(acc[3][2], xp, wb.x, acc[3][2]); FFMA2(acc[3][3], xp, wb.y, acc[3][3]);
            }
            #pragma unroll
            for (int i = 0; i < 4; i++)
                #pragma unroll
                for (int jp = 0; jp < 4; jp++)
                    MUL2(dtp[i][jp], acc[i][jp], we[i][jp]);
        }

        // ---- epilogue ----
        if (tc < 8) {
            #pragma unroll
            for (int i = 0; i < 4; i++) {
                const int ge = base + e0 + i;
                if (ge >= EE) continue;
                float lg = 0.0f;
                #pragma unroll
                for (int jp = 0; jp < 4; jp++) {
                    float x0, x1;
                    UPK2(x0, x1, dtp[i][jp]);
                    float lr0 = (x0 > 0.0f) ? x0 : 0.2f * x0;
                    float lr1 = (x1 > 0.0f) ? x1 : 0.2f * x1;
                    lg += lr0 * sal[tc*8 + 2*jp] + lr1 * sal[tc*8 + 2*jp + 1];
                }
                lg += el_g[ge];
                const int d = edst[ge];
                g_att[(size_t)ge*8 + tc] = lg;
                atomicMaxFloat(&g_max[(size_t)d*8 + tc], lg);
            }
        } else {
            const int c = (tc - 8) * 8;
            #pragma unroll
            for (int i = 0; i < 4; i++) {
                const int ge = base + e0 + i;
                if (ge >= EE) continue;
                float4 v0, v1;
                UPK2(v0.x, v0.y, dtp[i][0]); UPK2(v0.z, v0.w, dtp[i][1]);
                UPK2(v1.x, v1.y, dtp[i][2]); UPK2(v1.z, v1.w, dtp[i][3]);
                *(float4*)(g_val + (size_t)ge*64 + c)     = v0;
                *(float4*)(g_val + (size_t)ge*64 + c + 4) = v1;
            }
        }
    }
}

// ---------------- softmax pass 2 ----------------
__global__ void k_soft(const int* __restrict__ edst) {
    int i = blockIdx.x * blockDim.x + threadIdx.x;
    if (i >= EE*HH) return;
    int e = i >> 3, h = i & 7;
    int d = edst[e];
    float a = __expf(g_att[i] - g_max[(size_t)d*8 + h]);
    g_att[i] = a;
    atomicAdd(&g_z[(size_t)d*8 + h], a);
}

// ---------------- scatter: one thread per (edge, head) ----------------
__global__ void k_scat(const int* __restrict__ edst) {
    int i = blockIdx.x * blockDim.x + threadIdx.x;
    if (i >= EE*HH) return;
    int e = i >> 3, h = i & 7;
    int d = edst[e];
    float attn = g_att[i] / g_z[(size_t)d*8 + h];
    const float4* v = (const float4*)(g_val + (size_t)e*64 + h*8);
    float4 a = v[0], b = v[1];
    float* dst = g_acc + (size_t)d*64 + h*8;
    atomicAdd(dst+0, a.x*attn); atomicAdd(dst+1, a.y*attn);
    atomicAdd(dst+2, a.z*attn); atomicAdd(dst+3, a.w*attn);
    atomicAdd(dst+4, b.x*attn); atomicAdd(dst+5, b.y*attn);
    atomicAdd(dst+6, b.z*attn); atomicAdd(dst+7, b.w*attn);
}

// ---------------- final ----------------
#define SMEM_FIN_FLOATS 28672
__global__ void __launch_bounds__(256, 1)
k_final(const float* __restrict__ dst_f,
        const float* __restrict__ Wp, const float* __restrict__ bp,
        const float* __restrict__ lnw, const float* __restrict__ lnb,
        const float* __restrict__ Wf1, const float* __restrict__ bf1,
        const float* __restrict__ Wf2, const float* __restrict__ bf2,
        float* __restrict__ out) {
    extern __shared__ float sm[];
    float* sWp  = sm;
    float* sWf1 = sm + 4096;
    float* sWf2 = sm + 16384;
    for (int i = threadIdx.x; i < 4096;  i += blockDim.x) sWp[i]  = Wp[i];
    for (int i = threadIdx.x; i < 12288; i += blockDim.x) sWf1[i] = Wf1[i];
    for (int i = threadIdx.x; i < 12288; i += blockDim.x) sWf2[i] = Wf2[i];
    __syncthreads();
    const int l = threadIdx.x & 31;
    const int warp = (blockIdx.x * blockDim.x + threadIdx.x) >> 5;
    const int nw = (gridDim.x * blockDim.x) >> 5;
    for (int n = warp; n < NDN; n += nw) {
        float i0 = g_acc[(size_t)n*64 + l], i1 = g_acc[(size_t)n*64 + l + 32];
        float o0 = bp[l], o1 = bp[l+32];
        #pragma unroll
        for (int k = 0; k < 32; k++) {
            float b = __shfl_sync(~0u, i0, k);
            o0 += b * sWp[k*64 + l];
            o1 += b * sWp[k*64 + l + 32];
        }
        #pragma unroll
        for (int k = 0; k < 32; k++) {
            float b = __shfl_sync(~0u, i1, k);
            o0 += b * sWp[(k+32)*64 + l];
            o1 += b * sWp[(k+32)*64 + l + 32];
        }
        const float e0 = o0 + dst_f[(size_t)n*64 + l];
        const float e1 = o1 + dst_f[(size_t)n*64 + l + 32];
        float s = e0 + e1;
        #pragma unroll
        for (int o = 16; o; o >>= 1) s += __shfl_xor_sync(~0u, s, o);
        const float mean = s * (1.0f/64.0f);
        const float c0 = e0 - mean, c1 = e1 - mean;
        float v = c0*c0 + c1*c1;
        #pragma unroll
        for (int o = 16; o; o >>= 1) v += __shfl_xor_sync(~0u, v, o);
        const float rs = rsqrtf(v * (1.0f/64.0f) + LNEPS);
        const float y0 = c0 * rs * lnw[l]    + lnb[l];
        const float y1 = c1 * rs * lnw[l+32] + lnb[l+32];
        float h[6];
        #pragma unroll
        for (int i = 0; i < 6; i++) h[i] = bf1[l + 32*i];
        #pragma unroll
        for (int k = 0; k < 32; k++) {
            float b = __shfl_sync(~0u, y0, k);
            #pragma unroll
            for (int i = 0; i < 6; i++) h[i] += b * sWf1[k*192 + l + 32*i];
        }
        #pragma unroll
        for (int k = 0; k < 32; k++) {
            float b = __shfl_sync(~0u, y1, k);
            #pragma unroll
            for (int i = 0; i < 6; i++) h[i] += b * sWf1[(k+32)*192 + l + 32*i];
        }
        #pragma unroll
        for (int i = 0; i < 6; i++) h[i] = h[i] / (1.0f + __expf(-h[i]));
        float f0 = bf2[l], f1 = bf2[l+32];
        #pragma unroll
        for (int kk = 0; kk < 6; kk++)
            #pragma unroll
            for (int k2 = 0; k2 < 32; k2++) {
                float b = __shfl_sync(~0u, h[kk], k2);
                f0 += b * sWf2[(kk*32 + k2)*64 + l];
                f1 += b * sWf2[(kk*32 + k2)*64 + l + 32];
            }
        out[(size_t)n*64 + l]      = f0 + e0;
        out[(size_t)n*64 + l + 32] = f1 + e1;
    }
}

// ---------------- launch ----------------
extern "C" void kernel_launch(void* const* d_in, const int* in_sizes, int n_in,
                              void* d_out, int out_size) {
    const float* src_f        = (const float*)d_in[0];
    const float* dst_f        = (const float*)d_in[1];
    const float* edge_attr    = (const float*)d_in[2];
    const float* edge_scalars = (const float*)d_in[3];
    const float* edge_logits  = (const float*)d_in[4];
    const int*   edge_src     = (const int*)d_in[5];
    const int*   edge_dst     = (const int*)d_in[6];
    const float* ln_src_w = (const float*)d_in[7];
    const float* ln_src_b = (const float*)d_in[8];
    const float* W_src    = (const float*)d_in[9];
    const float* ln_dst_w = (const float*)d_in[10];
    const float* ln_dst_b = (const float*)d_in[11];
    const float* W_dst    = (const float*)d_in[12];
    const float* b_dst    = (const float*)d_in[13];
    const float* W_ea     = (const float*)d_in[14];
    const float* W_dtp    = (const float*)d_in[15];
    const float* W_r1     = (const float*)d_in[16];
    const float* b_r1     = (const float*)d_in[17];
    const float* W_r2     = (const float*)d_in[18];
    const float* b_r2     = (const float*)d_in[19];
    const float* alpha    = (const float*)d_in[20];
    const float* W_proj   = (const float*)d_in[21];
    const float* b_proj   = (const float*)d_in[22];
    const float* ln_post_w = (const float*)d_in[23];
    const float* ln_post_b = (const float*)d_in[24];
    const float* W_f1     = (const float*)d_in[25];
    const float* b_f1     = (const float*)d_in[26];
    const float* W_f2     = (const float*)d_in[27];
    const float* b_f2     = (const float*)d_in[28];
    float* out = (float*)d_out;

    cudaFuncSetAttribute(k_edge, cudaFuncAttributeMaxDynamicSharedMemorySize,
                         SMEM_EDGE_FLOATS * 4);
    cudaFuncSetAttribute(k_final, cudaFuncAttributeMaxDynamicSharedMemorySize,
                         SMEM_FIN_FLOATS * 4);

    k_init<<<(NDN*CC + 255)/256, 256>>>();
    k_node<<<1600, 256>>>(src_f, dst_f, ln_src_w, ln_src_b, W_src,
                          ln_dst_w, ln_dst_b, W_dst, b_dst);
    k_edge<<<148, 512, SMEM_EDGE_FLOATS*4>>>(edge_scalars, edge_attr, edge_logits,
                                             edge_src, edge_dst,
                                             W_r1, b_r1, W_r2, b_r2, W_ea, W_dtp, alpha);
    k_soft<<<(EE*HH + 255)/256, 256>>>(edge_dst);
    k_scat<<<(EE*HH + 255)/256, 256>>>(edge_dst);
    k_final<<<800, 256, SMEM_FIN_FLOATS*4>>>(dst_f, W_proj, b_proj,
                                             ln_post_w, ln_post_b,
                                             W_f1, b_f1, W_f2, b_f2, out);
}

// round 6
// speedup vs baseline: 1.2939x; 1.1203x over previous
#include <cuda_runtime.h>
#include <cstdint>

#define NSN 50000
#define NDN 50000
#define EE  600000
#define CC  64
#define HH  8
#define LNEPS 1e-5f

typedef unsigned long long u64;

// packed f32x2 helpers (SASS FFMA2 — only reachable via PTX fma.rn.f32x2)
#define FFMA2(d, a, b, c) asm("fma.rn.f32x2 %0, %1, %2, %3;" : "=l"(d) : "l"(a), "l"(b), "l"(c))
#define MUL2(d, a, b)     asm("mul.rn.f32x2 %0, %1, %2;"     : "=l"(d) : "l"(a), "l"(b))
#define ADD2(d, a, b)     asm("add.rn.f32x2 %0, %1, %2;"     : "=l"(d) : "l"(a), "l"(b))
#define PK2(d, x)         asm("mov.b64 %0, {%1, %1};"        : "=l"(d) : "f"(x))
#define UPK2(lo, hi, v)   asm("mov.b64 {%0, %1}, %2;"        : "=f"(lo), "=f"(hi) : "l"(v))

// ---------------- scratch ----------------
__device__ float g_ms[(size_t)NSN*CC];
__device__ float g_md[(size_t)NDN*CC];
__device__ float g_val[(size_t)EE*CC];
__device__ float g_att[(size_t)EE*HH];
__device__ float g_max[(size_t)NDN*HH];
__device__ float g_z[(size_t)NDN*HH];
__device__ float g_acc[(size_t)NDN*CC];

__device__ __forceinline__ void atomicMaxFloat(float* addr, float v) {
    if (v >= 0.0f) atomicMax((int*)addr, __float_as_int(v));
    else           atomicMin((unsigned int*)addr, __float_as_uint(v));
}

// ---------------- init ----------------
__global__ void k_init() {
    int i = blockIdx.x * blockDim.x + threadIdx.x;
    if (i < NDN*HH) { g_max[i] = __int_as_float(0xFF800000); g_z[i] = 0.0f; }
    if (i < NDN*CC) g_acc[i] = 0.0f;
}

// ---------------- node projections ----------------
__global__ void k_node(const float* __restrict__ src_f, const float* __restrict__ dst_f,
                       const float* __restrict__ lnsw, const float* __restrict__ lnsb,
                       const float* __restrict__ Wsrc,
                       const float* __restrict__ lndw, const float* __restrict__ lndb,
                       const float* __restrict__ Wdst, const float* __restrict__ bdst) {
    __shared__ float sW[2*64*64];
    for (int i = threadIdx.x; i < 8192; i += blockDim.x)
        sW[i] = (i < 4096) ? Wsrc[i] : Wdst[i-4096];
    __syncthreads();
    const int l = threadIdx.x & 31;
    const int warp = (blockIdx.x * blockDim.x + threadIdx.x) >> 5;
    const int nwarps = (gridDim.x * blockDim.x) >> 5;
    for (int n = warp; n < NSN + NDN; n += nwarps) {
        const bool isd = (n >= NSN);
        const int idx = isd ? n - NSN : n;
        const float* xf = (isd ? dst_f : src_f) + (size_t)idx * 64;
        float x0 = xf[l], x1 = xf[l+32];
        float s = x0 + x1;
        #pragma unroll
        for (int o = 16; o; o >>= 1) s += __shfl_xor_sync(~0u, s, o);
        const float mean = s * (1.0f/64.0f);
        const float c0 = x0 - mean, c1 = x1 - mean;
        float v = c0*c0 + c1*c1;
        #pragma unroll
        for (int o = 16; o; o >>= 1) v += __shfl_xor_sync(~0u, v, o);
        const float rs = rsqrtf(v * (1.0f/64.0f) + LNEPS);
        const float* lw = isd ? lndw : lnsw;
        const float* lb = isd ? lndb : lnsb;
        const float y0 = c0 * rs * lw[l]    + lb[l];
        const float y1 = c1 * rs * lw[l+32] + lb[l+32];
        const float* W = sW + (isd ? 4096 : 0);
        float a0 = 0.0f, a1 = 0.0f;
        #pragma unroll
        for (int k = 0; k < 32; k++) {
            float b = __shfl_sync(~0u, y0, k);
            a0 += b * W[k*64 + l];
            a1 += b * W[k*64 + l + 32];
        }
        #pragma unroll
        for (int k = 0; k < 32; k++) {
            float b = __shfl_sync(~0u, y1, k);
            a0 += b * W[(k+32)*64 + l];
            a1 += b * W[(k+32)*64 + l + 32];
        }
        if (isd) { a0 += bdst[l]; a1 += bdst[l+32]; }
        float* out = isd ? g_md : g_ms;
        out[(size_t)idx*64 + l]      = a0;
        out[(size_t)idx*64 + l + 32] = a1;
    }
}

// ---------------- heavy fused edge kernel: 256 threads, 128-edge tiles, 4e x 16c ----------------
#define TEDGE 128
#define NTILE2 ((EE + TEDGE - 1) / TEDGE)   // 4688
#define SDE 132                              // [k][edge] stride
#define OFF_WR1   0
#define OFF_WR2   4096
#define OFF_WEA   12288
#define OFF_WDTP  13312
#define OFF_BR1   21504
#define OFF_BR2   21568
#define OFF_AL    21696
#define OFF_ESt   21760                      // 64*132 = 8448
#define OFF_Rt    (OFF_ESt + 8448)           // 30208
#define OFF_MSGt  (OFF_Rt  + 8448)           // 38656
#define OFF_EAt   (OFF_MSGt+ 8448)           // 47104, 16*132 = 2112
#define SMEM_EDGE_FLOATS (OFF_EAt + 2112)    // 49216 floats = 196864 B

__global__ void __launch_bounds__(256, 1)
k_edge(const float* __restrict__ es_g, const float* __restrict__ ea_g,
       const float* __restrict__ el_g,
       const int* __restrict__ esrc, const int* __restrict__ edst,
       const float* __restrict__ Wr1, const float* __restrict__ br1,
       const float* __restrict__ Wr2, const float* __restrict__ br2,
       const float* __restrict__ Wea, const float* __restrict__ Wdtp,
       const float* __restrict__ alpha) {
    extern __shared__ float sm[];
    float* sWr1  = sm + OFF_WR1;
    float* sWr2  = sm + OFF_WR2;
    float* sWea  = sm + OFF_WEA;
    float* sWdtp = sm + OFF_WDTP;
    float* sbr1  = sm + OFF_BR1;
    float* sbr2  = sm + OFF_BR2;
    float* sal   = sm + OFF_AL;
    float* sESt  = sm + OFF_ESt;
    float* sRt   = sm + OFF_Rt;
    float* sMSGt = sm + OFF_MSGt;
    float* sEAt  = sm + OFF_EAt;

    const int tid = threadIdx.x;
    for (int i = tid; i < 4096; i += 256) sWr1[i]  = Wr1[i];
    for (int i = tid; i < 8192; i += 256) sWr2[i]  = Wr2[i];
    for (int i = tid; i < 1024; i += 256) sWea[i]  = Wea[i];
    for (int i = tid; i < 8192; i += 256) sWdtp[i] = Wdtp[i];
    if (tid < 64)  sbr1[tid] = br1[tid];
    if (tid < 128) sbr2[tid] = br2[tid];
    if (tid < 64)  sal[tid]  = alpha[tid];

    const int te = tid & 31;      // lane -> 4 edges
    const int tc = tid >> 5;      // warp -> col group [0,8)
    const int e0 = te * 4;

    for (int tile = blockIdx.x; tile < NTILE2; tile += gridDim.x) {
        const int base = tile * TEDGE;
        __syncthreads();  // previous tile consumed (covers weight load on iter 1)

        // ---- stage: ES^T, MSG^T (gather), EA^T ----
        {
            #pragma unroll
            for (int j = 0; j < 2; j++) {
                const int idx = tid + j*256;
                const int e = idx >> 2, p = idx & 3;
                int ge = base + e; if (ge >= EE) ge = EE - 1;
                const float4* esrow = (const float4*)(es_g + (size_t)ge*64 + p*16);
                const int sidx = esrc[ge], didx = edst[ge];
                const float4* msr = (const float4*)(g_ms + (size_t)sidx*64 + p*16);
                const float4* mdr = (const float4*)(g_md + (size_t)didx*64 + p*16);
                #pragma unroll
                for (int q = 0; q < 4; q++) {
                    float4 v = esrow[q];
                    int k0 = p*16 + q*4;
                    sESt[(k0+0)*SDE + e] = v.x;
                    sESt[(k0+1)*SDE + e] = v.y;
                    sESt[(k0+2)*SDE + e] = v.z;
                    sESt[(k0+3)*SDE + e] = v.w;
                    float4 a = msr[q], d = mdr[q];
                    sMSGt[(k0+0)*SDE + e] = a.x + d.x;
                    sMSGt[(k0+1)*SDE + e] = a.y + d.y;
                    sMSGt[(k0+2)*SDE + e] = a.z + d.z;
                    sMSGt[(k0+3)*SDE + e] = a.w + d.w;
                }
            }
            if (tid < TEDGE) {
                int ge2 = base + tid; if (ge2 >= EE) ge2 = EE - 1;
                const float4* ear = (const float4*)(ea_g + (size_t)ge2*16);
                #pragma unroll
                for (int q = 0; q < 4; q++) {
                    float4 v = ear[q];
                    sEAt[(q*4+0)*SDE + tid] = v.x;
                    sEAt[(q*4+1)*SDE + tid] = v.y;
                    sEAt[(q*4+2)*SDE + tid] = v.z;
                    sEAt[(q*4+3)*SDE + tid] = v.w;
                }
            }
        }
        __syncthreads();

        // ---- GEMM1: r = silu(es @ Wr1 + br1) [128e, 64c] -> sRt ; Gea -> regs ----
        u64 ea2[4][4] = {};
        {
            u64 acc[4][4] = {};
            #pragma unroll 4
            for (int k = 0; k < 64; k++) {
                float4 xv = *(const float4*)(sESt + k*SDE + e0);
                ulonglong2 wa = *(const ulonglong2*)(sWr1 + k*64 + tc*8);
                ulonglong2 wb = *(const ulonglong2*)(sWr1 + k*64 + tc*8 + 4);
                u64 xp;
                PK2(xp, xv.x);
                FFMA2(acc[0][0], xp, wa.x, acc[0][0]); FFMA2(acc[0][1], xp, wa.y, acc[0][1]);
                FFMA2(acc[0][2], xp, wb.x, acc[0][2]); FFMA2(acc[0][3], xp, wb.y, acc[0][3]);
                PK2(xp, xv.y);
                FFMA2(acc[1][0], xp, wa.x, acc[1][0]); FFMA2(acc[1][1], xp, wa.y, acc[1][1]);
                FFMA2(acc[1][2], xp, wb.x, acc[1][2]); FFMA2(acc[1][3], xp, wb.y, acc[1][3]);
                PK2(xp, xv.z);
                FFMA2(acc[2][0], xp, wa.x, acc[2][0]); FFMA2(acc[2][1], xp, wa.y, acc[2][1]);
                FFMA2(acc[2][2], xp, wb.x, acc[2][2]); FFMA2(acc[2][3], xp, wb.y, acc[2][3]);
                PK2(xp, xv.w);
                FFMA2(acc[3][0], xp, wa.x, acc[3][0]); FFMA2(acc[3][1], xp, wa.y, acc[3][1]);
                FFMA2(acc[3][2], xp, wb.x, acc[3][2]); FFMA2(acc[3][3], xp, wb.y, acc[3][3]);
            }
            // silu + write transposed, float4 per column across the 4 edges
            #pragma unroll
            for (int jp = 0; jp < 4; jp++) {
                float lo[4], hi[4];
                #pragma unroll
                for (int i = 0; i < 4; i++) UPK2(lo[i], hi[i], acc[i][jp]);
                float b0 = sbr1[tc*8 + 2*jp], b1 = sbr1[tc*8 + 2*jp + 1];
                float4 v0, v1;
                v0.x = lo[0]+b0; v0.y = lo[1]+b0; v0.z = lo[2]+b0; v0.w = lo[3]+b0;
                v1.x = hi[0]+b1; v1.y = hi[1]+b1; v1.z = hi[2]+b1; v1.w = hi[3]+b1;
                v0.x /= (1.0f + __expf(-v0.x)); v0.y /= (1.0f + __expf(-v0.y));
                v0.z /= (1.0f + __expf(-v0.z)); v0.w /= (1.0f + __expf(-v0.w));
                v1.x /= (1.0f + __expf(-v1.x)); v1.y /= (1.0f + __expf(-v1.y));
                v1.z /= (1.0f + __expf(-v1.z)); v1.w /= (1.0f + __expf(-v1.w));
                *(float4*)(sRt + (tc*8 + 2*jp)*SDE   + e0) = v0;
                *(float4*)(sRt + (tc*8 + 2*jp+1)*SDE + e0) = v1;
            }
            // Gea: ea2 = edge_attr @ Wea [128e, 64c]
            #pragma unroll
            for (int k = 0; k < 16; k++) {
                float4 xv = *(const float4*)(sEAt + k*SDE + e0);
                ulonglong2 wa = *(const ulonglong2*)(sWea + k*64 + tc*8);
                ulonglong2 wb = *(const ulonglong2*)(sWea + k*64 + tc*8 + 4);
                u64 xp;
                PK2(xp, xv.x);
                FFMA2(ea2[0][0], xp, wa.x, ea2[0][0]); FFMA2(ea2[0][1], xp, wa.y, ea2[0][1]);
                FFMA2(ea2[0][2], xp, wb.x, ea2[0][2]); FFMA2(ea2[0][3], xp, wb.y, ea2[0][3]);
                PK2(xp, xv.y);
                FFMA2(ea2[1][0], xp, wa.x, ea2[1][0]); FFMA2(ea2[1][1], xp, wa.y, ea2[1][1]);
                FFMA2(ea2[1][2], xp, wb.x, ea2[1][2]); FFMA2(ea2[1][3], xp, wb.y, ea2[1][3]);
                PK2(xp, xv.z);
                FFMA2(ea2[2][0], xp, wa.x, ea2[2][0]); FFMA2(ea2[2][1], xp, wa.y, ea2[2][1]);
                FFMA2(ea2[2][2], xp, wb.x, ea2[2][2]); FFMA2(ea2[2][3], xp, wb.y, ea2[2][3]);
                PK2(xp, xv.w);
                FFMA2(ea2[3][0], xp, wa.x, ea2[3][0]); FFMA2(ea2[3][1], xp, wa.y, ea2[3][1]);
                FFMA2(ea2[3][2], xp, wb.x, ea2[3][2]); FFMA2(ea2[3][3], xp, wb.y, ea2[3][3]);
            }
            // T = msg * ea2 written into sMSGt (exclusive cells)
            #pragma unroll
            for (int jp = 0; jp < 4; jp++) {
                #pragma unroll
                for (int h = 0; h < 2; h++) {
                    const int c = tc*8 + 2*jp + h;
                    float4 m4 = *(float4*)(sMSGt + c*SDE + e0);
                    float v0, v1, v2, v3, dummy;
                    if (h == 0) {
                        UPK2(v0, dummy, ea2[0][jp]); UPK2(v1, dummy, ea2[1][jp]);
                        UPK2(v2, dummy, ea2[2][jp]); UPK2(v3, dummy, ea2[3][jp]);
                    } else {
                        UPK2(dummy, v0, ea2[0][jp]); UPK2(dummy, v1, ea2[1][jp]);
                        UPK2(dummy, v2, ea2[2][jp]); UPK2(dummy, v3, ea2[3][jp]);
                    }
                    m4.x *= v0; m4.y *= v1; m4.z *= v2; m4.w *= v3;
                    *(float4*)(sMSGt + c*SDE + e0) = m4;
                }
            }
        }
        __syncthreads();   // sRt + T(sMSGt) complete

        // ---- GEMM2: w_edge = r @ Wr2 + br2 [128e, 128c], 16 cols/thread ----
        u64 we[4][8];
        {
            u64 acc[4][8] = {};
            #pragma unroll 2
            for (int k = 0; k < 64; k++) {
                float4 xv = *(const float4*)(sRt + k*SDE + e0);
                const float* wrow = sWr2 + k*128 + tc*16;
                ulonglong2 wa = *(const ulonglong2*)(wrow);
                ulonglong2 wb = *(const ulonglong2*)(wrow + 4);
                ulonglong2 wc = *(const ulonglong2*)(wrow + 8);
                ulonglong2 wd = *(const ulonglong2*)(wrow + 12);
                u64 xp;
                #pragma unroll
                for (int i = 0; i < 4; i++) {
                    float x = (i==0) ? xv.x : (i==1) ? xv.y : (i==2) ? xv.z : xv.w;
                    PK2(xp, x);
                    FFMA2(acc[i][0], xp, wa.x, acc[i][0]); FFMA2(acc[i][1], xp, wa.y, acc[i][1]);
                    FFMA2(acc[i][2], xp, wb.x, acc[i][2]); FFMA2(acc[i][3], xp, wb.y, acc[i][3]);
                    FFMA2(acc[i][4], xp, wc.x, acc[i][4]); FFMA2(acc[i][5], xp, wc.y, acc[i][5]);
                    FFMA2(acc[i][6], xp, wd.x, acc[i][6]); FFMA2(acc[i][7], xp, wd.y, acc[i][7]);
                }
            }
            #pragma unroll
            for (int i = 0; i < 4; i++)
                #pragma unroll
                for (int jp = 0; jp < 8; jp++) {
                    u64 b = *(const u64*)(sbr2 + tc*16 + 2*jp);
                    ADD2(we[i][jp], acc[i][jp], b);
                }
        }

        // ---- GEMM3: dtp = (T @ Wdtp) * w_edge [128e, 128c] ----
        u64 dtp[4][8];
        {
            u64 acc[4][8] = {};
            #pragma unroll 2
            for (int k = 0; k < 64; k++) {
                float4 xv = *(const float4*)(sMSGt + k*SDE + e0);
                const float* wrow = sWdtp + k*128 + tc*16;
                ulonglong2 wa = *(const ulonglong2*)(wrow);
                ulonglong2 wb = *(const ulonglong2*)(wrow + 4);
                ulonglong2 wc = *(const ulonglong2*)(wrow + 8);
                ulonglong2 wd = *(const ulonglong2*)(wrow + 12);
                u64 xp;
                #pragma unroll
                for (int i = 0; i < 4; i++) {
                    float x = (i==0) ? xv.x : (i==1) ? xv.y : (i==2) ? xv.z : xv.w;
                    PK2(xp, x);
                    FFMA2(acc[i][0], xp, wa.x, acc[i][0]); FFMA2(acc[i][1], xp, wa.y, acc[i][1]);
                    FFMA2(acc[i][2], xp, wb.x, acc[i][2]); FFMA2(acc[i][3], xp, wb.y, acc[i][3]);
                    FFMA2(acc[i][4], xp, wc.x, acc[i][4]); FFMA2(acc[i][5], xp, wc.y, acc[i][5]);
                    FFMA2(acc[i][6], xp, wd.x, acc[i][6]); FFMA2(acc[i][7], xp, wd.y, acc[i][7]);
                }
            }
            #pragma unroll
            for (int i = 0; i < 4; i++)
                #pragma unroll
                for (int jp = 0; jp < 8; jp++)
                    MUL2(dtp[i][jp], acc[i][jp], we[i][jp]);
        }

        // ---- epilogue: warps 0-3 -> logits (cols 0-63 = 2 heads each); warps 4-7 -> val ----
        if (tc < 4) {
            #pragma unroll
            for (int i = 0; i < 4; i++) {
                const int ge = base + e0 + i;
                if (ge >= EE) continue;
                float lg0 = 0.0f, lg1 = 0.0f;
                #pragma unroll
                for (int jp = 0; jp < 8; jp++) {
                    float x0, x1;
                    UPK2(x0, x1, dtp[i][jp]);
                    float lr0 = (x0 > 0.0f) ? x0 : 0.2f * x0;
                    float lr1 = (x1 > 0.0f) ? x1 : 0.2f * x1;
                    float contrib = lr0 * sal[tc*16 + 2*jp] + lr1 * sal[tc*16 + 2*jp + 1];
                    if (jp < 4) lg0 += contrib; else lg1 += contrib;
                }
                const float el = el_g[ge];
                const int d = edst[ge];
                const int h0 = tc*2;
                float L0 = lg0 + el, L1 = lg1 + el;
                g_att[(size_t)ge*8 + h0]     = L0;
                g_att[(size_t)ge*8 + h0 + 1] = L1;
                atomicMaxFloat(&g_max[(size_t)d*8 + h0],     L0);
                atomicMaxFloat(&g_max[(size_t)d*8 + h0 + 1], L1);
            }
        } else {
            const int c = (tc - 4) * 16;
            #pragma unroll
            for (int i = 0; i < 4; i++) {
                const int ge = base + e0 + i;
                if (ge >= EE) continue;
                #pragma unroll
                for (int q = 0; q < 4; q++) {
                    float4 v;
                    UPK2(v.x, v.y, dtp[i][2*q]);
                    UPK2(v.z, v.w, dtp[i][2*q+1]);
                    *(float4*)(g_val + (size_t)ge*64 + c + q*4) = v;
                }
            }
        }
    }
}

// ---------------- softmax pass 2 ----------------
__global__ void k_soft(const int* __restrict__ edst) {
    int i = blockIdx.x * blockDim.x + threadIdx.x;
    if (i >= EE*HH) return;
    int e = i >> 3, h = i & 7;
    int d = edst[e];
    float a = __expf(g_att[i] - g_max[(size_t)d*8 + h]);
    g_att[i] = a;
    atomicAdd(&g_z[(size_t)d*8 + h], a);
}

// ---------------- scatter: one thread per (edge, head), vectorized red.v4 ----------------
__global__ void k_scat(const int* __restrict__ edst) {
    int i = blockIdx.x * blockDim.x + threadIdx.x;
    if (i >= EE*HH) return;
    int e = i >> 3, h = i & 7;
    int d = edst[e];
    float attn = g_att[i] / g_z[(size_t)d*8 + h];
    const float4* v = (const float4*)(g_val + (size_t)e*64 + h*8);
    float4 a = v[0], b = v[1];
    float* dst = g_acc + (size_t)d*64 + h*8;
    asm volatile("red.global.add.v4.f32 [%0], {%1,%2,%3,%4};"
                 :: "l"(dst), "f"(a.x*attn), "f"(a.y*attn), "f"(a.z*attn), "f"(a.w*attn)
                 : "memory");
    asm volatile("red.global.add.v4.f32 [%0], {%1,%2,%3,%4};"
                 :: "l"(dst+4), "f"(b.x*attn), "f"(b.y*attn), "f"(b.z*attn), "f"(b.w*attn)
                 : "memory");
}

// ---------------- final ----------------
#define SMEM_FIN_FLOATS 28672
__global__ void __launch_bounds__(256, 1)
k_final(const float* __restrict__ dst_f,
        const float* __restrict__ Wp, const float* __restrict__ bp,
        const float* __restrict__ lnw, const float* __restrict__ lnb,
        const float* __restrict__ Wf1, const float* __restrict__ bf1,
        const float* __restrict__ Wf2, const float* __restrict__ bf2,
        float* __restrict__ out) {
    extern __shared__ float smf[];
    float* sWp  = smf;
    float* sWf1 = smf + 4096;
    float* sWf2 = smf + 16384;
    for (int i = threadIdx.x; i < 4096;  i += blockDim.x) sWp[i]  = Wp[i];
    for (int i = threadIdx.x; i < 12288; i += blockDim.x) sWf1[i] = Wf1[i];
    for (int i = threadIdx.x; i < 12288; i += blockDim.x) sWf2[i] = Wf2[i];
    __syncthreads();
    const int l = threadIdx.x & 31;
    const int warp = (blockIdx.x * blockDim.x + threadIdx.x) >> 5;
    const int nw = (gridDim.x * blockDim.x) >> 5;
    for (int n = warp; n < NDN; n += nw) {
        float i0 = g_acc[(size_t)n*64 + l], i1 = g_acc[(size_t)n*64 + l + 32];
        float o0 = bp[l], o1 = bp[l+32];
        #pragma unroll
        for (int k = 0; k < 32; k++) {
            float b = __shfl_sync(~0u, i0, k);
            o0 += b * sWp[k*64 + l];
            o1 += b * sWp[k*64 + l + 32];
        }
        #pragma unroll
        for (int k = 0; k < 32; k++) {
            float b = __shfl_sync(~0u, i1, k);
            o0 += b * sWp[(k+32)*64 + l];
            o1 += b * sWp[(k+32)*64 + l + 32];
        }
        const float e0 = o0 + dst_f[(size_t)n*64 + l];
        const float e1 = o1 + dst_f[(size_t)n*64 + l + 32];
        float s = e0 + e1;
        #pragma unroll
        for (int o = 16; o; o >>= 1) s += __shfl_xor_sync(~0u, s, o);
        const float mean = s * (1.0f/64.0f);
        const float c0 = e0 - mean, c1 = e1 - mean;
        float v = c0*c0 + c1*c1;
        #pragma unroll
        for (int o = 16; o; o >>= 1) v += __shfl_xor_sync(~0u, v, o);
        const float rs = rsqrtf(v * (1.0f/64.0f) + LNEPS);
        const float y0 = c0 * rs * lnw[l]    + lnb[l];
        const float y1 = c1 * rs * lnw[l+32] + lnb[l+32];
        float h[6];
        #pragma unroll
        for (int i = 0; i < 6; i++) h[i] = bf1[l + 32*i];
        #pragma unroll
        for (int k = 0; k < 32; k++) {
            float b = __shfl_sync(~0u, y0, k);
            #pragma unroll
            for (int i = 0; i < 6; i++) h[i] += b * sWf1[k*192 + l + 32*i];
        }
        #pragma unroll
        for (int k = 0; k < 32; k++) {
            float b = __shfl_sync(~0u, y1, k);
            #pragma unroll
            for (int i = 0; i < 6; i++) h[i] += b * sWf1[(k+32)*192 + l + 32*i];
        }
        #pragma unroll
        for (int i = 0; i < 6; i++) h[i] = h[i] / (1.0f + __expf(-h[i]));
        float f0 = bf2[l], f1 = bf2[l+32];
        #pragma unroll
        for (int kk = 0; kk < 6; kk++)
            #pragma unroll
            for (int k2 = 0; k2 < 32; k2++) {
                float b = __shfl_sync(~0u, h[kk], k2);
                f0 += b * sWf2[(kk*32 + k2)*64 + l];
                f1 += b * sWf2[(kk*32 + k2)*64 + l + 32];
            }
        out[(size_t)n*64 + l]      = f0 + e0;
        out[(size_t)n*64 + l + 32] = f1 + e1;
    }
}

// ---------------- launch ----------------
extern "C" void kernel_launch(void* const* d_in, const int* in_sizes, int n_in,
                              void* d_out, int out_size) {
    const float* src_f        = (const float*)d_in[0];
    const float* dst_f        = (const float*)d_in[1];
    const float* edge_attr    = (const float*)d_in[2];
    const float* edge_scalars = (const float*)d_in[3];
    const float* edge_logits  = (const float*)d_in[4];
    const int*   edge_src     = (const int*)d_in[5];
    const int*   edge_dst     = (const int*)d_in[6];
    const float* ln_src_w = (const float*)d_in[7];
    const float* ln_src_b = (const float*)d_in[8];
    const float* W_src    = (const float*)d_in[9];
    const float* ln_dst_w = (const float*)d_in[10];
    const float* ln_dst_b = (const float*)d_in[11];
    const float* W_dst    = (const float*)d_in[12];
    const float* b_dst    = (const float*)d_in[13];
    const float* W_ea     = (const float*)d_in[14];
    const float* W_dtp    = (const float*)d_in[15];
    const float* W_r1     = (const float*)d_in[16];
    const float* b_r1     = (const float*)d_in[17];
    const float* W_r2     = (const float*)d_in[18];
    const float* b_r2     = (const float*)d_in[19];
    const float* alpha    = (const float*)d_in[20];
    const float* W_proj   = (const float*)d_in[21];
    const float* b_proj   = (const float*)d_in[22];
    const float* ln_post_w = (const float*)d_in[23];
    const float* ln_post_b = (const float*)d_in[24];
    const float* W_f1     = (const float*)d_in[25];
    const float* b_f1     = (const float*)d_in[26];
    const float* W_f2     = (const float*)d_in[27];
    const float* b_f2     = (const float*)d_in[28];
    float* out = (float*)d_out;

    cudaFuncSetAttribute(k_edge, cudaFuncAttributeMaxDynamicSharedMemorySize,
                         SMEM_EDGE_FLOATS * 4);
    cudaFuncSetAttribute(k_final, cudaFuncAttributeMaxDynamicSharedMemorySize,
                         SMEM_FIN_FLOATS * 4);

    k_init<<<(NDN*CC + 255)/256, 256>>>();
    k_node<<<1600, 256>>>(src_f, dst_f, ln_src_w, ln_src_b, W_src,
                          ln_dst_w, ln_dst_b, W_dst, b_dst);
    k_edge<<<296, 256, SMEM_EDGE_FLOATS*4>>>(edge_scalars, edge_attr, edge_logits,
                                             edge_src, edge_dst,
                                             W_r1, b_r1, W_r2, b_r2, W_ea, W_dtp, alpha);
    k_soft<<<(EE*HH + 255)/256, 256>>>(edge_dst);
    k_scat<<<(EE*HH + 255)/256, 256>>>(edge_dst);
    k_final<<<800, 256, SMEM_FIN_FLOATS*4>>>(dst_f, W_proj, b_proj,
                                             ln_post_w, ln_post_b,
                                             W_f1, b_f1, W_f2, b_f2, out);
}

// round 7
// speedup vs baseline: 1.3822x; 1.0682x over previous
#include <cuda_runtime.h>
#include <cstdint>

#define NSN 50000
#define NDN 50000
#define EE  600000
#define CC  64
#define HH  8
#define LNEPS 1e-5f

typedef unsigned long long u64;

// packed f32x2 helpers (SASS FFMA2 — only reachable via PTX fma.rn.f32x2)
#define FFMA2(d, a, b, c) asm("fma.rn.f32x2 %0, %1, %2, %3;" : "=l"(d) : "l"(a), "l"(b), "l"(c))
#define MUL2(d, a, b)     asm("mul.rn.f32x2 %0, %1, %2;"     : "=l"(d) : "l"(a), "l"(b))
#define ADD2(d, a, b)     asm("add.rn.f32x2 %0, %1, %2;"     : "=l"(d) : "l"(a), "l"(b))
#define PK2(d, x)         asm("mov.b64 %0, {%1, %1};"        : "=l"(d) : "f"(x))
#define UPK2(lo, hi, v)   asm("mov.b64 {%0, %1}, %2;"        : "=f"(lo), "=f"(hi) : "l"(v))

// ---------------- scratch ----------------
__device__ float g_ms[(size_t)NSN*CC];
__device__ float g_md[(size_t)NDN*CC];
__device__ float g_z[(size_t)NDN*HH];
__device__ float g_acc[(size_t)NDN*CC];

// ---------------- init ----------------
__global__ void k_init() {
    int i = blockIdx.x * blockDim.x + threadIdx.x;
    if (i < NDN*HH) g_z[i] = 0.0f;
    if (i < NDN*CC) g_acc[i] = 0.0f;
}

// ---------------- node projections ----------------
__global__ void k_node(const float* __restrict__ src_f, const float* __restrict__ dst_f,
                       const float* __restrict__ lnsw, const float* __restrict__ lnsb,
                       const float* __restrict__ Wsrc,
                       const float* __restrict__ lndw, const float* __restrict__ lndb,
                       const float* __restrict__ Wdst, const float* __restrict__ bdst) {
    __shared__ float sW[2*64*64];
    for (int i = threadIdx.x; i < 8192; i += blockDim.x)
        sW[i] = (i < 4096) ? Wsrc[i] : Wdst[i-4096];
    __syncthreads();
    const int l = threadIdx.x & 31;
    const int warp = (blockIdx.x * blockDim.x + threadIdx.x) >> 5;
    const int nwarps = (gridDim.x * blockDim.x) >> 5;
    for (int n = warp; n < NSN + NDN; n += nwarps) {
        const bool isd = (n >= NSN);
        const int idx = isd ? n - NSN : n;
        const float* xf = (isd ? dst_f : src_f) + (size_t)idx * 64;
        float x0 = xf[l], x1 = xf[l+32];
        float s = x0 + x1;
        #pragma unroll
        for (int o = 16; o; o >>= 1) s += __shfl_xor_sync(~0u, s, o);
        const float mean = s * (1.0f/64.0f);
        const float c0 = x0 - mean, c1 = x1 - mean;
        float v = c0*c0 + c1*c1;
        #pragma unroll
        for (int o = 16; o; o >>= 1) v += __shfl_xor_sync(~0u, v, o);
        const float rs = rsqrtf(v * (1.0f/64.0f) + LNEPS);
        const float* lw = isd ? lndw : lnsw;
        const float* lb = isd ? lndb : lnsb;
        const float y0 = c0 * rs * lw[l]    + lb[l];
        const float y1 = c1 * rs * lw[l+32] + lb[l+32];
        const float* W = sW + (isd ? 4096 : 0);
        float a0 = 0.0f, a1 = 0.0f;
        #pragma unroll
        for (int k = 0; k < 32; k++) {
            float b = __shfl_sync(~0u, y0, k);
            a0 += b * W[k*64 + l];
            a1 += b * W[k*64 + l + 32];
        }
        #pragma unroll
        for (int k = 0; k < 32; k++) {
            float b = __shfl_sync(~0u, y1, k);
            a0 += b * W[(k+32)*64 + l];
            a1 += b * W[(k+32)*64 + l + 32];
        }
        if (isd) { a0 += bdst[l]; a1 += bdst[l+32]; }
        float* out = isd ? g_md : g_ms;
        out[(size_t)idx*64 + l]      = a0;
        out[(size_t)idx*64 + l + 32] = a1;
    }
}

// ---------------- heavy fused edge kernel: 256 threads, 128-edge tiles, 4e x 16c ----------------
#define TEDGE 128
#define NTILE2 ((EE + TEDGE - 1) / TEDGE)   // 4688
#define SDE 132                              // [k][edge] stride
#define OFF_WR1   0
#define OFF_WR2   4096
#define OFF_WEA   12288
#define OFF_WDTP  13312
#define OFF_BR1   21504
#define OFF_BR2   21568
#define OFF_AL    21696
#define OFF_ESt   21760                      // 64*132 = 8448
#define OFF_Rt    (OFF_ESt + 8448)           // 30208
#define OFF_MSGt  (OFF_Rt  + 8448)           // 38656
#define OFF_EAt   (OFF_MSGt+ 8448)           // 47104, 16*132 = 2112 (reused as sA in epilogue)
#define SMEM_EDGE_FLOATS (OFF_EAt + 2112)    // 49216 floats = 196864 B

__global__ void __launch_bounds__(256, 1)
k_edge(const float* __restrict__ es_g, const float* __restrict__ ea_g,
       const float* __restrict__ el_g,
       const int* __restrict__ esrc, const int* __restrict__ edst,
       const float* __restrict__ Wr1, const float* __restrict__ br1,
       const float* __restrict__ Wr2, const float* __restrict__ br2,
       const float* __restrict__ Wea, const float* __restrict__ Wdtp,
       const float* __restrict__ alpha) {
    extern __shared__ float sm[];
    float* sWr1  = sm + OFF_WR1;
    float* sWr2  = sm + OFF_WR2;
    float* sWea  = sm + OFF_WEA;
    float* sWdtp = sm + OFF_WDTP;
    float* sbr1  = sm + OFF_BR1;
    float* sbr2  = sm + OFF_BR2;
    float* sal   = sm + OFF_AL;
    float* sESt  = sm + OFF_ESt;
    float* sRt   = sm + OFF_Rt;
    float* sMSGt = sm + OFF_MSGt;
    float* sEAt  = sm + OFF_EAt;
    float* sA    = sm + OFF_EAt;   // reused after EA is consumed: a[edge][head]

    const int tid = threadIdx.x;
    for (int i = tid; i < 4096; i += 256) sWr1[i]  = Wr1[i];
    for (int i = tid; i < 8192; i += 256) sWr2[i]  = Wr2[i];
    for (int i = tid; i < 1024; i += 256) sWea[i]  = Wea[i];
    for (int i = tid; i < 8192; i += 256) sWdtp[i] = Wdtp[i];
    if (tid < 64)  sbr1[tid] = br1[tid];
    if (tid < 128) sbr2[tid] = br2[tid];
    if (tid < 64)  sal[tid]  = alpha[tid];

    const int te = tid & 31;      // lane -> 4 edges
    const int tc = tid >> 5;      // warp -> col group [0,8)
    const int e0 = te * 4;

    for (int tile = blockIdx.x; tile < NTILE2; tile += gridDim.x) {
        const int base = tile * TEDGE;
        __syncthreads();  // previous tile consumed (covers weight load on iter 1)

        // ---- stage: ES^T, MSG^T (gather), EA^T ----
        {
            #pragma unroll
            for (int j = 0; j < 2; j++) {
                const int idx = tid + j*256;
                const int e = idx >> 2, p = idx & 3;
                int ge = base + e; if (ge >= EE) ge = EE - 1;
                const float4* esrow = (const float4*)(es_g + (size_t)ge*64 + p*16);
                const int sidx = esrc[ge], didx = edst[ge];
                const float4* msr = (const float4*)(g_ms + (size_t)sidx*64 + p*16);
                const float4* mdr = (const float4*)(g_md + (size_t)didx*64 + p*16);
                #pragma unroll
                for (int q = 0; q < 4; q++) {
                    float4 v = esrow[q];
                    int k0 = p*16 + q*4;
                    sESt[(k0+0)*SDE + e] = v.x;
                    sESt[(k0+1)*SDE + e] = v.y;
                    sESt[(k0+2)*SDE + e] = v.z;
                    sESt[(k0+3)*SDE + e] = v.w;
                    float4 a = msr[q], d = mdr[q];
                    sMSGt[(k0+0)*SDE + e] = a.x + d.x;
                    sMSGt[(k0+1)*SDE + e] = a.y + d.y;
                    sMSGt[(k0+2)*SDE + e] = a.z + d.z;
                    sMSGt[(k0+3)*SDE + e] = a.w + d.w;
                }
            }
            if (tid < TEDGE) {
                int ge2 = base + tid; if (ge2 >= EE) ge2 = EE - 1;
                const float4* ear = (const float4*)(ea_g + (size_t)ge2*16);
                #pragma unroll
                for (int q = 0; q < 4; q++) {
                    float4 v = ear[q];
                    sEAt[(q*4+0)*SDE + tid] = v.x;
                    sEAt[(q*4+1)*SDE + tid] = v.y;
                    sEAt[(q*4+2)*SDE + tid] = v.z;
                    sEAt[(q*4+3)*SDE + tid] = v.w;
                }
            }
        }
        __syncthreads();

        // ---- GEMM1: r = silu(es @ Wr1 + br1) [128e, 64c] -> sRt ; Gea -> regs ----
        u64 ea2[4][4] = {};
        {
            u64 acc[4][4] = {};
            #pragma unroll 4
            for (int k = 0; k < 64; k++) {
                float4 xv = *(const float4*)(sESt + k*SDE + e0);
                ulonglong2 wa = *(const ulonglong2*)(sWr1 + k*64 + tc*8);
                ulonglong2 wb = *(const ulonglong2*)(sWr1 + k*64 + tc*8 + 4);
                u64 xp;
                PK2(xp, xv.x);
                FFMA2(acc[0][0], xp, wa.x, acc[0][0]); FFMA2(acc[0][1], xp, wa.y, acc[0][1]);
                FFMA2(acc[0][2], xp, wb.x, acc[0][2]); FFMA2(acc[0][3], xp, wb.y, acc[0][3]);
                PK2(xp, xv.y);
                FFMA2(acc[1][0], xp, wa.x, acc[1][0]); FFMA2(acc[1][1], xp, wa.y, acc[1][1]);
                FFMA2(acc[1][2], xp, wb.x, acc[1][2]); FFMA2(acc[1][3], xp, wb.y, acc[1][3]);
                PK2(xp, xv.z);
                FFMA2(acc[2][0], xp, wa.x, acc[2][0]); FFMA2(acc[2][1], xp, wa.y, acc[2][1]);
                FFMA2(acc[2][2], xp, wb.x, acc[2][2]); FFMA2(acc[2][3], xp, wb.y, acc[2][3]);
                PK2(xp, xv.w);
                FFMA2(acc[3][0], xp, wa.x, acc[3][0]); FFMA2(acc[3][1], xp, wa.y, acc[3][1]);
                FFMA2(acc[3][2], xp, wb.x, acc[3][2]); FFMA2(acc[3][3], xp, wb.y, acc[3][3]);
            }
            // silu + write transposed, float4 per column across the 4 edges
            #pragma unroll
            for (int jp = 0; jp < 4; jp++) {
                float lo[4], hi[4];
                #pragma unroll
                for (int i = 0; i < 4; i++) UPK2(lo[i], hi[i], acc[i][jp]);
                float b0 = sbr1[tc*8 + 2*jp], b1 = sbr1[tc*8 + 2*jp + 1];
                float4 v0, v1;
                v0.x = lo[0]+b0; v0.y = lo[1]+b0; v0.z = lo[2]+b0; v0.w = lo[3]+b0;
                v1.x = hi[0]+b1; v1.y = hi[1]+b1; v1.z = hi[2]+b1; v1.w = hi[3]+b1;
                v0.x /= (1.0f + __expf(-v0.x)); v0.y /= (1.0f + __expf(-v0.y));
                v0.z /= (1.0f + __expf(-v0.z)); v0.w /= (1.0f + __expf(-v0.w));
                v1.x /= (1.0f + __expf(-v1.x)); v1.y /= (1.0f + __expf(-v1.y));
                v1.z /= (1.0f + __expf(-v1.z)); v1.w /= (1.0f + __expf(-v1.w));
                *(float4*)(sRt + (tc*8 + 2*jp)*SDE   + e0) = v0;
                *(float4*)(sRt + (tc*8 + 2*jp+1)*SDE + e0) = v1;
            }
            // Gea: ea2 = edge_attr @ Wea [128e, 64c]
            #pragma unroll
            for (int k = 0; k < 16; k++) {
                float4 xv = *(const float4*)(sEAt + k*SDE + e0);
                ulonglong2 wa = *(const ulonglong2*)(sWea + k*64 + tc*8);
                ulonglong2 wb = *(const ulonglong2*)(sWea + k*64 + tc*8 + 4);
                u64 xp;
                PK2(xp, xv.x);
                FFMA2(ea2[0][0], xp, wa.x, ea2[0][0]); FFMA2(ea2[0][1], xp, wa.y, ea2[0][1]);
                FFMA2(ea2[0][2], xp, wb.x, ea2[0][2]); FFMA2(ea2[0][3], xp, wb.y, ea2[0][3]);
                PK2(xp, xv.y);
                FFMA2(ea2[1][0], xp, wa.x, ea2[1][0]); FFMA2(ea2[1][1], xp, wa.y, ea2[1][1]);
                FFMA2(ea2[1][2], xp, wb.x, ea2[1][2]); FFMA2(ea2[1][3], xp, wb.y, ea2[1][3]);
                PK2(xp, xv.z);
                FFMA2(ea2[2][0], xp, wa.x, ea2[2][0]); FFMA2(ea2[2][1], xp, wa.y, ea2[2][1]);
                FFMA2(ea2[2][2], xp, wb.x, ea2[2][2]); FFMA2(ea2[2][3], xp, wb.y, ea2[2][3]);
                PK2(xp, xv.w);
                FFMA2(ea2[3][0], xp, wa.x, ea2[3][0]); FFMA2(ea2[3][1], xp, wa.y, ea2[3][1]);
                FFMA2(ea2[3][2], xp, wb.x, ea2[3][2]); FFMA2(ea2[3][3], xp, wb.y, ea2[3][3]);
            }
            // T = msg * ea2 written into sMSGt (exclusive cells)
            #pragma unroll
            for (int jp = 0; jp < 4; jp++) {
                #pragma unroll
                for (int h = 0; h < 2; h++) {
                    const int c = tc*8 + 2*jp + h;
                    float4 m4 = *(float4*)(sMSGt + c*SDE + e0);
                    float v0, v1, v2, v3, dummy;
                    if (h == 0) {
                        UPK2(v0, dummy, ea2[0][jp]); UPK2(v1, dummy, ea2[1][jp]);
                        UPK2(v2, dummy, ea2[2][jp]); UPK2(v3, dummy, ea2[3][jp]);
                    } else {
                        UPK2(dummy, v0, ea2[0][jp]); UPK2(dummy, v1, ea2[1][jp]);
                        UPK2(dummy, v2, ea2[2][jp]); UPK2(dummy, v3, ea2[3][jp]);
                    }
                    m4.x *= v0; m4.y *= v1; m4.z *= v2; m4.w *= v3;
                    *(float4*)(sMSGt + c*SDE + e0) = m4;
                }
            }
        }
        __syncthreads();   // sRt + T(sMSGt) complete; sEAt dead from here

        // ---- GEMM2: w_edge = r @ Wr2 + br2 [128e, 128c], 16 cols/thread ----
        u64 we[4][8];
        {
            u64 acc[4][8] = {};
            #pragma unroll 2
            for (int k = 0; k < 64; k++) {
                float4 xv = *(const float4*)(sRt + k*SDE + e0);
                const float* wrow = sWr2 + k*128 + tc*16;
                ulonglong2 wa = *(const ulonglong2*)(wrow);
                ulonglong2 wb = *(const ulonglong2*)(wrow + 4);
                ulonglong2 wc = *(const ulonglong2*)(wrow + 8);
                ulonglong2 wd = *(const ulonglong2*)(wrow + 12);
                u64 xp;
                #pragma unroll
                for (int i = 0; i < 4; i++) {
                    float x = (i==0) ? xv.x : (i==1) ? xv.y : (i==2) ? xv.z : xv.w;
                    PK2(xp, x);
                    FFMA2(acc[i][0], xp, wa.x, acc[i][0]); FFMA2(acc[i][1], xp, wa.y, acc[i][1]);
                    FFMA2(acc[i][2], xp, wb.x, acc[i][2]); FFMA2(acc[i][3], xp, wb.y, acc[i][3]);
                    FFMA2(acc[i][4], xp, wc.x, acc[i][4]); FFMA2(acc[i][5], xp, wc.y, acc[i][5]);
                    FFMA2(acc[i][6], xp, wd.x, acc[i][6]); FFMA2(acc[i][7], xp, wd.y, acc[i][7]);
                }
            }
            #pragma unroll
            for (int i = 0; i < 4; i++)
                #pragma unroll
                for (int jp = 0; jp < 8; jp++) {
                    u64 b = *(const u64*)(sbr2 + tc*16 + 2*jp);
                    ADD2(we[i][jp], acc[i][jp], b);
                }
        }

        // ---- GEMM3: dtp = (T @ Wdtp) * w_edge [128e, 128c] ----
        u64 dtp[4][8];
        {
            u64 acc[4][8] = {};
            #pragma unroll 2
            for (int k = 0; k < 64; k++) {
                float4 xv = *(const float4*)(sMSGt + k*SDE + e0);
                const float* wrow = sWdtp + k*128 + tc*16;
                ulonglong2 wa = *(const ulonglong2*)(wrow);
                ulonglong2 wb = *(const ulonglong2*)(wrow + 4);
                ulonglong2 wc = *(const ulonglong2*)(wrow + 8);
                ulonglong2 wd = *(const ulonglong2*)(wrow + 12);
                u64 xp;
                #pragma unroll
                for (int i = 0; i < 4; i++) {
                    float x = (i==0) ? xv.x : (i==1) ? xv.y : (i==2) ? xv.z : xv.w;
                    PK2(xp, x);
                    FFMA2(acc[i][0], xp, wa.x, acc[i][0]); FFMA2(acc[i][1], xp, wa.y, acc[i][1]);
                    FFMA2(acc[i][2], xp, wb.x, acc[i][2]); FFMA2(acc[i][3], xp, wb.y, acc[i][3]);
                    FFMA2(acc[i][4], xp, wc.x, acc[i][4]); FFMA2(acc[i][5], xp, wc.y, acc[i][5]);
                    FFMA2(acc[i][6], xp, wd.x, acc[i][6]); FFMA2(acc[i][7], xp, wd.y, acc[i][7]);
                }
            }
            #pragma unroll
            for (int i = 0; i < 4; i++)
                #pragma unroll
                for (int jp = 0; jp < 8; jp++)
                    MUL2(dtp[i][jp], acc[i][jp], we[i][jp]);
        }

        // ---- fused epilogue part 1: warps 0-3 -> a = exp(logit); z red; stash a in smem ----
        if (tc < 4) {
            #pragma unroll
            for (int i = 0; i < 4; i++) {
                const int ge = base + e0 + i;
                if (ge >= EE) continue;
                float lg0 = 0.0f, lg1 = 0.0f;
                #pragma unroll
                for (int jp = 0; jp < 8; jp++) {
                    float x0, x1;
                    UPK2(x0, x1, dtp[i][jp]);
                    float lr0 = (x0 > 0.0f) ? x0 : 0.2f * x0;
                    float lr1 = (x1 > 0.0f) ? x1 : 0.2f * x1;
                    float contrib = lr0 * sal[tc*16 + 2*jp] + lr1 * sal[tc*16 + 2*jp + 1];
                    if (jp < 4) lg0 += contrib; else lg1 += contrib;
                }
                const float el = el_g[ge];
                const int d = edst[ge];
                const int h0 = tc*2;
                float a0 = __expf(lg0 + el);
                float a1 = __expf(lg1 + el);
                sA[(e0+i)*8 + h0]     = a0;
                sA[(e0+i)*8 + h0 + 1] = a1;
                asm volatile("red.global.add.v2.f32 [%0], {%1,%2};"
                             :: "l"(g_z + (size_t)d*8 + h0), "f"(a0), "f"(a1) : "memory");
            }
        }
        __syncthreads();

        // ---- fused epilogue part 2: warps 4-7 -> red.v4 of a*val into g_acc ----
        if (tc >= 4) {
            const int c = (tc - 4) * 16;
            const int hA = c >> 3;          // first head this warp covers
            #pragma unroll
            for (int i = 0; i < 4; i++) {
                const int ge = base + e0 + i;
                if (ge >= EE) continue;
                const int d = edst[ge];
                const float aa0 = sA[(e0+i)*8 + hA];
                const float aa1 = sA[(e0+i)*8 + hA + 1];
                float* dstp = g_acc + (size_t)d*64 + c;
                #pragma unroll
                for (int q = 0; q < 4; q++) {
                    float4 v;
                    UPK2(v.x, v.y, dtp[i][2*q]);
                    UPK2(v.z, v.w, dtp[i][2*q+1]);
                    const float av = (q < 2) ? aa0 : aa1;
                    asm volatile("red.global.add.v4.f32 [%0], {%1,%2,%3,%4};"
                                 :: "l"(dstp + q*4), "f"(v.x*av), "f"(v.y*av),
                                    "f"(v.z*av), "f"(v.w*av) : "memory");
                }
            }
        }
    }
}

// ---------------- final: divide by z, proj + skip + LN + FFN + skip ----------------
#define SMEM_FIN_FLOATS 28672
__global__ void __launch_bounds__(256, 1)
k_final(const float* __restrict__ dst_f,
        const float* __restrict__ Wp, const float* __restrict__ bp,
        const float* __restrict__ lnw, const float* __restrict__ lnb,
        const float* __restrict__ Wf1, const float* __restrict__ bf1,
        const float* __restrict__ Wf2, const float* __restrict__ bf2,
        float* __restrict__ out) {
    extern __shared__ float smf[];
    float* sWp  = smf;
    float* sWf1 = smf + 4096;
    float* sWf2 = smf + 16384;
    for (int i = threadIdx.x; i < 4096;  i += blockDim.x) sWp[i]  = Wp[i];
    for (int i = threadIdx.x; i < 12288; i += blockDim.x) sWf1[i] = Wf1[i];
    for (int i = threadIdx.x; i < 12288; i += blockDim.x) sWf2[i] = Wf2[i];
    __syncthreads();
    const int l = threadIdx.x & 31;
    const int warp = (blockIdx.x * blockDim.x + threadIdx.x) >> 5;
    const int nw = (gridDim.x * blockDim.x) >> 5;
    for (int n = warp; n < NDN; n += nw) {
        float z0 = g_z[(size_t)n*8 + (l >> 3)];
        float z1 = g_z[(size_t)n*8 + ((l + 32) >> 3)];
        float r0 = (z0 > 0.0f) ? 1.0f / z0 : 0.0f;
        float r1 = (z1 > 0.0f) ? 1.0f / z1 : 0.0f;
        float i0 = g_acc[(size_t)n*64 + l] * r0;
        float i1 = g_acc[(size_t)n*64 + l + 32] * r1;
        float o0 = bp[l], o1 = bp[l+32];
        #pragma unroll
        for (int k = 0; k < 32; k++) {
            float b = __shfl_sync(~0u, i0, k);
            o0 += b * sWp[k*64 + l];
            o1 += b * sWp[k*64 + l + 32];
        }
        #pragma unroll
        for (int k = 0; k < 32; k++) {
            float b = __shfl_sync(~0u, i1, k);
            o0 += b * sWp[(k+32)*64 + l];
            o1 += b * sWp[(k+32)*64 + l + 32];
        }
        const float e0 = o0 + dst_f[(size_t)n*64 + l];
        const float e1 = o1 + dst_f[(size_t)n*64 + l + 32];
        float s = e0 + e1;
        #pragma unroll
        for (int o = 16; o; o >>= 1) s += __shfl_xor_sync(~0u, s, o);
        const float mean = s * (1.0f/64.0f);
        const float c0 = e0 - mean, c1 = e1 - mean;
        float v = c0*c0 + c1*c1;
        #pragma unroll
        for (int o = 16; o; o >>= 1) v += __shfl_xor_sync(~0u, v, o);
        const float rs = rsqrtf(v * (1.0f/64.0f) + LNEPS);
        const float y0 = c0 * rs * lnw[l]    + lnb[l];
        const float y1 = c1 * rs * lnw[l+32] + lnb[l+32];
        float h[6];
        #pragma unroll
        for (int i = 0; i < 6; i++) h[i] = bf1[l + 32*i];
        #pragma unroll
        for (int k = 0; k < 32; k++) {
            float b = __shfl_sync(~0u, y0, k);
            #pragma unroll
            for (int i = 0; i < 6; i++) h[i] += b * sWf1[k*192 + l + 32*i];
        }
        #pragma unroll
        for (int k = 0; k < 32; k++) {
            float b = __shfl_sync(~0u, y1, k);
            #pragma unroll
            for (int i = 0; i < 6; i++) h[i] += b * sWf1[(k+32)*192 + l + 32*i];
        }
        #pragma unroll
        for (int i = 0; i < 6; i++) h[i] = h[i] / (1.0f + __expf(-h[i]));
        float f0 = bf2[l], f1 = bf2[l+32];
        #pragma unroll
        for (int kk = 0; kk < 6; kk++)
            #pragma unroll
            for (int k2 = 0; k2 < 32; k2++) {
                float b = __shfl_sync(~0u, h[kk], k2);
                f0 += b * sWf2[(kk*32 + k2)*64 + l];
                f1 += b * sWf2[(kk*32 + k2)*64 + l + 32];
            }
        out[(size_t)n*64 + l]      = f0 + e0;
        out[(size_t)n*64 + l + 32] = f1 + e1;
    }
}

// ---------------- launch ----------------
extern "C" void kernel_launch(void* const* d_in, const int* in_sizes, int n_in,
                              void* d_out, int out_size) {
    const float* src_f        = (const float*)d_in[0];
    const float* dst_f        = (const float*)d_in[1];
    const float* edge_attr    = (const float*)d_in[2];
    const float* edge_scalars = (const float*)d_in[3];
    const float* edge_logits  = (const float*)d_in[4];
    const int*   edge_src     = (const int*)d_in[5];
    const int*   edge_dst     = (const int*)d_in[6];
    const float* ln_src_w = (const float*)d_in[7];
    const float* ln_src_b = (const float*)d_in[8];
    const float* W_src    = (const float*)d_in[9];
    const float* ln_dst_w = (const float*)d_in[10];
    const float* ln_dst_b = (const float*)d_in[11];
    const float* W_dst    = (const float*)d_in[12];
    const float* b_dst    = (const float*)d_in[13];
    const float* W_ea     = (const float*)d_in[14];
    const float* W_dtp    = (const float*)d_in[15];
    const float* W_r1     = (const float*)d_in[16];
    const float* b_r1     = (const float*)d_in[17];
    const float* W_r2     = (const float*)d_in[18];
    const float* b_r2     = (const float*)d_in[19];
    const float* alpha    = (const float*)d_in[20];
    const float* W_proj   = (const float*)d_in[21];
    const float* b_proj   = (const float*)d_in[22];
    const float* ln_post_w = (const float*)d_in[23];
    const float* ln_post_b = (const float*)d_in[24];
    const float* W_f1     = (const float*)d_in[25];
    const float* b_f1     = (const float*)d_in[26];
    const float* W_f2     = (const float*)d_in[27];
    const float* b_f2     = (const float*)d_in[28];
    float* out = (float*)d_out;

    cudaFuncSetAttribute(k_edge, cudaFuncAttributeMaxDynamicSharedMemorySize,
                         SMEM_EDGE_FLOATS * 4);
    cudaFuncSetAttribute(k_final, cudaFuncAttributeMaxDynamicSharedMemorySize,
                         SMEM_FIN_FLOATS * 4);

    k_init<<<(NDN*CC + 255)/256, 256>>>();
    k_node<<<1600, 256>>>(src_f, dst_f, ln_src_w, ln_src_b, W_src,
                          ln_dst_w, ln_dst_b, W_dst, b_dst);
    k_edge<<<296, 256, SMEM_EDGE_FLOATS*4>>>(edge_scalars, edge_attr, edge_logits,
                                             edge_src, edge_dst,
                                             W_r1, b_r1, W_r2, b_r2, W_ea, W_dtp, alpha);
    k_final<<<800, 256, SMEM_FIN_FLOATS*4>>>(dst_f, W_proj, b_proj,
                                             ln_post_w, ln_post_b,
                                             W_f1, b_f1, W_f2, b_f2, out);
}

// round 8
// speedup vs baseline: 1.6441x; 1.1895x over previous
#include <cuda_runtime.h>
#include <cstdint>

#define NSN 50000
#define NDN 50000
#define EE  600000
#define CC  64
#define HH  8
#define LNEPS 1e-5f

typedef unsigned long long u64;

// packed f32x2 helpers (SASS FFMA2 — only reachable via PTX fma.rn.f32x2)
#define FFMA2(d, a, b, c) asm("fma.rn.f32x2 %0, %1, %2, %3;" : "=l"(d) : "l"(a), "l"(b), "l"(c))
#define MUL2(d, a, b)     asm("mul.rn.f32x2 %0, %1, %2;"     : "=l"(d) : "l"(a), "l"(b))
#define ADD2(d, a, b)     asm("add.rn.f32x2 %0, %1, %2;"     : "=l"(d) : "l"(a), "l"(b))
#define PK2(d, x)         asm("mov.b64 %0, {%1, %1};"        : "=l"(d) : "f"(x))
#define UPK2(lo, hi, v)   asm("mov.b64 {%0, %1}, %2;"        : "=f"(lo), "=f"(hi) : "l"(v))

// ---------------- scratch ----------------
__device__ float g_ms[(size_t)NSN*CC];
__device__ float g_md[(size_t)NDN*CC];
__device__ float g_z[(size_t)NDN*HH];
__device__ float g_acc[(size_t)NDN*CC];

// ---------------- init ----------------
__global__ void k_init() {
    int i = blockIdx.x * blockDim.x + threadIdx.x;
    if (i < NDN*HH) g_z[i] = 0.0f;
    if (i < NDN*CC) g_acc[i] = 0.0f;
}

// ---------------- node projections: tiled FFMA2 version ----------------
#define KN_SMEM 12864   // floats: W 8192 | Yt 4352 | bdst 64 | ln 256
__global__ void __launch_bounds__(256)
k_node(const float* __restrict__ src_f, const float* __restrict__ dst_f,
       const float* __restrict__ lnsw, const float* __restrict__ lnsb,
       const float* __restrict__ Wsrc,
       const float* __restrict__ lndw, const float* __restrict__ lndb,
       const float* __restrict__ Wdst, const float* __restrict__ bdst) {
    extern __shared__ float sn[];
    float* sW  = sn;           // 8192: Wsrc, Wdst
    float* sYt = sn + 8192;    // 4352 (64k x 68)
    float* sBd = sn + 12544;   // 64
    float* sLn = sn + 12608;   // 256
    const int tid = threadIdx.x;
    for (int i = tid; i < 8192; i += 256) sW[i] = (i < 4096) ? Wsrc[i] : Wdst[i-4096];
    if (tid < 64) {
        sBd[tid] = bdst[tid];
        sLn[tid] = lnsw[tid]; sLn[64+tid] = lnsb[tid];
        sLn[128+tid] = lndw[tid]; sLn[192+tid] = lndb[tid];
    }
    const int NTS = (NSN + 63)/64, NTD = (NDN + 63)/64;
    const int te = tid & 15, tc = tid >> 4, n0 = te*4;
    for (int tile = blockIdx.x; tile < NTS + NTD; tile += gridDim.x) {
        const bool isd = (tile >= NTS);
        const int base = (isd ? tile - NTS : tile) * 64;
        const int NV = isd ? NDN : NSN;
        __syncthreads();
        // stage + LN -> Yt transposed
        {
            const int n = tid >> 2, p = tid & 3;
            int gn = base + n; if (gn >= NV) gn = NV - 1;
            const float4* xr = (const float4*)((isd ? dst_f : src_f) + (size_t)gn*64 + p*16);
            float4 v[4]; float s = 0.f, q = 0.f;
            #pragma unroll
            for (int j = 0; j < 4; j++) {
                v[j] = xr[j];
                s += v[j].x + v[j].y + v[j].z + v[j].w;
                q += v[j].x*v[j].x + v[j].y*v[j].y + v[j].z*v[j].z + v[j].w*v[j].w;
            }
            s += __shfl_xor_sync(~0u, s, 1); s += __shfl_xor_sync(~0u, s, 2);
            q += __shfl_xor_sync(~0u, q, 1); q += __shfl_xor_sync(~0u, q, 2);
            const float mean = s * (1.0f/64.0f);
            const float var  = q * (1.0f/64.0f) - mean*mean;
            const float rs   = rsqrtf(var + LNEPS);
            const float* lw = sLn + (isd ? 128 : 0);
            const float* lb = sLn + (isd ? 192 : 64);
            #pragma unroll
            for (int j = 0; j < 4; j++) {
                const int k0 = p*16 + j*4;
                sYt[(k0+0)*68 + n] = (v[j].x - mean)*rs*lw[k0+0] + lb[k0+0];
                sYt[(k0+1)*68 + n] = (v[j].y - mean)*rs*lw[k0+1] + lb[k0+1];
                sYt[(k0+2)*68 + n] = (v[j].z - mean)*rs*lw[k0+2] + lb[k0+2];
                sYt[(k0+3)*68 + n] = (v[j].w - mean)*rs*lw[k0+3] + lb[k0+3];
            }
        }
        __syncthreads();
        // GEMM 64x64
        {
            const float* W = sW + (isd ? 4096 : 0);
            u64 acc[4][2] = {};
            #pragma unroll 4
            for (int k = 0; k < 64; k++) {
                float4 xv = *(const float4*)(sYt + k*68 + n0);
                ulonglong2 w = *(const ulonglong2*)(W + k*64 + tc*4);
                u64 xp;
                PK2(xp, xv.x); FFMA2(acc[0][0], xp, w.x, acc[0][0]); FFMA2(acc[0][1], xp, w.y, acc[0][1]);
                PK2(xp, xv.y); FFMA2(acc[1][0], xp, w.x, acc[1][0]); FFMA2(acc[1][1], xp, w.y, acc[1][1]);
                PK2(xp, xv.z); FFMA2(acc[2][0], xp, w.x, acc[2][0]); FFMA2(acc[2][1], xp, w.y, acc[2][1]);
                PK2(xp, xv.w); FFMA2(acc[3][0], xp, w.x, acc[3][0]); FFMA2(acc[3][1], xp, w.y, acc[3][1]);
            }
            float* outp = isd ? g_md : g_ms;
            #pragma unroll
            for (int i = 0; i < 4; i++) {
                const int gn = base + n0 + i;
                if (gn >= NV) continue;
                float4 o;
                UPK2(o.x, o.y, acc[i][0]); UPK2(o.z, o.w, acc[i][1]);
                if (isd) {
                    o.x += sBd[tc*4]; o.y += sBd[tc*4+1];
                    o.z += sBd[tc*4+2]; o.w += sBd[tc*4+3];
                }
                *(float4*)(outp + (size_t)gn*64 + tc*4) = o;
            }
        }
    }
}

// ---------------- heavy fused edge kernel (unchanged from R6 winner) ----------------
#define TEDGE 128
#define NTILE2 ((EE + TEDGE - 1) / TEDGE)
#define SDE 132
#define OFF_WR1   0
#define OFF_WR2   4096
#define OFF_WEA   12288
#define OFF_WDTP  13312
#define OFF_BR1   21504
#define OFF_BR2   21568
#define OFF_AL    21696
#define OFF_ESt   21760
#define OFF_Rt    (OFF_ESt + 8448)
#define OFF_MSGt  (OFF_Rt  + 8448)
#define OFF_EAt   (OFF_MSGt+ 8448)
#define SMEM_EDGE_FLOATS (OFF_EAt + 2112)

__global__ void __launch_bounds__(256, 1)
k_edge(const float* __restrict__ es_g, const float* __restrict__ ea_g,
       const float* __restrict__ el_g,
       const int* __restrict__ esrc, const int* __restrict__ edst,
       const float* __restrict__ Wr1, const float* __restrict__ br1,
       const float* __restrict__ Wr2, const float* __restrict__ br2,
       const float* __restrict__ Wea, const float* __restrict__ Wdtp,
       const float* __restrict__ alpha) {
    extern __shared__ float sm[];
    float* sWr1  = sm + OFF_WR1;
    float* sWr2  = sm + OFF_WR2;
    float* sWea  = sm + OFF_WEA;
    float* sWdtp = sm + OFF_WDTP;
    float* sbr1  = sm + OFF_BR1;
    float* sbr2  = sm + OFF_BR2;
    float* sal   = sm + OFF_AL;
    float* sESt  = sm + OFF_ESt;
    float* sRt   = sm + OFF_Rt;
    float* sMSGt = sm + OFF_MSGt;
    float* sEAt  = sm + OFF_EAt;
    float* sA    = sm + OFF_EAt;

    const int tid = threadIdx.x;
    for (int i = tid; i < 4096; i += 256) sWr1[i]  = Wr1[i];
    for (int i = tid; i < 8192; i += 256) sWr2[i]  = Wr2[i];
    for (int i = tid; i < 1024; i += 256) sWea[i]  = Wea[i];
    for (int i = tid; i < 8192; i += 256) sWdtp[i] = Wdtp[i];
    if (tid < 64)  sbr1[tid] = br1[tid];
    if (tid < 128) sbr2[tid] = br2[tid];
    if (tid < 64)  sal[tid]  = alpha[tid];

    const int te = tid & 31;
    const int tc = tid >> 5;
    const int e0 = te * 4;

    for (int tile = blockIdx.x; tile < NTILE2; tile += gridDim.x) {
        const int base = tile * TEDGE;
        __syncthreads();

        {
            #pragma unroll
            for (int j = 0; j < 2; j++) {
                const int idx = tid + j*256;
                const int e = idx >> 2, p = idx & 3;
                int ge = base + e; if (ge >= EE) ge = EE - 1;
                const float4* esrow = (const float4*)(es_g + (size_t)ge*64 + p*16);
                const int sidx = esrc[ge], didx = edst[ge];
                const float4* msr = (const float4*)(g_ms + (size_t)sidx*64 + p*16);
                const float4* mdr = (const float4*)(g_md + (size_t)didx*64 + p*16);
                #pragma unroll
                for (int q = 0; q < 4; q++) {
                    float4 v = esrow[q];
                    int k0 = p*16 + q*4;
                    sESt[(k0+0)*SDE + e] = v.x;
                    sESt[(k0+1)*SDE + e] = v.y;
                    sESt[(k0+2)*SDE + e] = v.z;
                    sESt[(k0+3)*SDE + e] = v.w;
                    float4 a = msr[q], d = mdr[q];
                    sMSGt[(k0+0)*SDE + e] = a.x + d.x;
                    sMSGt[(k0+1)*SDE + e] = a.y + d.y;
                    sMSGt[(k0+2)*SDE + e] = a.z + d.z;
                    sMSGt[(k0+3)*SDE + e] = a.w + d.w;
                }
            }
            if (tid < TEDGE) {
                int ge2 = base + tid; if (ge2 >= EE) ge2 = EE - 1;
                const float4* ear = (const float4*)(ea_g + (size_t)ge2*16);
                #pragma unroll
                for (int q = 0; q < 4; q++) {
                    float4 v = ear[q];
                    sEAt[(q*4+0)*SDE + tid] = v.x;
                    sEAt[(q*4+1)*SDE + tid] = v.y;
                    sEAt[(q*4+2)*SDE + tid] = v.z;
                    sEAt[(q*4+3)*SDE + tid] = v.w;
                }
            }
        }
        __syncthreads();

        u64 ea2[4][4] = {};
        {
            u64 acc[4][4] = {};
            #pragma unroll 4
            for (int k = 0; k < 64; k++) {
                float4 xv = *(const float4*)(sESt + k*SDE + e0);
                ulonglong2 wa = *(const ulonglong2*)(sWr1 + k*64 + tc*8);
                ulonglong2 wb = *(const ulonglong2*)(sWr1 + k*64 + tc*8 + 4);
                u64 xp;
                PK2(xp, xv.x);
                FFMA2(acc[0][0], xp, wa.x, acc[0][0]); FFMA2(acc[0][1], xp, wa.y, acc[0][1]);
                FFMA2(acc[0][2], xp, wb.x, acc[0][2]); FFMA2(acc[0][3], xp, wb.y, acc[0][3]);
                PK2(xp, xv.y);
                FFMA2(acc[1][0], xp, wa.x, acc[1][0]); FFMA2(acc[1][1], xp, wa.y, acc[1][1]);
                FFMA2(acc[1][2], xp, wb.x, acc[1][2]); FFMA2(acc[1][3], xp, wb.y, acc[1][3]);
                PK2(xp, xv.z);
                FFMA2(acc[2][0], xp, wa.x, acc[2][0]); FFMA2(acc[2][1], xp, wa.y, acc[2][1]);
                FFMA2(acc[2][2], xp, wb.x, acc[2][2]); FFMA2(acc[2][3], xp, wb.y, acc[2][3]);
                PK2(xp, xv.w);
                FFMA2(acc[3][0], xp, wa.x, acc[3][0]); FFMA2(acc[3][1], xp, wa.y, acc[3][1]);
                FFMA2(acc[3][2], xp, wb.x, acc[3][2]); FFMA2(acc[3][3], xp, wb.y, acc[3][3]);
            }
            #pragma unroll
            for (int jp = 0; jp < 4; jp++) {
                float lo[4], hi[4];
                #pragma unroll
                for (int i = 0; i < 4; i++) UPK2(lo[i], hi[i], acc[i][jp]);
                float b0 = sbr1[tc*8 + 2*jp], b1 = sbr1[tc*8 + 2*jp + 1];
                float4 v0, v1;
                v0.x = lo[0]+b0; v0.y = lo[1]+b0; v0.z = lo[2]+b0; v0.w = lo[3]+b0;
                v1.x = hi[0]+b1; v1.y = hi[1]+b1; v1.z = hi[2]+b1; v1.w = hi[3]+b1;
                v0.x /= (1.0f + __expf(-v0.x)); v0.y /= (1.0f + __expf(-v0.y));
                v0.z /= (1.0f + __expf(-v0.z)); v0.w /= (1.0f + __expf(-v0.w));
                v1.x /= (1.0f + __expf(-v1.x)); v1.y /= (1.0f + __expf(-v1.y));
                v1.z /= (1.0f + __expf(-v1.z)); v1.w /= (1.0f + __expf(-v1.w));
                *(float4*)(sRt + (tc*8 + 2*jp)*SDE   + e0) = v0;
                *(float4*)(sRt + (tc*8 + 2*jp+1)*SDE + e0) = v1;
            }
            #pragma unroll
            for (int k = 0; k < 16; k++) {
                float4 xv = *(const float4*)(sEAt + k*SDE + e0);
                ulonglong2 wa = *(const ulonglong2*)(sWea + k*64 + tc*8);
                ulonglong2 wb = *(const ulonglong2*)(sWea + k*64 + tc*8 + 4);
                u64 xp;
                PK2(xp, xv.x);
                FFMA2(ea2[0][0], xp, wa.x, ea2[0][0]); FFMA2(ea2[0][1], xp, wa.y, ea2[0][1]);
                FFMA2(ea2[0][2], xp, wb.x, ea2[0][2]); FFMA2(ea2[0][3], xp, wb.y, ea2[0][3]);
                PK2(xp, xv.y);
                FFMA2(ea2[1][0], xp, wa.x, ea2[1][0]); FFMA2(ea2[1][1], xp, wa.y, ea2[1][1]);
                FFMA2(ea2[1][2], xp, wb.x, ea2[1][2]); FFMA2(ea2[1][3], xp, wb.y, ea2[1][3]);
                PK2(xp, xv.z);
                FFMA2(ea2[2][0], xp, wa.x, ea2[2][0]); FFMA2(ea2[2][1], xp, wa.y, ea2[2][1]);
                FFMA2(ea2[2][2], xp, wb.x, ea2[2][2]); FFMA2(ea2[2][3], xp, wb.y, ea2[2][3]);
                PK2(xp, xv.w);
                FFMA2(ea2[3][0], xp, wa.x, ea2[3][0]); FFMA2(ea2[3][1], xp, wa.y, ea2[3][1]);
                FFMA2(ea2[3][2], xp, wb.x, ea2[3][2]); FFMA2(ea2[3][3], xp, wb.y, ea2[3][3]);
            }
            #pragma unroll
            for (int jp = 0; jp < 4; jp++) {
                #pragma unroll
                for (int h = 0; h < 2; h++) {
                    const int c = tc*8 + 2*jp + h;
                    float4 m4 = *(float4*)(sMSGt + c*SDE + e0);
                    float v0, v1, v2, v3, dummy;
                    if (h == 0) {
                        UPK2(v0, dummy, ea2[0][jp]); UPK2(v1, dummy, ea2[1][jp]);
                        UPK2(v2, dummy, ea2[2][jp]); UPK2(v3, dummy, ea2[3][jp]);
                    } else {
                        UPK2(dummy, v0, ea2[0][jp]); UPK2(dummy, v1, ea2[1][jp]);
                        UPK2(dummy, v2, ea2[2][jp]); UPK2(dummy, v3, ea2[3][jp]);
                    }
                    m4.x *= v0; m4.y *= v1; m4.z *= v2; m4.w *= v3;
                    *(float4*)(sMSGt + c*SDE + e0) = m4;
                }
            }
        }
        __syncthreads();

        u64 we[4][8];
        {
            u64 acc[4][8] = {};
            #pragma unroll 2
            for (int k = 0; k < 64; k++) {
                float4 xv = *(const float4*)(sRt + k*SDE + e0);
                const float* wrow = sWr2 + k*128 + tc*16;
                ulonglong2 wa = *(const ulonglong2*)(wrow);
                ulonglong2 wb = *(const ulonglong2*)(wrow + 4);
                ulonglong2 wc = *(const ulonglong2*)(wrow + 8);
                ulonglong2 wd = *(const ulonglong2*)(wrow + 12);
                u64 xp;
                #pragma unroll
                for (int i = 0; i < 4; i++) {
                    float x = (i==0) ? xv.x : (i==1) ? xv.y : (i==2) ? xv.z : xv.w;
                    PK2(xp, x);
                    FFMA2(acc[i][0], xp, wa.x, acc[i][0]); FFMA2(acc[i][1], xp, wa.y, acc[i][1]);
                    FFMA2(acc[i][2], xp, wb.x, acc[i][2]); FFMA2(acc[i][3], xp, wb.y, acc[i][3]);
                    FFMA2(acc[i][4], xp, wc.x, acc[i][4]); FFMA2(acc[i][5], xp, wc.y, acc[i][5]);
                    FFMA2(acc[i][6], xp, wd.x, acc[i][6]); FFMA2(acc[i][7], xp, wd.y, acc[i][7]);
                }
            }
            #pragma unroll
            for (int i = 0; i < 4; i++)
                #pragma unroll
                for (int jp = 0; jp < 8; jp++) {
                    u64 b = *(const u64*)(sbr2 + tc*16 + 2*jp);
                    ADD2(we[i][jp], acc[i][jp], b);
                }
        }

        u64 dtp[4][8];
        {
            u64 acc[4][8] = {};
            #pragma unroll 2
            for (int k = 0; k < 64; k++) {
                float4 xv = *(const float4*)(sMSGt + k*SDE + e0);
                const float* wrow = sWdtp + k*128 + tc*16;
                ulonglong2 wa = *(const ulonglong2*)(wrow);
                ulonglong2 wb = *(const ulonglong2*)(wrow + 4);
                ulonglong2 wc = *(const ulonglong2*)(wrow + 8);
                ulonglong2 wd = *(const ulonglong2*)(wrow + 12);
                u64 xp;
                #pragma unroll
                for (int i = 0; i < 4; i++) {
                    float x = (i==0) ? xv.x : (i==1) ? xv.y : (i==2) ? xv.z : xv.w;
                    PK2(xp, x);
                    FFMA2(acc[i][0], xp, wa.x, acc[i][0]); FFMA2(acc[i][1], xp, wa.y, acc[i][1]);
                    FFMA2(acc[i][2], xp, wb.x, acc[i][2]); FFMA2(acc[i][3], xp, wb.y, acc[i][3]);
                    FFMA2(acc[i][4], xp, wc.x, acc[i][4]); FFMA2(acc[i][5], xp, wc.y, acc[i][5]);
                    FFMA2(acc[i][6], xp, wd.x, acc[i][6]); FFMA2(acc[i][7], xp, wd.y, acc[i][7]);
                }
            }
            #pragma unroll
            for (int i = 0; i < 4; i++)
                #pragma unroll
                for (int jp = 0; jp < 8; jp++)
                    MUL2(dtp[i][jp], acc[i][jp], we[i][jp]);
        }

        if (tc < 4) {
            #pragma unroll
            for (int i = 0; i < 4; i++) {
                const int ge = base + e0 + i;
                if (ge >= EE) continue;
                float lg0 = 0.0f, lg1 = 0.0f;
                #pragma unroll
                for (int jp = 0; jp < 8; jp++) {
                    float x0, x1;
                    UPK2(x0, x1, dtp[i][jp]);
                    float lr0 = (x0 > 0.0f) ? x0 : 0.2f * x0;
                    float lr1 = (x1 > 0.0f) ? x1 : 0.2f * x1;
                    float contrib = lr0 * sal[tc*16 + 2*jp] + lr1 * sal[tc*16 + 2*jp + 1];
                    if (jp < 4) lg0 += contrib; else lg1 += contrib;
                }
                const float el = el_g[ge];
                const int d = edst[ge];
                const int h0 = tc*2;
                float a0 = __expf(lg0 + el);
                float a1 = __expf(lg1 + el);
                sA[(e0+i)*8 + h0]     = a0;
                sA[(e0+i)*8 + h0 + 1] = a1;
                asm volatile("red.global.add.v2.f32 [%0], {%1,%2};"
                             :: "l"(g_z + (size_t)d*8 + h0), "f"(a0), "f"(a1) : "memory");
            }
        }
        __syncthreads();

        if (tc >= 4) {
            const int c = (tc - 4) * 16;
            const int hA = c >> 3;
            #pragma unroll
            for (int i = 0; i < 4; i++) {
                const int ge = base + e0 + i;
                if (ge >= EE) continue;
                const int d = edst[ge];
                const float aa0 = sA[(e0+i)*8 + hA];
                const float aa1 = sA[(e0+i)*8 + hA + 1];
                float* dstp = g_acc + (size_t)d*64 + c;
                #pragma unroll
                for (int q = 0; q < 4; q++) {
                    float4 v;
                    UPK2(v.x, v.y, dtp[i][2*q]);
                    UPK2(v.z, v.w, dtp[i][2*q+1]);
                    const float av = (q < 2) ? aa0 : aa1;
                    asm volatile("red.global.add.v4.f32 [%0], {%1,%2,%3,%4};"
                                 :: "l"(dstp + q*4), "f"(v.x*av), "f"(v.y*av),
                                    "f"(v.z*av), "f"(v.w*av) : "memory");
                }
            }
        }
    }
}

// ---------------- final: tiled FFMA2 version ----------------
// smem float offsets
#define FW_P   0        // 4096
#define FW_1   4096     // 12288
#define FW_2   16384    // 12288
#define F_BP   28672    // 64
#define F_LNW  28736    // 64
#define F_LNB  28800    // 64
#define F_BF1  28864    // 192
#define F_BF2  29056    // 64
#define F_SS   29120    // 64
#define F_SQ   29184    // 64
#define F_XT   29248    // 64*68 = 4352
#define F_ET   33600    // 4352
#define F_YT   37952    // 4352
#define F_HT   42304    // 192*68 = 13056
#define SMEM_FIN 55360  // floats = 221440 B

__global__ void __launch_bounds__(256, 1)
k_final(const float* __restrict__ dst_f,
        const float* __restrict__ Wp, const float* __restrict__ bp,
        const float* __restrict__ lnw, const float* __restrict__ lnb,
        const float* __restrict__ Wf1, const float* __restrict__ bf1,
        const float* __restrict__ Wf2, const float* __restrict__ bf2,
        float* __restrict__ out) {
    extern __shared__ float sf[];
    const int tid = threadIdx.x;
    for (int i = tid; i < 4096;  i += 256) sf[FW_P + i] = Wp[i];
    for (int i = tid; i < 12288; i += 256) sf[FW_1 + i] = Wf1[i];
    for (int i = tid; i < 12288; i += 256) sf[FW_2 + i] = Wf2[i];
    if (tid < 64) {
        sf[F_BP  + tid] = bp[tid];
        sf[F_LNW + tid] = lnw[tid];
        sf[F_LNB + tid] = lnb[tid];
        sf[F_BF2 + tid] = bf2[tid];
    }
    if (tid < 192) sf[F_BF1 + tid] = bf1[tid];

    const int NT = (NDN + 63)/64;
    const int te = tid & 15, tc = tid >> 4, n0 = te*4;

    for (int tile = blockIdx.x; tile < NT; tile += gridDim.x) {
        const int base = tile * 64;
        __syncthreads();
        if (tid < 64) { sf[F_SS + tid] = 0.0f; sf[F_SQ + tid] = 0.0f; }
        // stage Xt = acc / z
        {
            const int n = tid >> 2, p = tid & 3;
            int gn = base + n; if (gn >= NDN) gn = NDN - 1;
            const float4* ar = (const float4*)(g_acc + (size_t)gn*64 + p*16);
            float z0 = g_z[(size_t)gn*8 + 2*p], z1 = g_z[(size_t)gn*8 + 2*p + 1];
            float r0 = (z0 > 0.0f) ? 1.0f/z0 : 0.0f;
            float r1 = (z1 > 0.0f) ? 1.0f/z1 : 0.0f;
            #pragma unroll
            for (int j = 0; j < 4; j++) {
                float4 v = ar[j];
                const float rr = (j < 2) ? r0 : r1;
                const int k0 = p*16 + j*4;
                sf[F_XT + (k0+0)*68 + n] = v.x * rr;
                sf[F_XT + (k0+1)*68 + n] = v.y * rr;
                sf[F_XT + (k0+2)*68 + n] = v.z * rr;
                sf[F_XT + (k0+3)*68 + n] = v.w * rr;
            }
        }
        __syncthreads();

        // GEMM1: emb = Xt @ Wp + bp + dst_f
        float emb[4][4];
        {
            u64 acc[4][2] = {};
            #pragma unroll 4
            for (int k = 0; k < 64; k++) {
                float4 xv = *(const float4*)(sf + F_XT + k*68 + n0);
                ulonglong2 w = *(const ulonglong2*)(sf + FW_P + k*64 + tc*4);
                u64 xp;
                PK2(xp, xv.x); FFMA2(acc[0][0], xp, w.x, acc[0][0]); FFMA2(acc[0][1], xp, w.y, acc[0][1]);
                PK2(xp, xv.y); FFMA2(acc[1][0], xp, w.x, acc[1][0]); FFMA2(acc[1][1], xp, w.y, acc[1][1]);
                PK2(xp, xv.z); FFMA2(acc[2][0], xp, w.x, acc[2][0]); FFMA2(acc[2][1], xp, w.y, acc[2][1]);
                PK2(xp, xv.w); FFMA2(acc[3][0], xp, w.x, acc[3][0]); FFMA2(acc[3][1], xp, w.y, acc[3][1]);
            }
            #pragma unroll
            for (int i = 0; i < 4; i++) {
                int gn = base + n0 + i; if (gn >= NDN) gn = NDN - 1;
                float4 df = *(const float4*)(dst_f + (size_t)gn*64 + tc*4);
                UPK2(emb[i][0], emb[i][1], acc[i][0]);
                UPK2(emb[i][2], emb[i][3], acc[i][1]);
                emb[i][0] += sf[F_BP + tc*4+0] + df.x;
                emb[i][1] += sf[F_BP + tc*4+1] + df.y;
                emb[i][2] += sf[F_BP + tc*4+2] + df.z;
                emb[i][3] += sf[F_BP + tc*4+3] + df.w;
            }
            // LN stats
            #pragma unroll
            for (int i = 0; i < 4; i++) {
                float s = emb[i][0] + emb[i][1] + emb[i][2] + emb[i][3];
                float q = emb[i][0]*emb[i][0] + emb[i][1]*emb[i][1]
                        + emb[i][2]*emb[i][2] + emb[i][3]*emb[i][3];
                atomicAdd(sf + F_SS + n0 + i, s);
                atomicAdd(sf + F_SQ + n0 + i, q);
            }
        }
        __syncthreads();

        // LN -> Yt
        {
            float mean[4], rs[4];
            #pragma unroll
            for (int i = 0; i < 4; i++) {
                mean[i] = sf[F_SS + n0 + i] * (1.0f/64.0f);
                float var = sf[F_SQ + n0 + i] * (1.0f/64.0f) - mean[i]*mean[i];
                rs[i] = rsqrtf(var + LNEPS);
            }
            #pragma unroll
            for (int j = 0; j < 4; j++) {
                const int c = tc*4 + j;
                const float lw = sf[F_LNW + c], lb = sf[F_LNB + c];
                float4 v;
                v.x = (emb[0][j] - mean[0]) * rs[0] * lw + lb;
                v.y = (emb[1][j] - mean[1]) * rs[1] * lw + lb;
                v.z = (emb[2][j] - mean[2]) * rs[2] * lw + lb;
                v.w = (emb[3][j] - mean[3]) * rs[3] * lw + lb;
                *(float4*)(sf + F_YT + c*68 + n0) = v;
            }
        }
        __syncthreads();

        // GEMM2: h = silu(Yt @ Wf1 + bf1) -> Ht, 3 passes of 64 cols
        #pragma unroll
        for (int pp = 0; pp < 3; pp++) {
            u64 acc[4][2] = {};
            #pragma unroll 4
            for (int k = 0; k < 64; k++) {
                float4 xv = *(const float4*)(sf + F_YT + k*68 + n0);
                ulonglong2 w = *(const ulonglong2*)(sf + FW_1 + k*192 + pp*64 + tc*4);
                u64 xp;
                PK2(xp, xv.x); FFMA2(acc[0][0], xp, w.x, acc[0][0]); FFMA2(acc[0][1], xp, w.y, acc[0][1]);
                PK2(xp, xv.y); FFMA2(acc[1][0], xp, w.x, acc[1][0]); FFMA2(acc[1][1], xp, w.y, acc[1][1]);
                PK2(xp, xv.z); FFMA2(acc[2][0], xp, w.x, acc[2][0]); FFMA2(acc[2][1], xp, w.y, acc[2][1]);
                PK2(xp, xv.w); FFMA2(acc[3][0], xp, w.x, acc[3][0]); FFMA2(acc[3][1], xp, w.y, acc[3][1]);
            }
            float h[4][4];
            #pragma unroll
            for (int i = 0; i < 4; i++) {
                UPK2(h[i][0], h[i][1], acc[i][0]);
                UPK2(h[i][2], h[i][3], acc[i][1]);
                #pragma unroll
                for (int j = 0; j < 4; j++) {
                    float x = h[i][j] + sf[F_BF1 + pp*64 + tc*4 + j];
                    h[i][j] = x / (1.0f + __expf(-x));
                }
            }
            #pragma unroll
            for (int j = 0; j < 4; j++) {
                float4 v = make_float4(h[0][j], h[1][j], h[2][j], h[3][j]);
                *(float4*)(sf + F_HT + (pp*64 + tc*4 + j)*68 + n0) = v;
            }
        }
        __syncthreads();

        // GEMM3: f = Ht @ Wf2 + bf2 + emb -> out
        {
            u64 acc[4][2] = {};
            #pragma unroll 2
            for (int k = 0; k < 192; k++) {
                float4 xv = *(const float4*)(sf + F_HT + k*68 + n0);
                ulonglong2 w = *(const ulonglong2*)(sf + FW_2 + k*64 + tc*4);
                u64 xp;
                PK2(xp, xv.x); FFMA2(acc[0][0], xp, w.x, acc[0][0]); FFMA2(acc[0][1], xp, w.y, acc[0][1]);
                PK2(xp, xv.y); FFMA2(acc[1][0], xp, w.x, acc[1][0]); FFMA2(acc[1][1], xp, w.y, acc[1][1]);
                PK2(xp, xv.z); FFMA2(acc[2][0], xp, w.x, acc[2][0]); FFMA2(acc[2][1], xp, w.y, acc[2][1]);
                PK2(xp, xv.w); FFMA2(acc[3][0], xp, w.x, acc[3][0]); FFMA2(acc[3][1], xp, w.y, acc[3][1]);
            }
            #pragma unroll
            for (int i = 0; i < 4; i++) {
                const int gn = base + n0 + i;
                if (gn >= NDN) continue;
                float4 o;
                UPK2(o.x, o.y, acc[i][0]); UPK2(o.z, o.w, acc[i][1]);
                o.x += sf[F_BF2 + tc*4+0] + emb[i][0];
                o.y += sf[F_BF2 + tc*4+1] + emb[i][1];
                o.z += sf[F_BF2 + tc*4+2] + emb[i][2];
                o.w += sf[F_BF2 + tc*4+3] + emb[i][3];
                *(float4*)(out + (size_t)gn*64 + tc*4) = o;
            }
        }
    }
}

// ---------------- launch ----------------
extern "C" void kernel_launch(void* const* d_in, const int* in_sizes, int n_in,
                              void* d_out, int out_size) {
    const float* src_f        = (const float*)d_in[0];
    const float* dst_f        = (const float*)d_in[1];
    const float* edge_attr    = (const float*)d_in[2];
    const float* edge_scalars = (const float*)d_in[3];
    const float* edge_logits  = (const float*)d_in[4];
    const int*   edge_src     = (const int*)d_in[5];
    const int*   edge_dst     = (const int*)d_in[6];
    const float* ln_src_w = (const float*)d_in[7];
    const float* ln_src_b = (const float*)d_in[8];
    const float* W_src    = (const float*)d_in[9];
    const float* ln_dst_w = (const float*)d_in[10];
    const float* ln_dst_b = (const float*)d_in[11];
    const float* W_dst    = (const float*)d_in[12];
    const float* b_dst    = (const float*)d_in[13];
    const float* W_ea     = (const float*)d_in[14];
    const float* W_dtp    = (const float*)d_in[15];
    const float* W_r1     = (const float*)d_in[16];
    const float* b_r1     = (const float*)d_in[17];
    const float* W_r2     = (const float*)d_in[18];
    const float* b_r2     = (const float*)d_in[19];
    const float* alpha    = (const float*)d_in[20];
    const float* W_proj   = (const float*)d_in[21];
    const float* b_proj   = (const float*)d_in[22];
    const float* ln_post_w = (const float*)d_in[23];
    const float* ln_post_b = (const float*)d_in[24];
    const float* W_f1     = (const float*)d_in[25];
    const float* b_f1     = (const float*)d_in[26];
    const float* W_f2     = (const float*)d_in[27];
    const float* b_f2     = (const float*)d_in[28];
    float* out = (float*)d_out;

    cudaFuncSetAttribute(k_edge, cudaFuncAttributeMaxDynamicSharedMemorySize,
                         SMEM_EDGE_FLOATS * 4);
    cudaFuncSetAttribute(k_final, cudaFuncAttributeMaxDynamicSharedMemorySize,
                         SMEM_FIN * 4);
    cudaFuncSetAttribute(k_node, cudaFuncAttributeMaxDynamicSharedMemorySize,
                         KN_SMEM * 4);

    k_init<<<(NDN*CC + 255)/256, 256>>>();
    k_node<<<296, 256, KN_SMEM*4>>>(src_f, dst_f, ln_src_w, ln_src_b, W_src,
                                    ln_dst_w, ln_dst_b, W_dst, b_dst);
    k_edge<<<296, 256, SMEM_EDGE_FLOATS*4>>>(edge_scalars, edge_attr, edge_logits,
                                             edge_src, edge_dst,
                                             W_r1, b_r1, W_r2, b_r2, W_ea, W_dtp, alpha);
    k_final<<<148, 256, SMEM_FIN*4>>>(dst_f, W_proj, b_proj,
                                      ln_post_w, ln_post_b,
                                      W_f1, b_f1, W_f2, b_f2, out);
}

// round 9
// speedup vs baseline: 1.7068x; 1.0382x over previous
#include <cuda_runtime.h>
#include <cstdint>

#define NSN 50000
#define NDN 50000
#define EE  600000
#define CC  64
#define HH  8
#define LNEPS 1e-5f

typedef unsigned long long u64;

// packed f32x2 helpers (SASS FFMA2 — only reachable via PTX fma.rn.f32x2)
#define FFMA2(d, a, b, c) asm("fma.rn.f32x2 %0, %1, %2, %3;" : "=l"(d) : "l"(a), "l"(b), "l"(c))
#define MUL2(d, a, b)     asm("mul.rn.f32x2 %0, %1, %2;"     : "=l"(d) : "l"(a), "l"(b))
#define ADD2(d, a, b)     asm("add.rn.f32x2 %0, %1, %2;"     : "=l"(d) : "l"(a), "l"(b))
#define PK2(d, x)         asm("mov.b64 %0, {%1, %1};"        : "=l"(d) : "f"(x))
#define UPK2(lo, hi, v)   asm("mov.b64 {%0, %1}, %2;"        : "=f"(lo), "=f"(hi) : "l"(v))

// ---------------- scratch ----------------
__device__ float g_ms[(size_t)NSN*CC];
__device__ float g_md[(size_t)NDN*CC];
__device__ float g_z[(size_t)NDN*HH];
__device__ float g_acc[(size_t)NDN*CC];

// ---------------- init ----------------
__global__ void k_init() {
    int i = blockIdx.x * blockDim.x + threadIdx.x;
    if (i < NDN*HH) g_z[i] = 0.0f;
    if (i < NDN*CC) g_acc[i] = 0.0f;
}

// ---------------- node projections: 512 threads, 128-node tiles ----------------
#define KN_SMEM 16960   // floats: W 8192 | Yt 8448 | bdst 64 | ln 256
#define SDN 132
__global__ void __launch_bounds__(512)
k_node(const float* __restrict__ src_f, const float* __restrict__ dst_f,
       const float* __restrict__ lnsw, const float* __restrict__ lnsb,
       const float* __restrict__ Wsrc,
       const float* __restrict__ lndw, const float* __restrict__ lndb,
       const float* __restrict__ Wdst, const float* __restrict__ bdst) {
    extern __shared__ float sn[];
    float* sW  = sn;           // 8192
    float* sYt = sn + 8192;    // 8448
    float* sBd = sn + 16640;   // 64
    float* sLn = sn + 16704;   // 256
    const int tid = threadIdx.x;
    for (int i = tid; i < 8192; i += 512) sW[i] = (i < 4096) ? Wsrc[i] : Wdst[i-4096];
    if (tid < 64) {
        sBd[tid] = bdst[tid];
        sLn[tid] = lnsw[tid]; sLn[64+tid] = lnsb[tid];
        sLn[128+tid] = lndw[tid]; sLn[192+tid] = lndb[tid];
    }
    const int NTS = (NSN + 127)/128, NTD = (NDN + 127)/128;
    const int te = tid & 31, tc = tid >> 5, n0 = te*4;
    for (int tile = blockIdx.x; tile < NTS + NTD; tile += gridDim.x) {
        const bool isd = (tile >= NTS);
        const int base = (isd ? tile - NTS : tile) * 128;
        const int NV = isd ? NDN : NSN;
        __syncthreads();
        // stage + LN -> Yt transposed
        {
            const int n = tid >> 2, p = tid & 3;
            int gn = base + n; if (gn >= NV) gn = NV - 1;
            const float4* xr = (const float4*)((isd ? dst_f : src_f) + (size_t)gn*64 + p*16);
            float4 v[4]; float s = 0.f, q = 0.f;
            #pragma unroll
            for (int j = 0; j < 4; j++) {
                v[j] = xr[j];
                s += v[j].x + v[j].y + v[j].z + v[j].w;
                q += v[j].x*v[j].x + v[j].y*v[j].y + v[j].z*v[j].z + v[j].w*v[j].w;
            }
            s += __shfl_xor_sync(~0u, s, 1); s += __shfl_xor_sync(~0u, s, 2);
            q += __shfl_xor_sync(~0u, q, 1); q += __shfl_xor_sync(~0u, q, 2);
            const float mean = s * (1.0f/64.0f);
            const float var  = q * (1.0f/64.0f) - mean*mean;
            const float rs   = rsqrtf(var + LNEPS);
            const float* lw = sLn + (isd ? 128 : 0);
            const float* lb = sLn + (isd ? 192 : 64);
            #pragma unroll
            for (int j = 0; j < 4; j++) {
                const int k0 = p*16 + j*4;
                sYt[(k0+0)*SDN + n] = (v[j].x - mean)*rs*lw[k0+0] + lb[k0+0];
                sYt[(k0+1)*SDN + n] = (v[j].y - mean)*rs*lw[k0+1] + lb[k0+1];
                sYt[(k0+2)*SDN + n] = (v[j].z - mean)*rs*lw[k0+2] + lb[k0+2];
                sYt[(k0+3)*SDN + n] = (v[j].w - mean)*rs*lw[k0+3] + lb[k0+3];
            }
        }
        __syncthreads();
        // GEMM 128x64
        {
            const float* W = sW + (isd ? 4096 : 0);
            u64 acc[4][2] = {};
            #pragma unroll 4
            for (int k = 0; k < 64; k++) {
                float4 xv = *(const float4*)(sYt + k*SDN + n0);
                ulonglong2 w = *(const ulonglong2*)(W + k*64 + tc*4);
                u64 xp;
                PK2(xp, xv.x); FFMA2(acc[0][0], xp, w.x, acc[0][0]); FFMA2(acc[0][1], xp, w.y, acc[0][1]);
                PK2(xp, xv.y); FFMA2(acc[1][0], xp, w.x, acc[1][0]); FFMA2(acc[1][1], xp, w.y, acc[1][1]);
                PK2(xp, xv.z); FFMA2(acc[2][0], xp, w.x, acc[2][0]); FFMA2(acc[2][1], xp, w.y, acc[2][1]);
                PK2(xp, xv.w); FFMA2(acc[3][0], xp, w.x, acc[3][0]); FFMA2(acc[3][1], xp, w.y, acc[3][1]);
            }
            float* outp = isd ? g_md : g_ms;
            #pragma unroll
            for (int i = 0; i < 4; i++) {
                const int gn = base + n0 + i;
                if (gn >= NV) continue;
                float4 o;
                UPK2(o.x, o.y, acc[i][0]); UPK2(o.z, o.w, acc[i][1]);
                if (isd) {
                    o.x += sBd[tc*4]; o.y += sBd[tc*4+1];
                    o.z += sBd[tc*4+2]; o.w += sBd[tc*4+3];
                }
                *(float4*)(outp + (size_t)gn*64 + tc*4) = o;
            }
        }
    }
}

// ---------------- heavy fused edge kernel (R6/R7 winner, unchanged) ----------------
#define TEDGE 128
#define NTILE2 ((EE + TEDGE - 1) / TEDGE)
#define SDE 132
#define OFF_WR1   0
#define OFF_WR2   4096
#define OFF_WEA   12288
#define OFF_WDTP  13312
#define OFF_BR1   21504
#define OFF_BR2   21568
#define OFF_AL    21696
#define OFF_ESt   21760
#define OFF_Rt    (OFF_ESt + 8448)
#define OFF_MSGt  (OFF_Rt  + 8448)
#define OFF_EAt   (OFF_MSGt+ 8448)
#define SMEM_EDGE_FLOATS (OFF_EAt + 2112)

__global__ void __launch_bounds__(256, 1)
k_edge(const float* __restrict__ es_g, const float* __restrict__ ea_g,
       const float* __restrict__ el_g,
       const int* __restrict__ esrc, const int* __restrict__ edst,
       const float* __restrict__ Wr1, const float* __restrict__ br1,
       const float* __restrict__ Wr2, const float* __restrict__ br2,
       const float* __restrict__ Wea, const float* __restrict__ Wdtp,
       const float* __restrict__ alpha) {
    extern __shared__ float sm[];
    float* sWr1  = sm + OFF_WR1;
    float* sWr2  = sm + OFF_WR2;
    float* sWea  = sm + OFF_WEA;
    float* sWdtp = sm + OFF_WDTP;
    float* sbr1  = sm + OFF_BR1;
    float* sbr2  = sm + OFF_BR2;
    float* sal   = sm + OFF_AL;
    float* sESt  = sm + OFF_ESt;
    float* sRt   = sm + OFF_Rt;
    float* sMSGt = sm + OFF_MSGt;
    float* sEAt  = sm + OFF_EAt;
    float* sA    = sm + OFF_EAt;

    const int tid = threadIdx.x;
    for (int i = tid; i < 4096; i += 256) sWr1[i]  = Wr1[i];
    for (int i = tid; i < 8192; i += 256) sWr2[i]  = Wr2[i];
    for (int i = tid; i < 1024; i += 256) sWea[i]  = Wea[i];
    for (int i = tid; i < 8192; i += 256) sWdtp[i] = Wdtp[i];
    if (tid < 64)  sbr1[tid] = br1[tid];
    if (tid < 128) sbr2[tid] = br2[tid];
    if (tid < 64)  sal[tid]  = alpha[tid];

    const int te = tid & 31;
    const int tc = tid >> 5;
    const int e0 = te * 4;

    for (int tile = blockIdx.x; tile < NTILE2; tile += gridDim.x) {
        const int base = tile * TEDGE;
        __syncthreads();

        {
            #pragma unroll
            for (int j = 0; j < 2; j++) {
                const int idx = tid + j*256;
                const int e = idx >> 2, p = idx & 3;
                int ge = base + e; if (ge >= EE) ge = EE - 1;
                const float4* esrow = (const float4*)(es_g + (size_t)ge*64 + p*16);
                const int sidx = esrc[ge], didx = edst[ge];
                const float4* msr = (const float4*)(g_ms + (size_t)sidx*64 + p*16);
                const float4* mdr = (const float4*)(g_md + (size_t)didx*64 + p*16);
                #pragma unroll
                for (int q = 0; q < 4; q++) {
                    float4 v = esrow[q];
                    int k0 = p*16 + q*4;
                    sESt[(k0+0)*SDE + e] = v.x;
                    sESt[(k0+1)*SDE + e] = v.y;
                    sESt[(k0+2)*SDE + e] = v.z;
                    sESt[(k0+3)*SDE + e] = v.w;
                    float4 a = msr[q], d = mdr[q];
                    sMSGt[(k0+0)*SDE + e] = a.x + d.x;
                    sMSGt[(k0+1)*SDE + e] = a.y + d.y;
                    sMSGt[(k0+2)*SDE + e] = a.z + d.z;
                    sMSGt[(k0+3)*SDE + e] = a.w + d.w;
                }
            }
            if (tid < TEDGE) {
                int ge2 = base + tid; if (ge2 >= EE) ge2 = EE - 1;
                const float4* ear = (const float4*)(ea_g + (size_t)ge2*16);
                #pragma unroll
                for (int q = 0; q < 4; q++) {
                    float4 v = ear[q];
                    sEAt[(q*4+0)*SDE + tid] = v.x;
                    sEAt[(q*4+1)*SDE + tid] = v.y;
                    sEAt[(q*4+2)*SDE + tid] = v.z;
                    sEAt[(q*4+3)*SDE + tid] = v.w;
                }
            }
        }
        __syncthreads();

        u64 ea2[4][4] = {};
        {
            u64 acc[4][4] = {};
            #pragma unroll 4
            for (int k = 0; k < 64; k++) {
                float4 xv = *(const float4*)(sESt + k*SDE + e0);
                ulonglong2 wa = *(const ulonglong2*)(sWr1 + k*64 + tc*8);
                ulonglong2 wb = *(const ulonglong2*)(sWr1 + k*64 + tc*8 + 4);
                u64 xp;
                PK2(xp, xv.x);
                FFMA2(acc[0][0], xp, wa.x, acc[0][0]); FFMA2(acc[0][1], xp, wa.y, acc[0][1]);
                FFMA2(acc[0][2], xp, wb.x, acc[0][2]); FFMA2(acc[0][3], xp, wb.y, acc[0][3]);
                PK2(xp, xv.y);
                FFMA2(acc[1][0], xp, wa.x, acc[1][0]); FFMA2(acc[1][1], xp, wa.y, acc[1][1]);
                FFMA2(acc[1][2], xp, wb.x, acc[1][2]); FFMA2(acc[1][3], xp, wb.y, acc[1][3]);
                PK2(xp, xv.z);
                FFMA2(acc[2][0], xp, wa.x, acc[2][0]); FFMA2(acc[2][1], xp, wa.y, acc[2][1]);
                FFMA2(acc[2][2], xp, wb.x, acc[2][2]); FFMA2(acc[2][3], xp, wb.y, acc[2][3]);
                PK2(xp, xv.w);
                FFMA2(acc[3][0], xp, wa.x, acc[3][0]); FFMA2(acc[3][1], xp, wa.y, acc[3][1]);
                FFMA2(acc[3][2], xp, wb.x, acc[3][2]); FFMA2(acc[3][3], xp, wb.y, acc[3][3]);
            }
            #pragma unroll
            for (int jp = 0; jp < 4; jp++) {
                float lo[4], hi[4];
                #pragma unroll
                for (int i = 0; i < 4; i++) UPK2(lo[i], hi[i], acc[i][jp]);
                float b0 = sbr1[tc*8 + 2*jp], b1 = sbr1[tc*8 + 2*jp + 1];
                float4 v0, v1;
                v0.x = lo[0]+b0; v0.y = lo[1]+b0; v0.z = lo[2]+b0; v0.w = lo[3]+b0;
                v1.x = hi[0]+b1; v1.y = hi[1]+b1; v1.z = hi[2]+b1; v1.w = hi[3]+b1;
                v0.x /= (1.0f + __expf(-v0.x)); v0.y /= (1.0f + __expf(-v0.y));
                v0.z /= (1.0f + __expf(-v0.z)); v0.w /= (1.0f + __expf(-v0.w));
                v1.x /= (1.0f + __expf(-v1.x)); v1.y /= (1.0f + __expf(-v1.y));
                v1.z /= (1.0f + __expf(-v1.z)); v1.w /= (1.0f + __expf(-v1.w));
                *(float4*)(sRt + (tc*8 + 2*jp)*SDE   + e0) = v0;
                *(float4*)(sRt + (tc*8 + 2*jp+1)*SDE + e0) = v1;
            }
            #pragma unroll
            for (int k = 0; k < 16; k++) {
                float4 xv = *(const float4*)(sEAt + k*SDE + e0);
                ulonglong2 wa = *(const ulonglong2*)(sWea + k*64 + tc*8);
                ulonglong2 wb = *(const ulonglong2*)(sWea + k*64 + tc*8 + 4);
                u64 xp;
                PK2(xp, xv.x);
                FFMA2(ea2[0][0], xp, wa.x, ea2[0][0]); FFMA2(ea2[0][1], xp, wa.y, ea2[0][1]);
                FFMA2(ea2[0][2], xp, wb.x, ea2[0][2]); FFMA2(ea2[0][3], xp, wb.y, ea2[0][3]);
                PK2(xp, xv.y);
                FFMA2(ea2[1][0], xp, wa.x, ea2[1][0]); FFMA2(ea2[1][1], xp, wa.y, ea2[1][1]);
                FFMA2(ea2[1][2], xp, wb.x, ea2[1][2]); FFMA2(ea2[1][3], xp, wb.y, ea2[1][3]);
                PK2(xp, xv.z);
                FFMA2(ea2[2][0], xp, wa.x, ea2[2][0]); FFMA2(ea2[2][1], xp, wa.y, ea2[2][1]);
                FFMA2(ea2[2][2], xp, wb.x, ea2[2][2]); FFMA2(ea2[2][3], xp, wb.y, ea2[2][3]);
                PK2(xp, xv.w);
                FFMA2(ea2[3][0], xp, wa.x, ea2[3][0]); FFMA2(ea2[3][1], xp, wa.y, ea2[3][1]);
                FFMA2(ea2[3][2], xp, wb.x, ea2[3][2]); FFMA2(ea2[3][3], xp, wb.y, ea2[3][3]);
            }
            #pragma unroll
            for (int jp = 0; jp < 4; jp++) {
                #pragma unroll
                for (int h = 0; h < 2; h++) {
                    const int c = tc*8 + 2*jp + h;
                    float4 m4 = *(float4*)(sMSGt + c*SDE + e0);
                    float v0, v1, v2, v3, dummy;
                    if (h == 0) {
                        UPK2(v0, dummy, ea2[0][jp]); UPK2(v1, dummy, ea2[1][jp]);
                        UPK2(v2, dummy, ea2[2][jp]); UPK2(v3, dummy, ea2[3][jp]);
                    } else {
                        UPK2(dummy, v0, ea2[0][jp]); UPK2(dummy, v1, ea2[1][jp]);
                        UPK2(dummy, v2, ea2[2][jp]); UPK2(dummy, v3, ea2[3][jp]);
                    }
                    m4.x *= v0; m4.y *= v1; m4.z *= v2; m4.w *= v3;
                    *(float4*)(sMSGt + c*SDE + e0) = m4;
                }
            }
        }
        __syncthreads();

        u64 we[4][8];
        {
            u64 acc[4][8] = {};
            #pragma unroll 2
            for (int k = 0; k < 64; k++) {
                float4 xv = *(const float4*)(sRt + k*SDE + e0);
                const float* wrow = sWr2 + k*128 + tc*16;
                ulonglong2 wa = *(const ulonglong2*)(wrow);
                ulonglong2 wb = *(const ulonglong2*)(wrow + 4);
                ulonglong2 wc = *(const ulonglong2*)(wrow + 8);
                ulonglong2 wd = *(const ulonglong2*)(wrow + 12);
                u64 xp;
                #pragma unroll
                for (int i = 0; i < 4; i++) {
                    float x = (i==0) ? xv.x : (i==1) ? xv.y : (i==2) ? xv.z : xv.w;
                    PK2(xp, x);
                    FFMA2(acc[i][0], xp, wa.x, acc[i][0]); FFMA2(acc[i][1], xp, wa.y, acc[i][1]);
                    FFMA2(acc[i][2], xp, wb.x, acc[i][2]); FFMA2(acc[i][3], xp, wb.y, acc[i][3]);
                    FFMA2(acc[i][4], xp, wc.x, acc[i][4]); FFMA2(acc[i][5], xp, wc.y, acc[i][5]);
                    FFMA2(acc[i][6], xp, wd.x, acc[i][6]); FFMA2(acc[i][7], xp, wd.y, acc[i][7]);
                }
            }
            #pragma unroll
            for (int i = 0; i < 4; i++)
                #pragma unroll
                for (int jp = 0; jp < 8; jp++) {
                    u64 b = *(const u64*)(sbr2 + tc*16 + 2*jp);
                    ADD2(we[i][jp], acc[i][jp], b);
                }
        }

        u64 dtp[4][8];
        {
            u64 acc[4][8] = {};
            #pragma unroll 2
            for (int k = 0; k < 64; k++) {
                float4 xv = *(const float4*)(sMSGt + k*SDE + e0);
                const float* wrow = sWdtp + k*128 + tc*16;
                ulonglong2 wa = *(const ulonglong2*)(wrow);
                ulonglong2 wb = *(const ulonglong2*)(wrow + 4);
                ulonglong2 wc = *(const ulonglong2*)(wrow + 8);
                ulonglong2 wd = *(const ulonglong2*)(wrow + 12);
                u64 xp;
                #pragma unroll
                for (int i = 0; i < 4; i++) {
                    float x = (i==0) ? xv.x : (i==1) ? xv.y : (i==2) ? xv.z : xv.w;
                    PK2(xp, x);
                    FFMA2(acc[i][0], xp, wa.x, acc[i][0]); FFMA2(acc[i][1], xp, wa.y, acc[i][1]);
                    FFMA2(acc[i][2], xp, wb.x, acc[i][2]); FFMA2(acc[i][3], xp, wb.y, acc[i][3]);
                    FFMA2(acc[i][4], xp, wc.x, acc[i][4]); FFMA2(acc[i][5], xp, wc.y, acc[i][5]);
                    FFMA2(acc[i][6], xp, wd.x, acc[i][6]); FFMA2(acc[i][7], xp, wd.y, acc[i][7]);
                }
            }
            #pragma unroll
            for (int i = 0; i < 4; i++)
                #pragma unroll
                for (int jp = 0; jp < 8; jp++)
                    MUL2(dtp[i][jp], acc[i][jp], we[i][jp]);
        }

        if (tc < 4) {
            #pragma unroll
            for (int i = 0; i < 4; i++) {
                const int ge = base + e0 + i;
                if (ge >= EE) continue;
                float lg0 = 0.0f, lg1 = 0.0f;
                #pragma unroll
                for (int jp = 0; jp < 8; jp++) {
                    float x0, x1;
                    UPK2(x0, x1, dtp[i][jp]);
                    float lr0 = (x0 > 0.0f) ? x0 : 0.2f * x0;
                    float lr1 = (x1 > 0.0f) ? x1 : 0.2f * x1;
                    float contrib = lr0 * sal[tc*16 + 2*jp] + lr1 * sal[tc*16 + 2*jp + 1];
                    if (jp < 4) lg0 += contrib; else lg1 += contrib;
                }
                const float el = el_g[ge];
                const int d = edst[ge];
                const int h0 = tc*2;
                float a0 = __expf(lg0 + el);
                float a1 = __expf(lg1 + el);
                sA[(e0+i)*8 + h0]     = a0;
                sA[(e0+i)*8 + h0 + 1] = a1;
                asm volatile("red.global.add.v2.f32 [%0], {%1,%2};"
                             :: "l"(g_z + (size_t)d*8 + h0), "f"(a0), "f"(a1) : "memory");
            }
        }
        __syncthreads();

        if (tc >= 4) {
            const int c = (tc - 4) * 16;
            const int hA = c >> 3;
            #pragma unroll
            for (int i = 0; i < 4; i++) {
                const int ge = base + e0 + i;
                if (ge >= EE) continue;
                const int d = edst[ge];
                const float aa0 = sA[(e0+i)*8 + hA];
                const float aa1 = sA[(e0+i)*8 + hA + 1];
                float* dstp = g_acc + (size_t)d*64 + c;
                #pragma unroll
                for (int q = 0; q < 4; q++) {
                    float4 v;
                    UPK2(v.x, v.y, dtp[i][2*q]);
                    UPK2(v.z, v.w, dtp[i][2*q+1]);
                    const float av = (q < 2) ? aa0 : aa1;
                    asm volatile("red.global.add.v4.f32 [%0], {%1,%2,%3,%4};"
                                 :: "l"(dstp + q*4), "f"(v.x*av), "f"(v.y*av),
                                    "f"(v.z*av), "f"(v.w*av) : "memory");
                }
            }
        }
    }
}

// ---------------- final: 512 threads, 128-node tiles, fused FFN ----------------
#define FW_P   0        // 4096
#define FW_1   4096     // 12288
#define FW_2   16384    // 12288
#define F_BP   28672    // 64
#define F_LNW  28736    // 64
#define F_LNB  28800    // 64
#define F_BF1  28864    // 192
#define F_BF2  29056    // 64
#define F_SS   29120    // 128
#define F_SQ   29248    // 128
#define F_XT   29376    // 64*132 = 8448 (reused as H-chunk buffer)
#define F_YT   37824    // 8448
#define SMEM_FIN 46272  // floats = 185088 B

__global__ void __launch_bounds__(512, 1)
k_final(const float* __restrict__ dst_f,
        const float* __restrict__ Wp, const float* __restrict__ bp,
        const float* __restrict__ lnw, const float* __restrict__ lnb,
        const float* __restrict__ Wf1, const float* __restrict__ bf1,
        const float* __restrict__ Wf2, const float* __restrict__ bf2,
        float* __restrict__ out) {
    extern __shared__ float sf[];
    const int tid = threadIdx.x;
    for (int i = tid; i < 4096;  i += 512) sf[FW_P + i] = Wp[i];
    for (int i = tid; i < 12288; i += 512) sf[FW_1 + i] = Wf1[i];
    for (int i = tid; i < 12288; i += 512) sf[FW_2 + i] = Wf2[i];
    if (tid < 64) {
        sf[F_BP  + tid] = bp[tid];
        sf[F_LNW + tid] = lnw[tid];
        sf[F_LNB + tid] = lnb[tid];
        sf[F_BF2 + tid] = bf2[tid];
    }
    if (tid < 192) sf[F_BF1 + tid] = bf1[tid];

    const int NT = (NDN + 127)/128;
    const int te = tid & 31, tc = tid >> 5, n0 = te*4;

    for (int tile = blockIdx.x; tile < NT; tile += gridDim.x) {
        const int base = tile * 128;
        __syncthreads();
        if (tid < 128) { sf[F_SS + tid] = 0.0f; sf[F_SQ + tid] = 0.0f; }
        // stage Xt = acc / z  (128 nodes)
        {
            const int n = tid >> 2, p = tid & 3;
            int gn = base + n; if (gn >= NDN) gn = NDN - 1;
            const float4* ar = (const float4*)(g_acc + (size_t)gn*64 + p*16);
            float z0 = g_z[(size_t)gn*8 + 2*p], z1 = g_z[(size_t)gn*8 + 2*p + 1];
            float r0 = (z0 > 0.0f) ? 1.0f/z0 : 0.0f;
            float r1 = (z1 > 0.0f) ? 1.0f/z1 : 0.0f;
            #pragma unroll
            for (int j = 0; j < 4; j++) {
                float4 v = ar[j];
                const float rr = (j < 2) ? r0 : r1;
                const int k0 = p*16 + j*4;
                sf[F_XT + (k0+0)*SDN + n] = v.x * rr;
                sf[F_XT + (k0+1)*SDN + n] = v.y * rr;
                sf[F_XT + (k0+2)*SDN + n] = v.z * rr;
                sf[F_XT + (k0+3)*SDN + n] = v.w * rr;
            }
        }
        __syncthreads();

        // GEMM1: emb = Xt @ Wp + bp + dst_f ; LN stats
        float emb[4][4];
        {
            u64 acc[4][2] = {};
            #pragma unroll 4
            for (int k = 0; k < 64; k++) {
                float4 xv = *(const float4*)(sf + F_XT + k*SDN + n0);
                ulonglong2 w = *(const ulonglong2*)(sf + FW_P + k*64 + tc*4);
                u64 xp;
                PK2(xp, xv.x); FFMA2(acc[0][0], xp, w.x, acc[0][0]); FFMA2(acc[0][1], xp, w.y, acc[0][1]);
                PK2(xp, xv.y); FFMA2(acc[1][0], xp, w.x, acc[1][0]); FFMA2(acc[1][1], xp, w.y, acc[1][1]);
                PK2(xp, xv.z); FFMA2(acc[2][0], xp, w.x, acc[2][0]); FFMA2(acc[2][1], xp, w.y, acc[2][1]);
                PK2(xp, xv.w); FFMA2(acc[3][0], xp, w.x, acc[3][0]); FFMA2(acc[3][1], xp, w.y, acc[3][1]);
            }
            #pragma unroll
            for (int i = 0; i < 4; i++) {
                int gn = base + n0 + i; if (gn >= NDN) gn = NDN - 1;
                float4 df = *(const float4*)(dst_f + (size_t)gn*64 + tc*4);
                UPK2(emb[i][0], emb[i][1], acc[i][0]);
                UPK2(emb[i][2], emb[i][3], acc[i][1]);
                emb[i][0] += sf[F_BP + tc*4+0] + df.x;
                emb[i][1] += sf[F_BP + tc*4+1] + df.y;
                emb[i][2] += sf[F_BP + tc*4+2] + df.z;
                emb[i][3] += sf[F_BP + tc*4+3] + df.w;
            }
            #pragma unroll
            for (int i = 0; i < 4; i++) {
                float s = emb[i][0] + emb[i][1] + emb[i][2] + emb[i][3];
                float q = emb[i][0]*emb[i][0] + emb[i][1]*emb[i][1]
                        + emb[i][2]*emb[i][2] + emb[i][3]*emb[i][3];
                atomicAdd(sf + F_SS + n0 + i, s);
                atomicAdd(sf + F_SQ + n0 + i, q);
            }
        }
        __syncthreads();

        // LN -> Yt
        {
            float mean[4], rs[4];
            #pragma unroll
            for (int i = 0; i < 4; i++) {
                mean[i] = sf[F_SS + n0 + i] * (1.0f/64.0f);
                float var = sf[F_SQ + n0 + i] * (1.0f/64.0f) - mean[i]*mean[i];
                rs[i] = rsqrtf(var + LNEPS);
            }
            #pragma unroll
            for (int j = 0; j < 4; j++) {
                const int c = tc*4 + j;
                const float lw = sf[F_LNW + c], lb = sf[F_LNB + c];
                float4 v;
                v.x = (emb[0][j] - mean[0]) * rs[0] * lw + lb;
                v.y = (emb[1][j] - mean[1]) * rs[1] * lw + lb;
                v.z = (emb[2][j] - mean[2]) * rs[2] * lw + lb;
                v.w = (emb[3][j] - mean[3]) * rs[3] * lw + lb;
                *(float4*)(sf + F_YT + c*SDN + n0) = v;
            }
        }
        __syncthreads();

        // fused FFN: 3 chunks of 64 hidden dims (GEMM2 chunk -> Hbuf=F_XT; GEMM3 partial)
        u64 oacc[4][2] = {};
        #pragma unroll
        for (int pp = 0; pp < 3; pp++) {
            {
                u64 acc[4][2] = {};
                #pragma unroll 4
                for (int k = 0; k < 64; k++) {
                    float4 xv = *(const float4*)(sf + F_YT + k*SDN + n0);
                    ulonglong2 w = *(const ulonglong2*)(sf + FW_1 + k*192 + pp*64 + tc*4);
                    u64 xp;
                    PK2(xp, xv.x); FFMA2(acc[0][0], xp, w.x, acc[0][0]); FFMA2(acc[0][1], xp, w.y, acc[0][1]);
                    PK2(xp, xv.y); FFMA2(acc[1][0], xp, w.x, acc[1][0]); FFMA2(acc[1][1], xp, w.y, acc[1][1]);
                    PK2(xp, xv.z); FFMA2(acc[2][0], xp, w.x, acc[2][0]); FFMA2(acc[2][1], xp, w.y, acc[2][1]);
                    PK2(xp, xv.w); FFMA2(acc[3][0], xp, w.x, acc[3][0]); FFMA2(acc[3][1], xp, w.y, acc[3][1]);
                }
                float h[4][4];
                #pragma unroll
                for (int i = 0; i < 4; i++) {
                    UPK2(h[i][0], h[i][1], acc[i][0]);
                    UPK2(h[i][2], h[i][3], acc[i][1]);
                    #pragma unroll
                    for (int j = 0; j < 4; j++) {
                        float x = h[i][j] + sf[F_BF1 + pp*64 + tc*4 + j];
                        h[i][j] = x / (1.0f + __expf(-x));
                    }
                }
                #pragma unroll
                for (int j = 0; j < 4; j++) {
                    float4 v = make_float4(h[0][j], h[1][j], h[2][j], h[3][j]);
                    *(float4*)(sf + F_XT + (tc*4 + j)*SDN + n0) = v;
                }
            }
            __syncthreads();
            {
                #pragma unroll 4
                for (int k = 0; k < 64; k++) {
                    float4 xv = *(const float4*)(sf + F_XT + k*SDN + n0);
                    ulonglong2 w = *(const ulonglong2*)(sf + FW_2 + (pp*64 + k)*64 + tc*4);
                    u64 xp;
                    PK2(xp, xv.x); FFMA2(oacc[0][0], xp, w.x, oacc[0][0]); FFMA2(oacc[0][1], xp, w.y, oacc[0][1]);
                    PK2(xp, xv.y); FFMA2(oacc[1][0], xp, w.x, oacc[1][0]); FFMA2(oacc[1][1], xp, w.y, oacc[1][1]);
                    PK2(xp, xv.z); FFMA2(oacc[2][0], xp, w.x, oacc[2][0]); FFMA2(oacc[2][1], xp, w.y, oacc[2][1]);
                    PK2(xp, xv.w); FFMA2(oacc[3][0], xp, w.x, oacc[3][0]); FFMA2(oacc[3][1], xp, w.y, oacc[3][1]);
                }
            }
            if (pp < 2) __syncthreads();
        }

        // write out
        #pragma unroll
        for (int i = 0; i < 4; i++) {
            const int gn = base + n0 + i;
            if (gn >= NDN) continue;
            float4 o;
            UPK2(o.x, o.y, oacc[i][0]); UPK2(o.z, o.w, oacc[i][1]);
            o.x += sf[F_BF2 + tc*4+0] + emb[i][0];
            o.y += sf[F_BF2 + tc*4+1] + emb[i][1];
            o.z += sf[F_BF2 + tc*4+2] + emb[i][2];
            o.w += sf[F_BF2 + tc*4+3] + emb[i][3];
            *(float4*)(out + (size_t)gn*64 + tc*4) = o;
        }
    }
}

// ---------------- launch ----------------
extern "C" void kernel_launch(void* const* d_in, const int* in_sizes, int n_in,
                              void* d_out, int out_size) {
    const float* src_f        = (const float*)d_in[0];
    const float* dst_f        = (const float*)d_in[1];
    const float* edge_attr    = (const float*)d_in[2];
    const float* edge_scalars = (const float*)d_in[3];
    const float* edge_logits  = (const float*)d_in[4];
    const int*   edge_src     = (const int*)d_in[5];
    const int*   edge_dst     = (const int*)d_in[6];
    const float* ln_src_w = (const float*)d_in[7];
    const float* ln_src_b = (const float*)d_in[8];
    const float* W_src    = (const float*)d_in[9];
    const float* ln_dst_w = (const float*)d_in[10];
    const float* ln_dst_b = (const float*)d_in[11];
    const float* W_dst    = (const float*)d_in[12];
    const float* b_dst    = (const float*)d_in[13];
    const float* W_ea     = (const float*)d_in[14];
    const float* W_dtp    = (const float*)d_in[15];
    const float* W_r1     = (const float*)d_in[16];
    const float* b_r1     = (const float*)d_in[17];
    const float* W_r2     = (const float*)d_in[18];
    const float* b_r2     = (const float*)d_in[19];
    const float* alpha    = (const float*)d_in[20];
    const float* W_proj   = (const float*)d_in[21];
    const float* b_proj   = (const float*)d_in[22];
    const float* ln_post_w = (const float*)d_in[23];
    const float* ln_post_b = (const float*)d_in[24];
    const float* W_f1     = (const float*)d_in[25];
    const float* b_f1     = (const float*)d_in[26];
    const float* W_f2     = (const float*)d_in[27];
    const float* b_f2     = (const float*)d_in[28];
    float* out = (float*)d_out;

    cudaFuncSetAttribute(k_edge, cudaFuncAttributeMaxDynamicSharedMemorySize,
                         SMEM_EDGE_FLOATS * 4);
    cudaFuncSetAttribute(k_final, cudaFuncAttributeMaxDynamicSharedMemorySize,
                         SMEM_FIN * 4);
    cudaFuncSetAttribute(k_node, cudaFuncAttributeMaxDynamicSharedMemorySize,
                         KN_SMEM * 4);

    k_init<<<(NDN*CC + 255)/256, 256>>>();
    k_node<<<296, 512, KN_SMEM*4>>>(src_f, dst_f, ln_src_w, ln_src_b, W_src,
                                    ln_dst_w, ln_dst_b, W_dst, b_dst);
    k_edge<<<296, 256, SMEM_EDGE_FLOATS*4>>>(edge_scalars, edge_attr, edge_logits,
                                             edge_src, edge_dst,
                                             W_r1, b_r1, W_r2, b_r2, W_ea, W_dtp, alpha);
    k_final<<<148, 512, SMEM_FIN*4>>>(dst_f, W_proj, b_proj,
                                      ln_post_w, ln_post_b,
                                      W_f1, b_f1, W_f2, b_f2, out);
}

// round 10
// speedup vs baseline: 1.7461x; 1.0231x over previous
#include <cuda_runtime.h>
#include <cstdint>

#define NSN 50000
#define NDN 50000
#define EE  600000
#define CC  64
#define HH  8
#define LNEPS 1e-5f

typedef unsigned long long u64;

// packed f32x2 helpers (SASS FFMA2 — only reachable via PTX fma.rn.f32x2)
#define FFMA2(d, a, b, c) asm("fma.rn.f32x2 %0, %1, %2, %3;" : "=l"(d) : "l"(a), "l"(b), "l"(c))
#define MUL2(d, a, b)     asm("mul.rn.f32x2 %0, %1, %2;"     : "=l"(d) : "l"(a), "l"(b))
#define ADD2(d, a, b)     asm("add.rn.f32x2 %0, %1, %2;"     : "=l"(d) : "l"(a), "l"(b))
#define PK2(d, x)         asm("mov.b64 %0, {%1, %1};"        : "=l"(d) : "f"(x))
#define UPK2(lo, hi, v)   asm("mov.b64 {%0, %1}, %2;"        : "=f"(lo), "=f"(hi) : "l"(v))

// ---------------- scratch ----------------
__device__ float g_ms[(size_t)NSN*CC];
__device__ float g_md[(size_t)NDN*CC];
__device__ float g_z[(size_t)NDN*HH];
__device__ float g_acc[(size_t)NDN*CC];

// ---------------- init ----------------
__global__ void k_init() {
    int i = blockIdx.x * blockDim.x + threadIdx.x;
    if (i < NDN*HH) g_z[i] = 0.0f;
    if (i < NDN*CC) g_acc[i] = 0.0f;
}

// ---------------- node projections: 512 threads, 128-node tiles, 2n x 8c ----------------
#define KN_SMEM 16960
#define SDN 132
__global__ void __launch_bounds__(512)
k_node(const float* __restrict__ src_f, const float* __restrict__ dst_f,
       const float* __restrict__ lnsw, const float* __restrict__ lnsb,
       const float* __restrict__ Wsrc,
       const float* __restrict__ lndw, const float* __restrict__ lndb,
       const float* __restrict__ Wdst, const float* __restrict__ bdst) {
    extern __shared__ float sn[];
    float* sW  = sn;           // 8192
    float* sYt = sn + 8192;    // 8448
    float* sBd = sn + 16640;   // 64
    float* sLn = sn + 16704;   // 256
    const int tid = threadIdx.x;
    for (int i = tid; i < 8192; i += 512) sW[i] = (i < 4096) ? Wsrc[i] : Wdst[i-4096];
    if (tid < 64) {
        sBd[tid] = bdst[tid];
        sLn[tid] = lnsw[tid]; sLn[64+tid] = lnsb[tid];
        sLn[128+tid] = lndw[tid]; sLn[192+tid] = lndb[tid];
    }
    const int NTS = (NSN + 127)/128, NTD = (NDN + 127)/128;
    const int lane = tid & 31, warp = tid >> 5;
    const int tc = warp & 7;                      // 8 cols
    const int n0 = ((warp >> 3) << 6) + lane*2;   // 2 nodes
    for (int tile = blockIdx.x; tile < NTS + NTD; tile += gridDim.x) {
        const bool isd = (tile >= NTS);
        const int base = (isd ? tile - NTS : tile) * 128;
        const int NV = isd ? NDN : NSN;
        __syncthreads();
        // stage + LN -> Yt transposed
        {
            const int n = tid >> 2, p = tid & 3;
            int gn = base + n; if (gn >= NV) gn = NV - 1;
            const float4* xr = (const float4*)((isd ? dst_f : src_f) + (size_t)gn*64 + p*16);
            float4 v[4]; float s = 0.f, q = 0.f;
            #pragma unroll
            for (int j = 0; j < 4; j++) {
                v[j] = xr[j];
                s += v[j].x + v[j].y + v[j].z + v[j].w;
                q += v[j].x*v[j].x + v[j].y*v[j].y + v[j].z*v[j].z + v[j].w*v[j].w;
            }
            s += __shfl_xor_sync(~0u, s, 1); s += __shfl_xor_sync(~0u, s, 2);
            q += __shfl_xor_sync(~0u, q, 1); q += __shfl_xor_sync(~0u, q, 2);
            const float mean = s * (1.0f/64.0f);
            const float var  = q * (1.0f/64.0f) - mean*mean;
            const float rs   = rsqrtf(var + LNEPS);
            const float* lw = sLn + (isd ? 128 : 0);
            const float* lb = sLn + (isd ? 192 : 64);
            #pragma unroll
            for (int j = 0; j < 4; j++) {
                const int k0 = p*16 + j*4;
                sYt[(k0+0)*SDN + n] = (v[j].x - mean)*rs*lw[k0+0] + lb[k0+0];
                sYt[(k0+1)*SDN + n] = (v[j].y - mean)*rs*lw[k0+1] + lb[k0+1];
                sYt[(k0+2)*SDN + n] = (v[j].z - mean)*rs*lw[k0+2] + lb[k0+2];
                sYt[(k0+3)*SDN + n] = (v[j].w - mean)*rs*lw[k0+3] + lb[k0+3];
            }
        }
        __syncthreads();
        // GEMM 128x64: 2n x 8c per thread
        {
            const float* W = sW + (isd ? 4096 : 0);
            u64 acc[2][4] = {};
            #pragma unroll 4
            for (int k = 0; k < 64; k++) {
                float2 xv = *(const float2*)(sYt + k*SDN + n0);
                ulonglong2 wa = *(const ulonglong2*)(W + k*64 + tc*8);
                ulonglong2 wb = *(const ulonglong2*)(W + k*64 + tc*8 + 4);
                u64 xp;
                PK2(xp, xv.x);
                FFMA2(acc[0][0], xp, wa.x, acc[0][0]); FFMA2(acc[0][1], xp, wa.y, acc[0][1]);
                FFMA2(acc[0][2], xp, wb.x, acc[0][2]); FFMA2(acc[0][3], xp, wb.y, acc[0][3]);
                PK2(xp, xv.y);
                FFMA2(acc[1][0], xp, wa.x, acc[1][0]); FFMA2(acc[1][1], xp, wa.y, acc[1][1]);
                FFMA2(acc[1][2], xp, wb.x, acc[1][2]); FFMA2(acc[1][3], xp, wb.y, acc[1][3]);
            }
            float* outp = isd ? g_md : g_ms;
            #pragma unroll
            for (int i = 0; i < 2; i++) {
                const int gn = base + n0 + i;
                if (gn >= NV) continue;
                float4 o0, o1;
                UPK2(o0.x, o0.y, acc[i][0]); UPK2(o0.z, o0.w, acc[i][1]);
                UPK2(o1.x, o1.y, acc[i][2]); UPK2(o1.z, o1.w, acc[i][3]);
                if (isd) {
                    o0.x += sBd[tc*8+0]; o0.y += sBd[tc*8+1];
                    o0.z += sBd[tc*8+2]; o0.w += sBd[tc*8+3];
                    o1.x += sBd[tc*8+4]; o1.y += sBd[tc*8+5];
                    o1.z += sBd[tc*8+6]; o1.w += sBd[tc*8+7];
                }
                *(float4*)(outp + (size_t)gn*64 + tc*8)     = o0;
                *(float4*)(outp + (size_t)gn*64 + tc*8 + 4) = o1;
            }
        }
    }
}

// ---------------- heavy fused edge kernel: strip-split epilogue ----------------
#define TEDGE 128
#define NTILE2 ((EE + TEDGE - 1) / TEDGE)
#define SDE 132
#define OFF_WR1   0
#define OFF_WR2   4096
#define OFF_WEA   12288
#define OFF_WDTP  13312
#define OFF_BR1   21504
#define OFF_BR2   21568
#define OFF_AL    21696
#define OFF_ESt   21760
#define OFF_Rt    (OFF_ESt + 8448)
#define OFF_MSGt  (OFF_Rt  + 8448)
#define OFF_EAt   (OFF_MSGt+ 8448)
#define SMEM_EDGE_FLOATS (OFF_EAt + 2112)

__global__ void __launch_bounds__(256, 1)
k_edge(const float* __restrict__ es_g, const float* __restrict__ ea_g,
       const float* __restrict__ el_g,
       const int* __restrict__ esrc, const int* __restrict__ edst,
       const float* __restrict__ Wr1, const float* __restrict__ br1,
       const float* __restrict__ Wr2, const float* __restrict__ br2,
       const float* __restrict__ Wea, const float* __restrict__ Wdtp,
       const float* __restrict__ alpha) {
    extern __shared__ float sm[];
    float* sWr1  = sm + OFF_WR1;
    float* sWr2  = sm + OFF_WR2;
    float* sWea  = sm + OFF_WEA;
    float* sWdtp = sm + OFF_WDTP;
    float* sbr1  = sm + OFF_BR1;
    float* sbr2  = sm + OFF_BR2;
    float* sal   = sm + OFF_AL;
    float* sESt  = sm + OFF_ESt;
    float* sRt   = sm + OFF_Rt;
    float* sMSGt = sm + OFF_MSGt;
    float* sEAt  = sm + OFF_EAt;

    const int tid = threadIdx.x;
    for (int i = tid; i < 4096; i += 256) sWr1[i]  = Wr1[i];
    for (int i = tid; i < 8192; i += 256) sWr2[i]  = Wr2[i];
    for (int i = tid; i < 1024; i += 256) sWea[i]  = Wea[i];
    for (int i = tid; i < 8192; i += 256) sWdtp[i] = Wdtp[i];
    if (tid < 64)  sbr1[tid] = br1[tid];
    if (tid < 128) sbr2[tid] = br2[tid];
    if (tid < 64)  sal[tid]  = alpha[tid];

    const int te = tid & 31;
    const int tc = tid >> 5;     // warp = head index; logit strip [tc*8,+8), val strip [64+tc*8,+8)
    const int e0 = te * 4;

    for (int tile = blockIdx.x; tile < NTILE2; tile += gridDim.x) {
        const int base = tile * TEDGE;
        __syncthreads();

        {
            #pragma unroll
            for (int j = 0; j < 2; j++) {
                const int idx = tid + j*256;
                const int e = idx >> 2, p = idx & 3;
                int ge = base + e; if (ge >= EE) ge = EE - 1;
                const float4* esrow = (const float4*)(es_g + (size_t)ge*64 + p*16);
                const int sidx = esrc[ge], didx = edst[ge];
                const float4* msr = (const float4*)(g_ms + (size_t)sidx*64 + p*16);
                const float4* mdr = (const float4*)(g_md + (size_t)didx*64 + p*16);
                #pragma unroll
                for (int q = 0; q < 4; q++) {
                    float4 v = esrow[q];
                    int k0 = p*16 + q*4;
                    sESt[(k0+0)*SDE + e] = v.x;
                    sESt[(k0+1)*SDE + e] = v.y;
                    sESt[(k0+2)*SDE + e] = v.z;
                    sESt[(k0+3)*SDE + e] = v.w;
                    float4 a = msr[q], d = mdr[q];
                    sMSGt[(k0+0)*SDE + e] = a.x + d.x;
                    sMSGt[(k0+1)*SDE + e] = a.y + d.y;
                    sMSGt[(k0+2)*SDE + e] = a.z + d.z;
                    sMSGt[(k0+3)*SDE + e] = a.w + d.w;
                }
            }
            if (tid < TEDGE) {
                int ge2 = base + tid; if (ge2 >= EE) ge2 = EE - 1;
                const float4* ear = (const float4*)(ea_g + (size_t)ge2*16);
                #pragma unroll
                for (int q = 0; q < 4; q++) {
                    float4 v = ear[q];
                    sEAt[(q*4+0)*SDE + tid] = v.x;
                    sEAt[(q*4+1)*SDE + tid] = v.y;
                    sEAt[(q*4+2)*SDE + tid] = v.z;
                    sEAt[(q*4+3)*SDE + tid] = v.w;
                }
            }
        }
        __syncthreads();

        // GEMM1 + Gea + T (unchanged col mapping: tc*8..+8 of 64)
        u64 ea2[4][4] = {};
        {
            u64 acc[4][4] = {};
            #pragma unroll 4
            for (int k = 0; k < 64; k++) {
                float4 xv = *(const float4*)(sESt + k*SDE + e0);
                ulonglong2 wa = *(const ulonglong2*)(sWr1 + k*64 + tc*8);
                ulonglong2 wb = *(const ulonglong2*)(sWr1 + k*64 + tc*8 + 4);
                u64 xp;
                PK2(xp, xv.x);
                FFMA2(acc[0][0], xp, wa.x, acc[0][0]); FFMA2(acc[0][1], xp, wa.y, acc[0][1]);
                FFMA2(acc[0][2], xp, wb.x, acc[0][2]); FFMA2(acc[0][3], xp, wb.y, acc[0][3]);
                PK2(xp, xv.y);
                FFMA2(acc[1][0], xp, wa.x, acc[1][0]); FFMA2(acc[1][1], xp, wa.y, acc[1][1]);
                FFMA2(acc[1][2], xp, wb.x, acc[1][2]); FFMA2(acc[1][3], xp, wb.y, acc[1][3]);
                PK2(xp, xv.z);
                FFMA2(acc[2][0], xp, wa.x, acc[2][0]); FFMA2(acc[2][1], xp, wa.y, acc[2][1]);
                FFMA2(acc[2][2], xp, wb.x, acc[2][2]); FFMA2(acc[2][3], xp, wb.y, acc[2][3]);
                PK2(xp, xv.w);
                FFMA2(acc[3][0], xp, wa.x, acc[3][0]); FFMA2(acc[3][1], xp, wa.y, acc[3][1]);
                FFMA2(acc[3][2], xp, wb.x, acc[3][2]); FFMA2(acc[3][3], xp, wb.y, acc[3][3]);
            }
            #pragma unroll
            for (int jp = 0; jp < 4; jp++) {
                float lo[4], hi[4];
                #pragma unroll
                for (int i = 0; i < 4; i++) UPK2(lo[i], hi[i], acc[i][jp]);
                float b0 = sbr1[tc*8 + 2*jp], b1 = sbr1[tc*8 + 2*jp + 1];
                float4 v0, v1;
                v0.x = lo[0]+b0; v0.y = lo[1]+b0; v0.z = lo[2]+b0; v0.w = lo[3]+b0;
                v1.x = hi[0]+b1; v1.y = hi[1]+b1; v1.z = hi[2]+b1; v1.w = hi[3]+b1;
                v0.x /= (1.0f + __expf(-v0.x)); v0.y /= (1.0f + __expf(-v0.y));
                v0.z /= (1.0f + __expf(-v0.z)); v0.w /= (1.0f + __expf(-v0.w));
                v1.x /= (1.0f + __expf(-v1.x)); v1.y /= (1.0f + __expf(-v1.y));
                v1.z /= (1.0f + __expf(-v1.z)); v1.w /= (1.0f + __expf(-v1.w));
                *(float4*)(sRt + (tc*8 + 2*jp)*SDE   + e0) = v0;
                *(float4*)(sRt + (tc*8 + 2*jp+1)*SDE + e0) = v1;
            }
            #pragma unroll
            for (int k = 0; k < 16; k++) {
                float4 xv = *(const float4*)(sEAt + k*SDE + e0);
                ulonglong2 wa = *(const ulonglong2*)(sWea + k*64 + tc*8);
                ulonglong2 wb = *(const ulonglong2*)(sWea + k*64 + tc*8 + 4);
                u64 xp;
                PK2(xp, xv.x);
                FFMA2(ea2[0][0], xp, wa.x, ea2[0][0]); FFMA2(ea2[0][1], xp, wa.y, ea2[0][1]);
                FFMA2(ea2[0][2], xp, wb.x, ea2[0][2]); FFMA2(ea2[0][3], xp, wb.y, ea2[0][3]);
                PK2(xp, xv.y);
                FFMA2(ea2[1][0], xp, wa.x, ea2[1][0]); FFMA2(ea2[1][1], xp, wa.y, ea2[1][1]);
                FFMA2(ea2[1][2], xp, wb.x, ea2[1][2]); FFMA2(ea2[1][3], xp, wb.y, ea2[1][3]);
                PK2(xp, xv.z);
                FFMA2(ea2[2][0], xp, wa.x, ea2[2][0]); FFMA2(ea2[2][1], xp, wa.y, ea2[2][1]);
                FFMA2(ea2[2][2], xp, wb.x, ea2[2][2]); FFMA2(ea2[2][3], xp, wb.y, ea2[2][3]);
                PK2(xp, xv.w);
                FFMA2(ea2[3][0], xp, wa.x, ea2[3][0]); FFMA2(ea2[3][1], xp, wa.y, ea2[3][1]);
                FFMA2(ea2[3][2], xp, wb.x, ea2[3][2]); FFMA2(ea2[3][3], xp, wb.y, ea2[3][3]);
            }
            #pragma unroll
            for (int jp = 0; jp < 4; jp++) {
                #pragma unroll
                for (int h = 0; h < 2; h++) {
                    const int c = tc*8 + 2*jp + h;
                    float4 m4 = *(float4*)(sMSGt + c*SDE + e0);
                    float v0, v1, v2, v3, dummy;
                    if (h == 0) {
                        UPK2(v0, dummy, ea2[0][jp]); UPK2(v1, dummy, ea2[1][jp]);
                        UPK2(v2, dummy, ea2[2][jp]); UPK2(v3, dummy, ea2[3][jp]);
                    } else {
                        UPK2(dummy, v0, ea2[0][jp]); UPK2(dummy, v1, ea2[1][jp]);
                        UPK2(dummy, v2, ea2[2][jp]); UPK2(dummy, v3, ea2[3][jp]);
                    }
                    m4.x *= v0; m4.y *= v1; m4.z *= v2; m4.w *= v3;
                    *(float4*)(sMSGt + c*SDE + e0) = m4;
                }
            }
        }
        __syncthreads();

        // GEMM2: w_edge, cols = strip A [tc*8,+8) + strip B [64+tc*8,+8)
        u64 we[4][8];
        {
            u64 acc[4][8] = {};
            #pragma unroll 2
            for (int k = 0; k < 64; k++) {
                float4 xv = *(const float4*)(sRt + k*SDE + e0);
                const float* wrow = sWr2 + k*128;
                ulonglong2 wa = *(const ulonglong2*)(wrow + tc*8);
                ulonglong2 wb = *(const ulonglong2*)(wrow + tc*8 + 4);
                ulonglong2 wc = *(const ulonglong2*)(wrow + 64 + tc*8);
                ulonglong2 wd = *(const ulonglong2*)(wrow + 64 + tc*8 + 4);
                u64 xp;
                #pragma unroll
                for (int i = 0; i < 4; i++) {
                    float x = (i==0) ? xv.x : (i==1) ? xv.y : (i==2) ? xv.z : xv.w;
                    PK2(xp, x);
                    FFMA2(acc[i][0], xp, wa.x, acc[i][0]); FFMA2(acc[i][1], xp, wa.y, acc[i][1]);
                    FFMA2(acc[i][2], xp, wb.x, acc[i][2]); FFMA2(acc[i][3], xp, wb.y, acc[i][3]);
                    FFMA2(acc[i][4], xp, wc.x, acc[i][4]); FFMA2(acc[i][5], xp, wc.y, acc[i][5]);
                    FFMA2(acc[i][6], xp, wd.x, acc[i][6]); FFMA2(acc[i][7], xp, wd.y, acc[i][7]);
                }
            }
            #pragma unroll
            for (int i = 0; i < 4; i++) {
                #pragma unroll
                for (int jp = 0; jp < 4; jp++) {
                    u64 bA = *(const u64*)(sbr2 + tc*8 + 2*jp);
                    u64 bB = *(const u64*)(sbr2 + 64 + tc*8 + 2*jp);
                    ADD2(we[i][jp],   acc[i][jp],   bA);
                    ADD2(we[i][jp+4], acc[i][jp+4], bB);
                }
            }
        }

        // GEMM3: dtp, same strips
        u64 dtp[4][8];
        {
            u64 acc[4][8] = {};
            #pragma unroll 2
            for (int k = 0; k < 64; k++) {
                float4 xv = *(const float4*)(sMSGt + k*SDE + e0);
                const float* wrow = sWdtp + k*128;
                ulonglong2 wa = *(const ulonglong2*)(wrow + tc*8);
                ulonglong2 wb = *(const ulonglong2*)(wrow + tc*8 + 4);
                ulonglong2 wc = *(const ulonglong2*)(wrow + 64 + tc*8);
                ulonglong2 wd = *(const ulonglong2*)(wrow + 64 + tc*8 + 4);
                u64 xp;
                #pragma unroll
                for (int i = 0; i < 4; i++) {
                    float x = (i==0) ? xv.x : (i==1) ? xv.y : (i==2) ? xv.z : xv.w;
                    PK2(xp, x);
                    FFMA2(acc[i][0], xp, wa.x, acc[i][0]); FFMA2(acc[i][1], xp, wa.y, acc[i][1]);
                    FFMA2(acc[i][2], xp, wb.x, acc[i][2]); FFMA2(acc[i][3], xp, wb.y, acc[i][3]);
                    FFMA2(acc[i][4], xp, wc.x, acc[i][4]); FFMA2(acc[i][5], xp, wc.y, acc[i][5]);
                    FFMA2(acc[i][6], xp, wd.x, acc[i][6]); FFMA2(acc[i][7], xp, wd.y, acc[i][7]);
                }
            }
            #pragma unroll
            for (int i = 0; i < 4; i++)
                #pragma unroll
                for (int jp = 0; jp < 8; jp++)
                    MUL2(dtp[i][jp], acc[i][jp], we[i][jp]);
        }

        // fused epilogue: every warp owns head tc end-to-end; no smem, no sync
        #pragma unroll
        for (int i = 0; i < 4; i++) {
            const int ge = base + e0 + i;
            if (ge >= EE) continue;
            float lg = 0.0f;
            #pragma unroll
            for (int jp = 0; jp < 4; jp++) {
                float x0, x1;
                UPK2(x0, x1, dtp[i][jp]);
                float lr0 = (x0 > 0.0f) ? x0 : 0.2f * x0;
                float lr1 = (x1 > 0.0f) ? x1 : 0.2f * x1;
                lg += lr0 * sal[tc*8 + 2*jp] + lr1 * sal[tc*8 + 2*jp + 1];
            }
            const int d = edst[ge];
            const float a = __expf(lg + el_g[ge]);
            asm volatile("red.global.add.f32 [%0], %1;"
                         :: "l"(g_z + (size_t)d*8 + tc), "f"(a) : "memory");
            float* dstp = g_acc + (size_t)d*64 + tc*8;
            #pragma unroll
            for (int q = 0; q < 2; q++) {
                float4 v;
                UPK2(v.x, v.y, dtp[i][4 + 2*q]);
                UPK2(v.z, v.w, dtp[i][4 + 2*q + 1]);
                asm volatile("red.global.add.v4.f32 [%0], {%1,%2,%3,%4};"
                             :: "l"(dstp + q*4), "f"(v.x*a), "f"(v.y*a),
                                "f"(v.z*a), "f"(v.w*a) : "memory");
            }
        }
    }
}

// ---------------- final: 512 threads, 128-node tiles, 2n x 8c, fused FFN ----------------
#define FW_P   0
#define FW_1   4096
#define FW_2   16384
#define F_BP   28672
#define F_LNW  28736
#define F_LNB  28800
#define F_BF1  28864
#define F_BF2  29056
#define F_SS   29120
#define F_SQ   29248
#define F_XT   29376
#define F_YT   37824
#define SMEM_FIN 46272

__global__ void __launch_bounds__(512, 1)
k_final(const float* __restrict__ dst_f,
        const float* __restrict__ Wp, const float* __restrict__ bp,
        const float* __restrict__ lnw, const float* __restrict__ lnb,
        const float* __restrict__ Wf1, const float* __restrict__ bf1,
        const float* __restrict__ Wf2, const float* __restrict__ bf2,
        float* __restrict__ out) {
    extern __shared__ float sf[];
    const int tid = threadIdx.x;
    for (int i = tid; i < 4096;  i += 512) sf[FW_P + i] = Wp[i];
    for (int i = tid; i < 12288; i += 512) sf[FW_1 + i] = Wf1[i];
    for (int i = tid; i < 12288; i += 512) sf[FW_2 + i] = Wf2[i];
    if (tid < 64) {
        sf[F_BP  + tid] = bp[tid];
        sf[F_LNW + tid] = lnw[tid];
        sf[F_LNB + tid] = lnb[tid];
        sf[F_BF2 + tid] = bf2[tid];
    }
    if (tid < 192) sf[F_BF1 + tid] = bf1[tid];

    const int NT = (NDN + 127)/128;
    const int lane = tid & 31, warp = tid >> 5;
    const int tc = warp & 7;
    const int n0 = ((warp >> 3) << 6) + lane*2;

    for (int tile = blockIdx.x; tile < NT; tile += gridDim.x) {
        const int base = tile * 128;
        __syncthreads();
        if (tid < 128) { sf[F_SS + tid] = 0.0f; sf[F_SQ + tid] = 0.0f; }
        // stage Xt = acc / z
        {
            const int n = tid >> 2, p = tid & 3;
            int gn = base + n; if (gn >= NDN) gn = NDN - 1;
            const float4* ar = (const float4*)(g_acc + (size_t)gn*64 + p*16);
            float z0 = g_z[(size_t)gn*8 + 2*p], z1 = g_z[(size_t)gn*8 + 2*p + 1];
            float r0 = (z0 > 0.0f) ? 1.0f/z0 : 0.0f;
            float r1 = (z1 > 0.0f) ? 1.0f/z1 : 0.0f;
            #pragma unroll
            for (int j = 0; j < 4; j++) {
                float4 v = ar[j];
                const float rr = (j < 2) ? r0 : r1;
                const int k0 = p*16 + j*4;
                sf[F_XT + (k0+0)*SDN + n] = v.x * rr;
                sf[F_XT + (k0+1)*SDN + n] = v.y * rr;
                sf[F_XT + (k0+2)*SDN + n] = v.z * rr;
                sf[F_XT + (k0+3)*SDN + n] = v.w * rr;
            }
        }
        __syncthreads();

        // GEMM1: emb = Xt @ Wp + bp + dst_f ; LN stats
        float emb[2][8];
        {
            u64 acc[2][4] = {};
            #pragma unroll 4
            for (int k = 0; k < 64; k++) {
                float2 xv = *(const float2*)(sf + F_XT + k*SDN + n0);
                ulonglong2 wa = *(const ulonglong2*)(sf + FW_P + k*64 + tc*8);
                ulonglong2 wb = *(const ulonglong2*)(sf + FW_P + k*64 + tc*8 + 4);
                u64 xp;
                PK2(xp, xv.x);
                FFMA2(acc[0][0], xp, wa.x, acc[0][0]); FFMA2(acc[0][1], xp, wa.y, acc[0][1]);
                FFMA2(acc[0][2], xp, wb.x, acc[0][2]); FFMA2(acc[0][3], xp, wb.y, acc[0][3]);
                PK2(xp, xv.y);
                FFMA2(acc[1][0], xp, wa.x, acc[1][0]); FFMA2(acc[1][1], xp, wa.y, acc[1][1]);
                FFMA2(acc[1][2], xp, wb.x, acc[1][2]); FFMA2(acc[1][3], xp, wb.y, acc[1][3]);
            }
            #pragma unroll
            for (int i = 0; i < 2; i++) {
                int gn = base + n0 + i; if (gn >= NDN) gn = NDN - 1;
                float4 d0 = *(const float4*)(dst_f + (size_t)gn*64 + tc*8);
                float4 d1 = *(const float4*)(dst_f + (size_t)gn*64 + tc*8 + 4);
                UPK2(emb[i][0], emb[i][1], acc[i][0]);
                UPK2(emb[i][2], emb[i][3], acc[i][1]);
                UPK2(emb[i][4], emb[i][5], acc[i][2]);
                UPK2(emb[i][6], emb[i][7], acc[i][3]);
                emb[i][0] += sf[F_BP + tc*8+0] + d0.x;
                emb[i][1] += sf[F_BP + tc*8+1] + d0.y;
                emb[i][2] += sf[F_BP + tc*8+2] + d0.z;
                emb[i][3] += sf[F_BP + tc*8+3] + d0.w;
                emb[i][4] += sf[F_BP + tc*8+4] + d1.x;
                emb[i][5] += sf[F_BP + tc*8+5] + d1.y;
                emb[i][6] += sf[F_BP + tc*8+6] + d1.z;
                emb[i][7] += sf[F_BP + tc*8+7] + d1.w;
            }
            #pragma unroll
            for (int i = 0; i < 2; i++) {
                float s = 0.f, q = 0.f;
                #pragma unroll
                for (int j = 0; j < 8; j++) { s += emb[i][j]; q += emb[i][j]*emb[i][j]; }
                atomicAdd(sf + F_SS + n0 + i, s);
                atomicAdd(sf + F_SQ + n0 + i, q);
            }
        }
        __syncthreads();

        // LN -> Yt
        {
            float mean[2], rs[2];
            #pragma unroll
            for (int i = 0; i < 2; i++) {
                mean[i] = sf[F_SS + n0 + i] * (1.0f/64.0f);
                float var = sf[F_SQ + n0 + i] * (1.0f/64.0f) - mean[i]*mean[i];
                rs[i] = rsqrtf(var + LNEPS);
            }
            #pragma unroll
            for (int j = 0; j < 8; j++) {
                const int c = tc*8 + j;
                const float lw = sf[F_LNW + c], lb = sf[F_LNB + c];
                float2 v;
                v.x = (emb[0][j] - mean[0]) * rs[0] * lw + lb;
                v.y = (emb[1][j] - mean[1]) * rs[1] * lw + lb;
                *(float2*)(sf + F_YT + c*SDN + n0) = v;
            }
        }
        __syncthreads();

        // fused FFN: 3 chunks of 64 hidden dims
        u64 oacc[2][4] = {};
        #pragma unroll
        for (int pp = 0; pp < 3; pp++) {
            {
                u64 acc[2][4] = {};
                #pragma unroll 4
                for (int k = 0; k < 64; k++) {
                    float2 xv = *(const float2*)(sf + F_YT + k*SDN + n0);
                    ulonglong2 wa = *(const ulonglong2*)(sf + FW_1 + k*192 + pp*64 + tc*8);
                    ulonglong2 wb = *(const ulonglong2*)(sf + FW_1 + k*192 + pp*64 + tc*8 + 4);
                    u64 xp;
                    PK2(xp, xv.x);
                    FFMA2(acc[0][0], xp, wa.x, acc[0][0]); FFMA2(acc[0][1], xp, wa.y, acc[0][1]);
                    FFMA2(acc[0][2], xp, wb.x, acc[0][2]); FFMA2(acc[0][3], xp, wb.y, acc[0][3]);
                    PK2(xp, xv.y);
                    FFMA2(acc[1][0], xp, wa.x, acc[1][0]); FFMA2(acc[1][1], xp, wa.y, acc[1][1]);
                    FFMA2(acc[1][2], xp, wb.x, acc[1][2]); FFMA2(acc[1][3], xp, wb.y, acc[1][3]);
                }
                float h[2][8];
                #pragma unroll
                for (int i = 0; i < 2; i++) {
                    UPK2(h[i][0], h[i][1], acc[i][0]);
                    UPK2(h[i][2], h[i][3], acc[i][1]);
                    UPK2(h[i][4], h[i][5], acc[i][2]);
                    UPK2(h[i][6], h[i][7], acc[i][3]);
                    #pragma unroll
                    for (int j = 0; j < 8; j++) {
                        float x = h[i][j] + sf[F_BF1 + pp*64 + tc*8 + j];
                        h[i][j] = x / (1.0f + __expf(-x));
                    }
                }
                #pragma unroll
                for (int j = 0; j < 8; j++) {
                    float2 v = make_float2(h[0][j], h[1][j]);
                    *(float2*)(sf + F_XT + (tc*8 + j)*SDN + n0) = v;
                }
            }
            __syncthreads();
            {
                #pragma unroll 4
                for (int k = 0; k < 64; k++) {
                    float2 xv = *(const float2*)(sf + F_XT + k*SDN + n0);
                    ulonglong2 wa = *(const ulonglong2*)(sf + FW_2 + (pp*64 + k)*64 + tc*8);
                    ulonglong2 wb = *(const ulonglong2*)(sf + FW_2 + (pp*64 + k)*64 + tc*8 + 4);
                    u64 xp;
                    PK2(xp, xv.x);
                    FFMA2(oacc[0][0], xp, wa.x, oacc[0][0]); FFMA2(oacc[0][1], xp, wa.y, oacc[0][1]);
                    FFMA2(oacc[0][2], xp, wb.x, oacc[0][2]); FFMA2(oacc[0][3], xp, wb.y, oacc[0][3]);
                    PK2(xp, xv.y);
                    FFMA2(oacc[1][0], xp, wa.x, oacc[1][0]); FFMA2(oacc[1][1], xp, wa.y, oacc[1][1]);
                    FFMA2(oacc[1][2], xp, wb.x, oacc[1][2]); FFMA2(oacc[1][3], xp, wb.y, oacc[1][3]);
                }
            }
            if (pp < 2) __syncthreads();
        }

        // write out
        #pragma unroll
        for (int i = 0; i < 2; i++) {
            const int gn = base + n0 + i;
            if (gn >= NDN) continue;
            float o[8];
            UPK2(o[0], o[1], oacc[i][0]); UPK2(o[2], o[3], oacc[i][1]);
            UPK2(o[4], o[5], oacc[i][2]); UPK2(o[6], o[7], oacc[i][3]);
            float4 v0, v1;
            v0.x = o[0] + sf[F_BF2 + tc*8+0] + emb[i][0];
            v0.y = o[1] + sf[F_BF2 + tc*8+1] + emb[i][1];
            v0.z = o[2] + sf[F_BF2 + tc*8+2] + emb[i][2];
            v0.w = o[3] + sf[F_BF2 + tc*8+3] + emb[i][3];
            v1.x = o[4] + sf[F_BF2 + tc*8+4] + emb[i][4];
            v1.y = o[5] + sf[F_BF2 + tc*8+5] + emb[i][5];
            v1.z = o[6] + sf[F_BF2 + tc*8+6] + emb[i][6];
            v1.w = o[7] + sf[F_BF2 + tc*8+7] + emb[i][7];
            *(float4*)(out + (size_t)gn*64 + tc*8)     = v0;
            *(float4*)(out + (size_t)gn*64 + tc*8 + 4) = v1;
        }
    }
}

// ---------------- launch ----------------
extern "C" void kernel_launch(void* const* d_in, const int* in_sizes, int n_in,
                              void* d_out, int out_size) {
    const float* src_f        = (const float*)d_in[0];
    const float* dst_f        = (const float*)d_in[1];
    const float* edge_attr    = (const float*)d_in[2];
    const float* edge_scalars = (const float*)d_in[3];
    const float* edge_logits  = (const float*)d_in[4];
    const int*   edge_src     = (const int*)d_in[5];
    const int*   edge_dst     = (const int*)d_in[6];
    const float* ln_src_w = (const float*)d_in[7];
    const float* ln_src_b = (const float*)d_in[8];
    const float* W_src    = (const float*)d_in[9];
    const float* ln_dst_w = (const float*)d_in[10];
    const float* ln_dst_b = (const float*)d_in[11];
    const float* W_dst    = (const float*)d_in[12];
    const float* b_dst    = (const float*)d_in[13];
    const float* W_ea     = (const float*)d_in[14];
    const float* W_dtp    = (const float*)d_in[15];
    const float* W_r1     = (const float*)d_in[16];
    const float* b_r1     = (const float*)d_in[17];
    const float* W_r2     = (const float*)d_in[18];
    const float* b_r2     = (const float*)d_in[19];
    const float* alpha    = (const float*)d_in[20];
    const float* W_proj   = (const float*)d_in[21];
    const float* b_proj   = (const float*)d_in[22];
    const float* ln_post_w = (const float*)d_in[23];
    const float* ln_post_b = (const float*)d_in[24];
    const float* W_f1     = (const float*)d_in[25];
    const float* b_f1     = (const float*)d_in[26];
    const float* W_f2     = (const float*)d_in[27];
    const float* b_f2     = (const float*)d_in[28];
    float* out = (float*)d_out;

    cudaFuncSetAttribute(k_edge, cudaFuncAttributeMaxDynamicSharedMemorySize,
                         SMEM_EDGE_FLOATS * 4);
    cudaFuncSetAttribute(k_final, cudaFuncAttributeMaxDynamicSharedMemorySize,
                         SMEM_FIN * 4);
    cudaFuncSetAttribute(k_node, cudaFuncAttributeMaxDynamicSharedMemorySize,
                         KN_SMEM * 4);

    k_init<<<(NDN*CC + 255)/256, 256>>>();
    k_node<<<296, 512, KN_SMEM*4>>>(src_f, dst_f, ln_src_w, ln_src_b, W_src,
                                    ln_dst_w, ln_dst_b, W_dst, b_dst);
    k_edge<<<296, 256, SMEM_EDGE_FLOATS*4>>>(edge_scalars, edge_attr, edge_logits,
                                             edge_src, edge_dst,
                                             W_r1, b_r1, W_r2, b_r2, W_ea, W_dtp, alpha);
    k_final<<<148, 512, SMEM_FIN*4>>>(dst_f, W_proj, b_proj,
                                      ln_post_w, ln_post_b,
                                      W_f1, b_f1, W_f2, b_f2, out);
}